// round 10
// baseline (speedup 1.0000x reference)
#include <cuda_runtime.h>
#include <cuda_fp16.h>
#include <cstdint>

#define NN    4096
#define DF    128
#define DR    64
#define HID   1024
#define TOPK  10
#define NCAND 16
#define XDIM  192

typedef __half f16;

// ---------------- static scratch ----------------
__device__ float g_key[(size_t)NN * NN];
__device__ float g_sq [NN];
__device__ int   g_cand[NN * NCAND];
__device__ int   g_nidx[NN * TOPK];
__device__ float g_pushed[NN * DR];

__device__ f16 g_x0h[NN * XDIM], g_x0l[NN * XDIM];
__device__ f16 g_hAh[NN * HID],  g_hAl[NN * HID];
__device__ f16 g_hBh[NN * HID],  g_hBl[NN * HID];
__device__ f16 g_ch [NN * DF],   g_cl [NN * DF];
__device__ f16 g_cth[DF * NN],   g_ctl[DF * NN];
__device__ f16 g_Wih[XDIM * HID], g_Wil[XDIM * HID];
__device__ f16 g_W1h[HID * HID],  g_W1l[HID * HID];
__device__ f16 g_W2h[HID * HID],  g_W2l[HID * HID];
__device__ f16 g_W3h[HID * HID],  g_W3l[HID * HID];
__device__ f16 g_Woh[HID * DR],   g_Wol[HID * DR];

// ---------------- helpers ----------------
__device__ __forceinline__ float sp(float x) {
    return fmaxf(x, 0.0f) + log1pf(expf(-fabsf(x)));
}

__device__ __forceinline__ void cpa16(void* s, const void* g) {
    uint32_t sa = (uint32_t)__cvta_generic_to_shared(s);
    asm volatile("cp.async.cg.shared.global [%0], [%1], 16;" :: "r"(sa), "l"(g) : "memory");
}
#define CP_COMMIT() asm volatile("cp.async.commit_group;" ::: "memory")
#define CP_WAIT1()  asm volatile("cp.async.wait_group 1;" ::: "memory")

__device__ __forceinline__ void ldm_x4(uint32_t* r, const void* p) {
    uint32_t a = (uint32_t)__cvta_generic_to_shared(p);
    asm volatile("ldmatrix.sync.aligned.m8n8.x4.shared.b16 {%0,%1,%2,%3}, [%4];"
        : "=r"(r[0]), "=r"(r[1]), "=r"(r[2]), "=r"(r[3]) : "r"(a));
}
__device__ __forceinline__ void ldm_x2t(uint32_t* r, const void* p) {
    uint32_t a = (uint32_t)__cvta_generic_to_shared(p);
    asm volatile("ldmatrix.sync.aligned.m8n8.x2.trans.shared.b16 {%0,%1}, [%2];"
        : "=r"(r[0]), "=r"(r[1]) : "r"(a));
}
__device__ __forceinline__ void mma16816(float* c, const uint32_t* a, const uint32_t* b) {
    asm volatile("mma.sync.aligned.m16n8k16.row.col.f32.f16.f16.f32 "
        "{%0,%1,%2,%3}, {%4,%5,%6,%7}, {%8,%9}, {%0,%1,%2,%3};"
        : "+f"(c[0]), "+f"(c[1]), "+f"(c[2]), "+f"(c[3])
        : "r"(a[0]), "r"(a[1]), "r"(a[2]), "r"(a[3]), "r"(b[0]), "r"(b[1]));
}

__device__ __forceinline__ void split1(float v, f16& h, f16& l) {
    h = __float2half(v);
    l = __float2half(v - __half2float(h));
}

// ---------------- small prep kernels ----------------
__global__ void sq_kernel(const float* __restrict__ cond, float* __restrict__ sq) {
    const int row  = blockIdx.x * 8 + (threadIdx.x >> 5);
    const int lane = threadIdx.x & 31;
    const float4 t = reinterpret_cast<const float4*>(cond)[row * 32 + lane];
    float s = t.x * t.x + t.y * t.y + t.z * t.z + t.w * t.w;
    #pragma unroll
    for (int o = 16; o > 0; o >>= 1) s += __shfl_down_sync(0xffffffffu, s, o);
    if (lane == 0) sq[row] = s;
}

// vectorized split with 4x ILP per thread
__global__ void split4_kernel(const float* __restrict__ src, f16* __restrict__ hi,
                              f16* __restrict__ lo, int n4) {
    const int i0 = blockIdx.x * (blockDim.x * 4) + threadIdx.x;
    #pragma unroll
    for (int u = 0; u < 4; u++) {
        const int i = i0 + u * blockDim.x;
        if (i >= n4) return;
        const float4 v = reinterpret_cast<const float4*>(src)[i];
        f16 h0, l0, h1, l1, h2, l2, h3, l3;
        split1(v.x, h0, l0); split1(v.y, h1, l1);
        split1(v.z, h2, l2); split1(v.w, h3, l3);
        __half2 hh[2] = { __halves2half2(h0, h1), __halves2half2(h2, h3) };
        __half2 ll[2] = { __halves2half2(l0, l1), __halves2half2(l2, l3) };
        reinterpret_cast<uint2*>(hi)[i] = *reinterpret_cast<uint2*>(hh);
        reinterpret_cast<uint2*>(lo)[i] = *reinterpret_cast<uint2*>(ll);
    }
}

// condT[k][n] = cond[n][k], split
__global__ void tsplit_kernel(const float* __restrict__ cond, f16* __restrict__ hi,
                              f16* __restrict__ lo) {
    const int i = blockIdx.x * blockDim.x + threadIdx.x;
    if (i >= DF * NN) return;
    const int k = i / NN, n = i % NN;
    f16 h, l; split1(cond[n * DF + k], h, l);
    hi[i] = h; lo[i] = l;
}

// x0 = concat(cond, tens), split
__global__ void concat_split_kernel(const float* __restrict__ cond, const float* __restrict__ tens,
                                    f16* __restrict__ hi, f16* __restrict__ lo) {
    const int i = blockIdx.x * blockDim.x + threadIdx.x;
    if (i >= NN * XDIM) return;
    const int r = i / XDIM, c = i % XDIM;
    const float v = (c < DF) ? cond[r * DF + c] : tens[r * DR + (c - DF)];
    f16 h, l; split1(v, h, l);
    hi[i] = h; lo[i] = l;
}

// ---------------- split-fp16 tensor-core GEMM ----------------
// C[M,N] ~= (Ah+Al)@(Bh+Bl)  (drop lo*lo).  BM=128, BK=16, warp tile 64x32.
// Threads = (BN/32)*64: BN=128 -> 256 thr (8 warps), BN=256 -> 512 thr (16 warps).
// EPI 0: y = softplus(acc + bias[c]) -> write split fp16 (Oh, Ol)
// EPI 1: Cf = extra - (acc + bias[c])
// EPI 2: Cf = max(bias[r] + bias[c] - 2*acc, 0)      (gram keys; bias = sq)
template<int BN, int EPI, int OCC>
__global__ void __launch_bounds__((BN / 32) * 64, OCC)
mma_gemm(const f16* __restrict__ Ah, const f16* __restrict__ Al,
         const f16* __restrict__ Bh, const f16* __restrict__ Bl,
         const float* __restrict__ bias, const float* __restrict__ extra,
         float* __restrict__ Cf, f16* __restrict__ Oh, f16* __restrict__ Ol,
         int M, int N, int K)
{
    constexpr int WN = BN / 32;
    constexpr int THREADS = 2 * WN * 32;
    constexpr int AST = 24;       // As row stride: 48B, conflict-free ldmatrix
    constexpr int BST = BN + 8;   // Bs row stride

    __shared__ __align__(16) f16 As[2][2][128 * AST];
    __shared__ __align__(16) f16 Bs[2][2][16 * BST];

    const int tid  = threadIdx.x;
    const int lane = tid & 31;
    const int w    = tid >> 5;
    const int wm   = w / WN;
    const int wn   = w % WN;
    const int row0 = blockIdx.y * 128;
    const int col0 = blockIdx.x * BN;

    float acc[4][4][4];
    #pragma unroll
    for (int a = 0; a < 4; a++)
        #pragma unroll
        for (int b = 0; b < 4; b++)
            #pragma unroll
            for (int c = 0; c < 4; c++) acc[a][b][c] = 0.0f;

    const int nchunk = K / 16;

    auto load_chunk = [&](int ci, int buf) {
        const int kt = ci * 16;
        #pragma unroll
        for (int s = 0; s < 2; s++) {
            const f16* Ag = s ? Al : Ah;
            for (int f = tid; f < 128 * 2; f += THREADS) {
                const int m = f >> 1, c = (f & 1) * 8;
                cpa16(&As[buf][s][m * AST + c], Ag + (size_t)(row0 + m) * K + kt + c);
            }
            const f16* Bg = s ? Bl : Bh;
            for (int f = tid; f < 16 * (BN / 8); f += THREADS) {
                const int k = f / (BN / 8), c = (f % (BN / 8)) * 8;
                cpa16(&Bs[buf][s][k * BST + c], Bg + (size_t)(kt + k) * N + col0 + c);
            }
        }
    };

    load_chunk(0, 0);
    CP_COMMIT();

    for (int ci = 0; ci < nchunk; ci++) {
        const int buf = ci & 1;
        if (ci + 1 < nchunk) load_chunk(ci + 1, buf ^ 1);
        CP_COMMIT();
        CP_WAIT1();
        __syncthreads();

        uint32_t a[4][4], b[4][2];
        const int arow = wm * 64 + (lane & 15);
        const int acol = (lane >> 4) << 3;
        const int brow = (lane & 15) * BST;
        const int bcol = wn * 32;

        // pass 1: Ahi x Blo
        #pragma unroll
        for (int mt = 0; mt < 4; mt++)
            ldm_x4(a[mt], &As[buf][0][(arow + mt * 16) * AST + acol]);
        #pragma unroll
        for (int nt = 0; nt < 4; nt++)
            ldm_x2t(b[nt], &Bs[buf][1][brow + bcol + nt * 8]);
        #pragma unroll
        for (int mt = 0; mt < 4; mt++)
            #pragma unroll
            for (int nt = 0; nt < 4; nt++) mma16816(acc[mt][nt], a[mt], b[nt]);

        // pass 2: Ahi x Bhi
        #pragma unroll
        for (int nt = 0; nt < 4; nt++)
            ldm_x2t(b[nt], &Bs[buf][0][brow + bcol + nt * 8]);
        #pragma unroll
        for (int mt = 0; mt < 4; mt++)
            #pragma unroll
            for (int nt = 0; nt < 4; nt++) mma16816(acc[mt][nt], a[mt], b[nt]);

        // pass 3: Alo x Bhi (b regs reused)
        #pragma unroll
        for (int mt = 0; mt < 4; mt++)
            ldm_x4(a[mt], &As[buf][1][(arow + mt * 16) * AST + acol]);
        #pragma unroll
        for (int mt = 0; mt < 4; mt++)
            #pragma unroll
            for (int nt = 0; nt < 4; nt++) mma16816(acc[mt][nt], a[mt], b[nt]);

        __syncthreads();
    }

    // epilogue
    #pragma unroll
    for (int mt = 0; mt < 4; mt++) {
        #pragma unroll
        for (int nt = 0; nt < 4; nt++) {
            const int r = row0 + wm * 64 + mt * 16 + (lane >> 2);
            const int c = col0 + wn * 32 + nt * 8 + ((lane & 3) << 1);
            const float* ac = acc[mt][nt];
            if constexpr (EPI == 0) {
                const float bc0 = bias[c], bc1 = bias[c + 1];
                #pragma unroll
                for (int h = 0; h < 2; h++) {
                    const int rr = r + 8 * h;
                    const float y0 = sp(ac[2 * h] + bc0);
                    const float y1 = sp(ac[2 * h + 1] + bc1);
                    f16 h0, l0, h1, l1;
                    split1(y0, h0, l0); split1(y1, h1, l1);
                    *(__half2*)(Oh + (size_t)rr * N + c) = __halves2half2(h0, h1);
                    *(__half2*)(Ol + (size_t)rr * N + c) = __halves2half2(l0, l1);
                }
            } else if constexpr (EPI == 1) {
                const float bc0 = bias[c], bc1 = bias[c + 1];
                #pragma unroll
                for (int h = 0; h < 2; h++) {
                    const size_t o = (size_t)(r + 8 * h) * N + c;
                    Cf[o]     = extra[o]     - (ac[2 * h]     + bc0);
                    Cf[o + 1] = extra[o + 1] - (ac[2 * h + 1] + bc1);
                }
            } else {
                const float sc0 = bias[c], sc1 = bias[c + 1];
                #pragma unroll
                for (int h = 0; h < 2; h++) {
                    const float sr = bias[r + 8 * h];
                    const size_t o = (size_t)(r + 8 * h) * NN + c;
                    Cf[o]     = fmaxf(sr + sc0 - 2.0f * ac[2 * h],     0.0f);
                    Cf[o + 1] = fmaxf(sr + sc1 - 2.0f * ac[2 * h + 1], 0.0f);
                }
            }
        }
    }
}

// ---------------- top-NCAND smallest per row (approx keys), register lists ------
template<int L>
__device__ __forceinline__ void insL(float x, int j, float (&v)[L], int (&id)[L]) {
    if (x >= v[L - 1]) return;
    #pragma unroll
    for (int t = L - 1; t > 0; t--) {
        const bool shf = (x < v[t - 1]);
        const bool put = !shf && (x < v[t]);
        v[t]  = shf ? v[t - 1]  : (put ? x : v[t]);
        id[t] = shf ? id[t - 1] : (put ? j : id[t]);
    }
    if (x < v[0]) { v[0] = x; id[0] = j; }
}

__global__ void topk_kernel(const float* __restrict__ key, int* __restrict__ out_cand) {
    const int row  = blockIdx.x * 8 + (threadIdx.x >> 5);
    const int lane = threadIdx.x & 31;
    const float4* k4 = reinterpret_cast<const float4*>(key + (size_t)row * NN);

    float v[NCAND]; int id[NCAND];
    #pragma unroll
    for (int t = 0; t < NCAND; t++) { v[t] = 3.0e38f; id[t] = 0x7fffffff; }

    #pragma unroll 4
    for (int j = lane; j < NN / 4; j += 32) {
        const float4 t = k4[j];
        const int b = 4 * j;
        insL<NCAND>(t.x, b,     v, id);
        insL<NCAND>(t.y, b + 1, v, id);
        insL<NCAND>(t.z, b + 2, v, id);
        insL<NCAND>(t.w, b + 3, v, id);
    }

    #pragma unroll
    for (int k = 0; k < NCAND; k++) {
        float mv = v[0]; int mi = id[0];
        #pragma unroll
        for (int off = 16; off > 0; off >>= 1) {
            const float ov = __shfl_down_sync(0xffffffffu, mv, off);
            const int   oi = __shfl_down_sync(0xffffffffu, mi, off);
            if (ov < mv || (ov == mv && oi < mi)) { mv = ov; mi = oi; }
        }
        mv = __shfl_sync(0xffffffffu, mv, 0);
        mi = __shfl_sync(0xffffffffu, mi, 0);
        if (id[0] == mi) {
            #pragma unroll
            for (int t = 0; t < NCAND - 1; t++) { v[t] = v[t + 1]; id[t] = id[t + 1]; }
            v[NCAND - 1] = 3.0e38f; id[NCAND - 1] = 0x7fffffff;
        }
        if (lane == 0) out_cand[row * NCAND + k] = mi;
    }
}

// ---------------- exact fp32 rescore of the 16 candidates -> final top-10 --------
__global__ void rescore_kernel(const float* __restrict__ cond, const float* __restrict__ sq,
                               const int* __restrict__ cand, int* __restrict__ out_idx) {
    const int row  = blockIdx.x * 8 + (threadIdx.x >> 5);
    const int lane = threadIdx.x & 31;
    const float4 cr = reinterpret_cast<const float4*>(cond)[row * 32 + lane];
    const float sr = sq[row];

    float mv = 3.0e38f; int mid = 0x7fffffff;
    #pragma unroll
    for (int c = 0; c < NCAND; c++) {
        const int j = cand[row * NCAND + c];
        const float4 cc = reinterpret_cast<const float4*>(cond)[j * 32 + lane];
        float d = cr.x * cc.x + cr.y * cc.y + cr.z * cc.z + cr.w * cc.w;
        #pragma unroll
        for (int o = 16; o > 0; o >>= 1) d += __shfl_down_sync(0xffffffffu, d, o);
        d = __shfl_sync(0xffffffffu, d, 0);
        const float k = fmaxf(sr + sq[j] - 2.0f * d, 0.0f);
        if (lane == c) { mv = k; mid = j; }
    }

    #pragma unroll
    for (int k = 0; k < TOPK; k++) {
        float bv = mv; int bi = mid;
        #pragma unroll
        for (int off = 16; off > 0; off >>= 1) {
            const float ov = __shfl_down_sync(0xffffffffu, bv, off);
            const int   oi = __shfl_down_sync(0xffffffffu, bi, off);
            if (ov < bv || (ov == bv && oi < bi)) { bv = ov; bi = oi; }
        }
        bv = __shfl_sync(0xffffffffu, bv, 0);
        bi = __shfl_sync(0xffffffffu, bi, 0);
        if (mid == bi) { mv = 3.0e38f; mid = 0x7fffffff; }
        if (lane == 0) out_idx[row * TOPK + k] = bi;
    }
}

// ---------------- final gather ----------------
__global__ void gather_kernel(const int* __restrict__ nidx, const float* __restrict__ pushed,
                              float* __restrict__ out) {
    const int t = blockIdx.x * blockDim.x + threadIdx.x;
    if (t >= NN * TOPK * 16) return;
    const int r = t >> 4, c = t & 15;
    const int j = nidx[r];
    reinterpret_cast<float4*>(out)[t] = reinterpret_cast<const float4*>(pushed)[j * 16 + c];
}

// ---------------- launch ----------------
extern "C" void kernel_launch(void* const* d_in, const int* in_sizes, int n_in,
                              void* d_out, int out_size)
{
    const float* cond = (const float*)d_in[0];
    const float* tens = (const float*)d_in[1];
    const float* Win  = (const float*)d_in[2];
    const float* b_in = (const float*)d_in[3];
    const float* W1   = (const float*)d_in[4];
    const float* b1   = (const float*)d_in[5];
    const float* W2   = (const float*)d_in[6];
    const float* b2   = (const float*)d_in[7];
    const float* W3   = (const float*)d_in[8];
    const float* b3   = (const float*)d_in[9];
    const float* Wout = (const float*)d_in[10];
    const float* bout = (const float*)d_in[11];
    float* out = (float*)d_out;

    float *key, *sq, *pushed; int *cand, *nidx;
    f16 *x0h, *x0l, *hAh, *hAl, *hBh, *hBl, *ch, *cl, *cth, *ctl;
    f16 *Wih, *Wil, *W1h, *W1l, *W2h, *W2l, *W3h, *W3l, *Woh, *Wol;
    cudaGetSymbolAddress((void**)&key, g_key);
    cudaGetSymbolAddress((void**)&sq, g_sq);
    cudaGetSymbolAddress((void**)&cand, g_cand);
    cudaGetSymbolAddress((void**)&nidx, g_nidx);
    cudaGetSymbolAddress((void**)&pushed, g_pushed);
    cudaGetSymbolAddress((void**)&x0h, g_x0h); cudaGetSymbolAddress((void**)&x0l, g_x0l);
    cudaGetSymbolAddress((void**)&hAh, g_hAh); cudaGetSymbolAddress((void**)&hAl, g_hAl);
    cudaGetSymbolAddress((void**)&hBh, g_hBh); cudaGetSymbolAddress((void**)&hBl, g_hBl);
    cudaGetSymbolAddress((void**)&ch,  g_ch);  cudaGetSymbolAddress((void**)&cl,  g_cl);
    cudaGetSymbolAddress((void**)&cth, g_cth); cudaGetSymbolAddress((void**)&ctl, g_ctl);
    cudaGetSymbolAddress((void**)&Wih, g_Wih); cudaGetSymbolAddress((void**)&Wil, g_Wil);
    cudaGetSymbolAddress((void**)&W1h, g_W1h); cudaGetSymbolAddress((void**)&W1l, g_W1l);
    cudaGetSymbolAddress((void**)&W2h, g_W2h); cudaGetSymbolAddress((void**)&W2l, g_W2l);
    cudaGetSymbolAddress((void**)&W3h, g_W3h); cudaGetSymbolAddress((void**)&W3l, g_W3l);
    cudaGetSymbolAddress((void**)&Woh, g_Woh); cudaGetSymbolAddress((void**)&Wol, g_Wol);

    // lazy-create side streams + events (first call is outside graph capture)
    static cudaStream_t s2 = nullptr, s3 = nullptr;
    static cudaEvent_t evF = nullptr, evJ = nullptr, evW = nullptr;
    if (s2 == nullptr) {
        cudaStreamCreateWithFlags(&s2, cudaStreamNonBlocking);
        cudaStreamCreateWithFlags(&s3, cudaStreamNonBlocking);
        cudaEventCreateWithFlags(&evF, cudaEventDisableTiming);
        cudaEventCreateWithFlags(&evJ, cudaEventDisableTiming);
        cudaEventCreateWithFlags(&evW, cudaEventDisableTiming);
    }

    // ---- fork point ----
    cudaEventRecord(evF, 0);
    cudaStreamWaitEvent(s2, evF, 0);
    cudaStreamWaitEvent(s3, evF, 0);

    // ---- s3: weight splits (DRAM-bound; overlap with tensor-bound gram) ----
    split4_kernel<<<(XDIM * HID / 4 + 1023) / 1024, 256, 0, s3>>>(Win, Wih, Wil, XDIM * HID / 4);
    split4_kernel<<<(HID * HID / 4 + 1023) / 1024, 256, 0, s3>>>(W1, W1h, W1l, HID * HID / 4);
    split4_kernel<<<(HID * HID / 4 + 1023) / 1024, 256, 0, s3>>>(W2, W2h, W2l, HID * HID / 4);
    split4_kernel<<<(HID * HID / 4 + 1023) / 1024, 256, 0, s3>>>(W3, W3h, W3l, HID * HID / 4);
    split4_kernel<<<(HID * DR / 4 + 1023) / 1024, 256, 0, s3>>>(Wout, Woh, Wol, HID * DR / 4);
    cudaEventRecord(evW, s3);

    // ---- default: prep needed by the gram chain ----
    sq_kernel<<<NN / 8, 256>>>(cond, sq);
    split4_kernel<<<(NN * DF / 4 + 1023) / 1024, 256>>>(cond, ch, cl, NN * DF / 4);
    tsplit_kernel<<<(DF * NN + 255) / 256, 256>>>(cond, cth, ctl);

    // ---- fork: gram -> topk -> rescore on s2 ----
    cudaEventRecord(evF, 0);
    cudaStreamWaitEvent(s2, evF, 0);
    mma_gemm<128, 2, 2><<<dim3(NN / 128, NN / 128), 256, 0, s2>>>(
        ch, cl, cth, ctl, sq, nullptr, key, nullptr, nullptr, NN, NN, DF);
    topk_kernel<<<NN / 8, 256, 0, s2>>>(key, cand);
    rescore_kernel<<<NN / 8, 256, 0, s2>>>(cond, sq, cand, nidx);
    cudaEventRecord(evJ, s2);

    // ---- default: MLP chain (BN=256, 512 thr, single wave: 128 CTAs) ----
    concat_split_kernel<<<(NN * XDIM + 255) / 256, 256>>>(cond, tens, x0h, x0l);
    cudaStreamWaitEvent(0, evW, 0);

    mma_gemm<256, 0, 1><<<dim3(HID / 256, NN / 128), 512>>>(
        x0h, x0l, Wih, Wil, b_in, nullptr, nullptr, hAh, hAl, NN, HID, XDIM);
    mma_gemm<256, 0, 1><<<dim3(HID / 256, NN / 128), 512>>>(
        hAh, hAl, W1h, W1l, b1, nullptr, nullptr, hBh, hBl, NN, HID, HID);
    mma_gemm<256, 0, 1><<<dim3(HID / 256, NN / 128), 512>>>(
        hBh, hBl, W2h, W2l, b2, nullptr, nullptr, hAh, hAl, NN, HID, HID);
    mma_gemm<256, 0, 1><<<dim3(HID / 256, NN / 128), 512>>>(
        hAh, hAl, W3h, W3l, b3, nullptr, nullptr, hBh, hBl, NN, HID, HID);

    mma_gemm<64, 1, 2><<<dim3(DR / 64, NN / 128), 128>>>(
        hBh, hBl, Woh, Wol, bout, tens, pushed, nullptr, nullptr, NN, DR, HID);

    // ---- join, then gather ----
    cudaStreamWaitEvent(0, evJ, 0);
    gather_kernel<<<(NN * TOPK * 16 + 255) / 256, 256>>>(nidx, pushed, out);
}

// round 11
// speedup vs baseline: 1.0359x; 1.0359x over previous
#include <cuda_runtime.h>
#include <cuda_fp16.h>
#include <cstdint>

#define NN    4096
#define DF    128
#define DR    64
#define HID   1024
#define TOPK  10
#define NCAND 16
#define XDIM  192

typedef __half f16;

// ---------------- static scratch ----------------
__device__ float g_key[(size_t)NN * NN];
__device__ float g_sq [NN];
__device__ int   g_cand[NN * NCAND];
__device__ int   g_nidx[NN * TOPK];
__device__ float g_pushed[NN * DR];

__device__ f16 g_x0h[NN * XDIM], g_x0l[NN * XDIM];
__device__ f16 g_hAh[NN * HID],  g_hAl[NN * HID];
__device__ f16 g_hBh[NN * HID],  g_hBl[NN * HID];
__device__ f16 g_ch [NN * DF],   g_cl [NN * DF];
__device__ f16 g_cth[DF * NN],   g_ctl[DF * NN];
__device__ f16 g_Wih[XDIM * HID], g_Wil[XDIM * HID];
__device__ f16 g_W1h[HID * HID],  g_W1l[HID * HID];
__device__ f16 g_W2h[HID * HID],  g_W2l[HID * HID];
__device__ f16 g_W3h[HID * HID],  g_W3l[HID * HID];
__device__ f16 g_Woh[HID * DR],   g_Wol[HID * DR];

// ---------------- helpers ----------------
__device__ __forceinline__ float sp(float x) {
    return fmaxf(x, 0.0f) + log1pf(expf(-fabsf(x)));
}

__device__ __forceinline__ void cpa16(void* s, const void* g) {
    uint32_t sa = (uint32_t)__cvta_generic_to_shared(s);
    asm volatile("cp.async.cg.shared.global [%0], [%1], 16;" :: "r"(sa), "l"(g) : "memory");
}
#define CP_COMMIT() asm volatile("cp.async.commit_group;" ::: "memory")
#define CP_WAIT1()  asm volatile("cp.async.wait_group 1;" ::: "memory")

__device__ __forceinline__ void ldm_x4(uint32_t* r, const void* p) {
    uint32_t a = (uint32_t)__cvta_generic_to_shared(p);
    asm volatile("ldmatrix.sync.aligned.m8n8.x4.shared.b16 {%0,%1,%2,%3}, [%4];"
        : "=r"(r[0]), "=r"(r[1]), "=r"(r[2]), "=r"(r[3]) : "r"(a));
}
__device__ __forceinline__ void ldm_x2t(uint32_t* r, const void* p) {
    uint32_t a = (uint32_t)__cvta_generic_to_shared(p);
    asm volatile("ldmatrix.sync.aligned.m8n8.x2.trans.shared.b16 {%0,%1}, [%2];"
        : "=r"(r[0]), "=r"(r[1]) : "r"(a));
}
__device__ __forceinline__ void mma16816(float* c, const uint32_t* a, const uint32_t* b) {
    asm volatile("mma.sync.aligned.m16n8k16.row.col.f32.f16.f16.f32 "
        "{%0,%1,%2,%3}, {%4,%5,%6,%7}, {%8,%9}, {%0,%1,%2,%3};"
        : "+f"(c[0]), "+f"(c[1]), "+f"(c[2]), "+f"(c[3])
        : "r"(a[0]), "r"(a[1]), "r"(a[2]), "r"(a[3]), "r"(b[0]), "r"(b[1]));
}

__device__ __forceinline__ void split1(float v, f16& h, f16& l) {
    h = __float2half(v);
    l = __float2half(v - __half2float(h));
}

// ---------------- small prep kernels ----------------
__global__ void sq_kernel(const float* __restrict__ cond, float* __restrict__ sq) {
    const int row  = blockIdx.x * 8 + (threadIdx.x >> 5);
    const int lane = threadIdx.x & 31;
    const float4 t = reinterpret_cast<const float4*>(cond)[row * 32 + lane];
    float s = t.x * t.x + t.y * t.y + t.z * t.z + t.w * t.w;
    #pragma unroll
    for (int o = 16; o > 0; o >>= 1) s += __shfl_down_sync(0xffffffffu, s, o);
    if (lane == 0) sq[row] = s;
}

__global__ void split4_kernel(const float* __restrict__ src, f16* __restrict__ hi,
                              f16* __restrict__ lo, int n4) {
    const int i0 = blockIdx.x * (blockDim.x * 4) + threadIdx.x;
    #pragma unroll
    for (int u = 0; u < 4; u++) {
        const int i = i0 + u * blockDim.x;
        if (i >= n4) return;
        const float4 v = reinterpret_cast<const float4*>(src)[i];
        f16 h0, l0, h1, l1, h2, l2, h3, l3;
        split1(v.x, h0, l0); split1(v.y, h1, l1);
        split1(v.z, h2, l2); split1(v.w, h3, l3);
        __half2 hh[2] = { __halves2half2(h0, h1), __halves2half2(h2, h3) };
        __half2 ll[2] = { __halves2half2(l0, l1), __halves2half2(l2, l3) };
        reinterpret_cast<uint2*>(hi)[i] = *reinterpret_cast<uint2*>(hh);
        reinterpret_cast<uint2*>(lo)[i] = *reinterpret_cast<uint2*>(ll);
    }
}

__global__ void tsplit_kernel(const float* __restrict__ cond, f16* __restrict__ hi,
                              f16* __restrict__ lo) {
    const int i = blockIdx.x * blockDim.x + threadIdx.x;
    if (i >= DF * NN) return;
    const int k = i / NN, n = i % NN;
    f16 h, l; split1(cond[n * DF + k], h, l);
    hi[i] = h; lo[i] = l;
}

__global__ void concat_split_kernel(const float* __restrict__ cond, const float* __restrict__ tens,
                                    f16* __restrict__ hi, f16* __restrict__ lo) {
    const int i = blockIdx.x * blockDim.x + threadIdx.x;
    if (i >= NN * XDIM) return;
    const int r = i / XDIM, c = i % XDIM;
    const float v = (c < DF) ? cond[r * DF + c] : tens[r * DR + (c - DF)];
    f16 h, l; split1(v, h, l);
    hi[i] = h; lo[i] = l;
}

// ---------------- split-fp16 tensor-core GEMM, BK=32 (2 x k16 per barrier) -------
// C[M,N] ~= (Ah+Al)@(Bh+Bl)  (drop lo*lo).  BM=128, warp tile 64x32.
// Dynamic smem layout: A[(buf*2+sub)*2+s][128*AST], then B[...][16*BST].
// EPI 0: softplus -> split fp16; EPI 1: extra-(acc+bias); EPI 2: gram keys.
template<int BN, int EPI, int OCC>
__global__ void __launch_bounds__((BN / 32) * 64, OCC)
mma_gemm(const f16* __restrict__ Ah, const f16* __restrict__ Al,
         const f16* __restrict__ Bh, const f16* __restrict__ Bl,
         const float* __restrict__ bias, const float* __restrict__ extra,
         float* __restrict__ Cf, f16* __restrict__ Oh, f16* __restrict__ Ol,
         int M, int N, int K)
{
    constexpr int WN = BN / 32;
    constexpr int THREADS = 2 * WN * 32;
    constexpr int AST = 24;       // per-subtile A row stride (48B, conflict-free)
    constexpr int BST = BN + 8;
    constexpr int ASZ = 128 * AST;
    constexpr int BSZ = 16 * BST;

    extern __shared__ __align__(16) f16 dsm[];
    f16* Abase = dsm;                 // 8 * ASZ halves
    f16* Bbase = dsm + 8 * ASZ;       // 8 * BSZ halves
    auto Asp = [&](int buf, int sub, int s) { return Abase + ((buf * 2 + sub) * 2 + s) * ASZ; };
    auto Bsp = [&](int buf, int sub, int s) { return Bbase + ((buf * 2 + sub) * 2 + s) * BSZ; };

    const int tid  = threadIdx.x;
    const int lane = tid & 31;
    const int w    = tid >> 5;
    const int wm   = w / WN;
    const int wn   = w % WN;
    const int row0 = blockIdx.y * 128;
    const int col0 = blockIdx.x * BN;

    float acc[4][4][4];
    #pragma unroll
    for (int a = 0; a < 4; a++)
        #pragma unroll
        for (int b = 0; b < 4; b++)
            #pragma unroll
            for (int c = 0; c < 4; c++) acc[a][b][c] = 0.0f;

    const int nchunk = K / 32;

    auto load_chunk = [&](int ci, int buf) {
        #pragma unroll
        for (int sub = 0; sub < 2; sub++) {
            const int kt = ci * 32 + sub * 16;
            #pragma unroll
            for (int s = 0; s < 2; s++) {
                const f16* Ag = s ? Al : Ah;
                f16* As = Asp(buf, sub, s);
                for (int f = tid; f < 128 * 2; f += THREADS) {
                    const int m = f >> 1, c = (f & 1) * 8;
                    cpa16(&As[m * AST + c], Ag + (size_t)(row0 + m) * K + kt + c);
                }
                const f16* Bg = s ? Bl : Bh;
                f16* Bs = Bsp(buf, sub, s);
                for (int f = tid; f < 16 * (BN / 8); f += THREADS) {
                    const int k = f / (BN / 8), c = (f % (BN / 8)) * 8;
                    cpa16(&Bs[k * BST + c], Bg + (size_t)(kt + k) * N + col0 + c);
                }
            }
        }
    };

    load_chunk(0, 0);
    CP_COMMIT();

    for (int ci = 0; ci < nchunk; ci++) {
        const int buf = ci & 1;
        if (ci + 1 < nchunk) load_chunk(ci + 1, buf ^ 1);
        CP_COMMIT();
        CP_WAIT1();
        __syncthreads();

        #pragma unroll
        for (int sub = 0; sub < 2; sub++) {
            uint32_t a[4][4], b[4][2];
            const int arow = wm * 64 + (lane & 15);
            const int acol = (lane >> 4) << 3;
            const int brow = (lane & 15) * BST;
            const int bcol = wn * 32;
            const f16* Ash = Asp(buf, sub, 0);
            const f16* Asl = Asp(buf, sub, 1);
            const f16* Bsh = Bsp(buf, sub, 0);
            const f16* Bsl = Bsp(buf, sub, 1);

            // pass 1: Ahi x Blo
            #pragma unroll
            for (int mt = 0; mt < 4; mt++)
                ldm_x4(a[mt], &Ash[(arow + mt * 16) * AST + acol]);
            #pragma unroll
            for (int nt = 0; nt < 4; nt++)
                ldm_x2t(b[nt], &Bsl[brow + bcol + nt * 8]);
            #pragma unroll
            for (int mt = 0; mt < 4; mt++)
                #pragma unroll
                for (int nt = 0; nt < 4; nt++) mma16816(acc[mt][nt], a[mt], b[nt]);

            // pass 2: Ahi x Bhi
            #pragma unroll
            for (int nt = 0; nt < 4; nt++)
                ldm_x2t(b[nt], &Bsh[brow + bcol + nt * 8]);
            #pragma unroll
            for (int mt = 0; mt < 4; mt++)
                #pragma unroll
                for (int nt = 0; nt < 4; nt++) mma16816(acc[mt][nt], a[mt], b[nt]);

            // pass 3: Alo x Bhi
            #pragma unroll
            for (int mt = 0; mt < 4; mt++)
                ldm_x4(a[mt], &Asl[(arow + mt * 16) * AST + acol]);
            #pragma unroll
            for (int mt = 0; mt < 4; mt++)
                #pragma unroll
                for (int nt = 0; nt < 4; nt++) mma16816(acc[mt][nt], a[mt], b[nt]);
        }
        __syncthreads();
    }

    // epilogue
    #pragma unroll
    for (int mt = 0; mt < 4; mt++) {
        #pragma unroll
        for (int nt = 0; nt < 4; nt++) {
            const int r = row0 + wm * 64 + mt * 16 + (lane >> 2);
            const int c = col0 + wn * 32 + nt * 8 + ((lane & 3) << 1);
            const float* ac = acc[mt][nt];
            if constexpr (EPI == 0) {
                const float bc0 = bias[c], bc1 = bias[c + 1];
                #pragma unroll
                for (int h = 0; h < 2; h++) {
                    const int rr = r + 8 * h;
                    const float y0 = sp(ac[2 * h] + bc0);
                    const float y1 = sp(ac[2 * h + 1] + bc1);
                    f16 h0, l0, h1, l1;
                    split1(y0, h0, l0); split1(y1, h1, l1);
                    *(__half2*)(Oh + (size_t)rr * N + c) = __halves2half2(h0, h1);
                    *(__half2*)(Ol + (size_t)rr * N + c) = __halves2half2(l0, l1);
                }
            } else if constexpr (EPI == 1) {
                const float bc0 = bias[c], bc1 = bias[c + 1];
                #pragma unroll
                for (int h = 0; h < 2; h++) {
                    const size_t o = (size_t)(r + 8 * h) * N + c;
                    Cf[o]     = extra[o]     - (ac[2 * h]     + bc0);
                    Cf[o + 1] = extra[o + 1] - (ac[2 * h + 1] + bc1);
                }
            } else {
                const float sc0 = bias[c], sc1 = bias[c + 1];
                #pragma unroll
                for (int h = 0; h < 2; h++) {
                    const float sr = bias[r + 8 * h];
                    const size_t o = (size_t)(r + 8 * h) * NN + c;
                    Cf[o]     = fmaxf(sr + sc0 - 2.0f * ac[2 * h],     0.0f);
                    Cf[o + 1] = fmaxf(sr + sc1 - 2.0f * ac[2 * h + 1], 0.0f);
                }
            }
        }
    }
}

// ---------------- top-NCAND smallest per row (approx keys), register lists ------
template<int L>
__device__ __forceinline__ void insL(float x, int j, float (&v)[L], int (&id)[L]) {
    if (x >= v[L - 1]) return;
    #pragma unroll
    for (int t = L - 1; t > 0; t--) {
        const bool shf = (x < v[t - 1]);
        const bool put = !shf && (x < v[t]);
        v[t]  = shf ? v[t - 1]  : (put ? x : v[t]);
        id[t] = shf ? id[t - 1] : (put ? j : id[t]);
    }
    if (x < v[0]) { v[0] = x; id[0] = j; }
}

__global__ void topk_kernel(const float* __restrict__ key, int* __restrict__ out_cand) {
    const int row  = blockIdx.x * 8 + (threadIdx.x >> 5);
    const int lane = threadIdx.x & 31;
    const float4* k4 = reinterpret_cast<const float4*>(key + (size_t)row * NN);

    float v[NCAND]; int id[NCAND];
    #pragma unroll
    for (int t = 0; t < NCAND; t++) { v[t] = 3.0e38f; id[t] = 0x7fffffff; }

    #pragma unroll 4
    for (int j = lane; j < NN / 4; j += 32) {
        const float4 t = k4[j];
        const int b = 4 * j;
        insL<NCAND>(t.x, b,     v, id);
        insL<NCAND>(t.y, b + 1, v, id);
        insL<NCAND>(t.z, b + 2, v, id);
        insL<NCAND>(t.w, b + 3, v, id);
    }

    #pragma unroll
    for (int k = 0; k < NCAND; k++) {
        float mv = v[0]; int mi = id[0];
        #pragma unroll
        for (int off = 16; off > 0; off >>= 1) {
            const float ov = __shfl_down_sync(0xffffffffu, mv, off);
            const int   oi = __shfl_down_sync(0xffffffffu, mi, off);
            if (ov < mv || (ov == mv && oi < mi)) { mv = ov; mi = oi; }
        }
        mv = __shfl_sync(0xffffffffu, mv, 0);
        mi = __shfl_sync(0xffffffffu, mi, 0);
        if (id[0] == mi) {
            #pragma unroll
            for (int t = 0; t < NCAND - 1; t++) { v[t] = v[t + 1]; id[t] = id[t + 1]; }
            v[NCAND - 1] = 3.0e38f; id[NCAND - 1] = 0x7fffffff;
        }
        if (lane == 0) out_cand[row * NCAND + k] = mi;
    }
}

// ---------------- exact fp32 rescore of the 16 candidates -> final top-10 --------
__global__ void rescore_kernel(const float* __restrict__ cond, const float* __restrict__ sq,
                               const int* __restrict__ cand, int* __restrict__ out_idx) {
    const int row  = blockIdx.x * 8 + (threadIdx.x >> 5);
    const int lane = threadIdx.x & 31;
    const float4 cr = reinterpret_cast<const float4*>(cond)[row * 32 + lane];
    const float sr = sq[row];

    float mv = 3.0e38f; int mid = 0x7fffffff;
    #pragma unroll
    for (int c = 0; c < NCAND; c++) {
        const int j = cand[row * NCAND + c];
        const float4 cc = reinterpret_cast<const float4*>(cond)[j * 32 + lane];
        float d = cr.x * cc.x + cr.y * cc.y + cr.z * cc.z + cr.w * cc.w;
        #pragma unroll
        for (int o = 16; o > 0; o >>= 1) d += __shfl_down_sync(0xffffffffu, d, o);
        d = __shfl_sync(0xffffffffu, d, 0);
        const float k = fmaxf(sr + sq[j] - 2.0f * d, 0.0f);
        if (lane == c) { mv = k; mid = j; }
    }

    #pragma unroll
    for (int k = 0; k < TOPK; k++) {
        float bv = mv; int bi = mid;
        #pragma unroll
        for (int off = 16; off > 0; off >>= 1) {
            const float ov = __shfl_down_sync(0xffffffffu, bv, off);
            const int   oi = __shfl_down_sync(0xffffffffu, bi, off);
            if (ov < bv || (ov == bv && oi < bi)) { bv = ov; bi = oi; }
        }
        bv = __shfl_sync(0xffffffffu, bv, 0);
        bi = __shfl_sync(0xffffffffu, bi, 0);
        if (mid == bi) { mv = 3.0e38f; mid = 0x7fffffff; }
        if (lane == 0) out_idx[row * TOPK + k] = bi;
    }
}

// ---------------- final gather ----------------
__global__ void gather_kernel(const int* __restrict__ nidx, const float* __restrict__ pushed,
                              float* __restrict__ out) {
    const int t = blockIdx.x * blockDim.x + threadIdx.x;
    if (t >= NN * TOPK * 16) return;
    const int r = t >> 4, c = t & 15;
    const int j = nidx[r];
    reinterpret_cast<float4*>(out)[t] = reinterpret_cast<const float4*>(pushed)[j * 16 + c];
}

// ---------------- launch ----------------
extern "C" void kernel_launch(void* const* d_in, const int* in_sizes, int n_in,
                              void* d_out, int out_size)
{
    const float* cond = (const float*)d_in[0];
    const float* tens = (const float*)d_in[1];
    const float* Win  = (const float*)d_in[2];
    const float* b_in = (const float*)d_in[3];
    const float* W1   = (const float*)d_in[4];
    const float* b1   = (const float*)d_in[5];
    const float* W2   = (const float*)d_in[6];
    const float* b2   = (const float*)d_in[7];
    const float* W3   = (const float*)d_in[8];
    const float* b3   = (const float*)d_in[9];
    const float* Wout = (const float*)d_in[10];
    const float* bout = (const float*)d_in[11];
    float* out = (float*)d_out;

    float *key, *sq, *pushed; int *cand, *nidx;
    f16 *x0h, *x0l, *hAh, *hAl, *hBh, *hBl, *ch, *cl, *cth, *ctl;
    f16 *Wih, *Wil, *W1h, *W1l, *W2h, *W2l, *W3h, *W3l, *Woh, *Wol;
    cudaGetSymbolAddress((void**)&key, g_key);
    cudaGetSymbolAddress((void**)&sq, g_sq);
    cudaGetSymbolAddress((void**)&cand, g_cand);
    cudaGetSymbolAddress((void**)&nidx, g_nidx);
    cudaGetSymbolAddress((void**)&pushed, g_pushed);
    cudaGetSymbolAddress((void**)&x0h, g_x0h); cudaGetSymbolAddress((void**)&x0l, g_x0l);
    cudaGetSymbolAddress((void**)&hAh, g_hAh); cudaGetSymbolAddress((void**)&hAl, g_hAl);
    cudaGetSymbolAddress((void**)&hBh, g_hBh); cudaGetSymbolAddress((void**)&hBl, g_hBl);
    cudaGetSymbolAddress((void**)&ch,  g_ch);  cudaGetSymbolAddress((void**)&cl,  g_cl);
    cudaGetSymbolAddress((void**)&cth, g_cth); cudaGetSymbolAddress((void**)&ctl, g_ctl);
    cudaGetSymbolAddress((void**)&Wih, g_Wih); cudaGetSymbolAddress((void**)&Wil, g_Wil);
    cudaGetSymbolAddress((void**)&W1h, g_W1h); cudaGetSymbolAddress((void**)&W1l, g_W1l);
    cudaGetSymbolAddress((void**)&W2h, g_W2h); cudaGetSymbolAddress((void**)&W2l, g_W2l);
    cudaGetSymbolAddress((void**)&W3h, g_W3h); cudaGetSymbolAddress((void**)&W3l, g_W3l);
    cudaGetSymbolAddress((void**)&Woh, g_Woh); cudaGetSymbolAddress((void**)&Wol, g_Wol);

    // dynamic smem sizes: 8*(128*24 + 16*(BN+8)) halves
    const int SMEM128 = 2 * 8 * (128 * 24 + 16 * (128 + 8));   // 83968 B
    const int SMEM64  = 2 * 8 * (128 * 24 + 16 * (64 + 8));    // 67584 B

    // lazy-create side streams + events + smem opt-in (outside graph capture)
    static cudaStream_t s2 = nullptr, s3 = nullptr;
    static cudaEvent_t evF = nullptr, evJ = nullptr, evW = nullptr;
    if (s2 == nullptr) {
        cudaStreamCreateWithFlags(&s2, cudaStreamNonBlocking);
        cudaStreamCreateWithFlags(&s3, cudaStreamNonBlocking);
        cudaEventCreateWithFlags(&evF, cudaEventDisableTiming);
        cudaEventCreateWithFlags(&evJ, cudaEventDisableTiming);
        cudaEventCreateWithFlags(&evW, cudaEventDisableTiming);
        cudaFuncSetAttribute(mma_gemm<128, 0, 2>, cudaFuncAttributeMaxDynamicSharedMemorySize, SMEM128);
        cudaFuncSetAttribute(mma_gemm<128, 2, 2>, cudaFuncAttributeMaxDynamicSharedMemorySize, SMEM128);
        cudaFuncSetAttribute(mma_gemm<64, 1, 2>,  cudaFuncAttributeMaxDynamicSharedMemorySize, SMEM64);
    }

    // ---- fork point ----
    cudaEventRecord(evF, 0);
    cudaStreamWaitEvent(s2, evF, 0);
    cudaStreamWaitEvent(s3, evF, 0);

    // ---- s3: weight splits (DRAM-bound; overlap with tensor-bound gram) ----
    split4_kernel<<<(XDIM * HID / 4 + 1023) / 1024, 256, 0, s3>>>(Win, Wih, Wil, XDIM * HID / 4);
    split4_kernel<<<(HID * HID / 4 + 1023) / 1024, 256, 0, s3>>>(W1, W1h, W1l, HID * HID / 4);
    split4_kernel<<<(HID * HID / 4 + 1023) / 1024, 256, 0, s3>>>(W2, W2h, W2l, HID * HID / 4);
    split4_kernel<<<(HID * HID / 4 + 1023) / 1024, 256, 0, s3>>>(W3, W3h, W3l, HID * HID / 4);
    split4_kernel<<<(HID * DR / 4 + 1023) / 1024, 256, 0, s3>>>(Wout, Woh, Wol, HID * DR / 4);
    cudaEventRecord(evW, s3);

    // ---- default: prep needed by the gram chain ----
    sq_kernel<<<NN / 8, 256>>>(cond, sq);
    split4_kernel<<<(NN * DF / 4 + 1023) / 1024, 256>>>(cond, ch, cl, NN * DF / 4);
    tsplit_kernel<<<(DF * NN + 255) / 256, 256>>>(cond, cth, ctl);

    // ---- fork: gram -> topk -> rescore on s2 ----
    cudaEventRecord(evF, 0);
    cudaStreamWaitEvent(s2, evF, 0);
    mma_gemm<128, 2, 2><<<dim3(NN / 128, NN / 128), 256, SMEM128, s2>>>(
        ch, cl, cth, ctl, sq, nullptr, key, nullptr, nullptr, NN, NN, DF);
    topk_kernel<<<NN / 8, 256, 0, s2>>>(key, cand);
    rescore_kernel<<<NN / 8, 256, 0, s2>>>(cond, sq, cand, nidx);
    cudaEventRecord(evJ, s2);

    // ---- default: MLP chain (BN=128, 256 thr, occ 2) ----
    concat_split_kernel<<<(NN * XDIM + 255) / 256, 256>>>(cond, tens, x0h, x0l);
    cudaStreamWaitEvent(0, evW, 0);

    mma_gemm<128, 0, 2><<<dim3(HID / 128, NN / 128), 256, SMEM128>>>(
        x0h, x0l, Wih, Wil, b_in, nullptr, nullptr, hAh, hAl, NN, HID, XDIM);
    mma_gemm<128, 0, 2><<<dim3(HID / 128, NN / 128), 256, SMEM128>>>(
        hAh, hAl, W1h, W1l, b1, nullptr, nullptr, hBh, hBl, NN, HID, HID);
    mma_gemm<128, 0, 2><<<dim3(HID / 128, NN / 128), 256, SMEM128>>>(
        hBh, hBl, W2h, W2l, b2, nullptr, nullptr, hAh, hAl, NN, HID, HID);
    mma_gemm<128, 0, 2><<<dim3(HID / 128, NN / 128), 256, SMEM128>>>(
        hAh, hAl, W3h, W3l, b3, nullptr, nullptr, hBh, hBl, NN, HID, HID);

    mma_gemm<64, 1, 2><<<dim3(DR / 64, NN / 128), 128, SMEM64>>>(
        hBh, hBl, Woh, Wol, bout, tens, pushed, nullptr, nullptr, NN, DR, HID);

    // ---- join, then gather ----
    cudaStreamWaitEvent(0, evJ, 0);
    gather_kernel<<<(NN * TOPK * 16 + 255) / 256, 256>>>(nidx, pushed, out);
}

// round 12
// speedup vs baseline: 1.0744x; 1.0372x over previous
#include <cuda_runtime.h>
#include <cuda_fp16.h>
#include <cstdint>

#define NN    4096
#define DF    128
#define DR    64
#define HID   1024
#define TOPK  10
#define NCAND 16
#define XDIM  192

typedef __half f16;

// ---------------- static scratch ----------------
__device__ float g_key[(size_t)NN * NN];
__device__ float g_sq [NN];
__device__ int   g_cand[NN * NCAND];
__device__ int   g_nidx[NN * TOPK];
__device__ float g_pushed[NN * DR];

__device__ f16 g_x0h[NN * XDIM], g_x0l[NN * XDIM];
__device__ f16 g_hAh[NN * HID],  g_hAl[NN * HID];
__device__ f16 g_hBh[NN * HID],  g_hBl[NN * HID];
__device__ f16 g_ch [NN * DF],   g_cl [NN * DF];
__device__ f16 g_cth[DF * NN],   g_ctl[DF * NN];
__device__ f16 g_Wih[XDIM * HID], g_Wil[XDIM * HID];
__device__ f16 g_W1h[HID * HID],  g_W1l[HID * HID];
__device__ f16 g_W2h[HID * HID],  g_W2l[HID * HID];
__device__ f16 g_W3h[HID * HID],  g_W3l[HID * HID];
__device__ f16 g_Woh[HID * DR],   g_Wol[HID * DR];

// ---------------- helpers ----------------
__device__ __forceinline__ float sp(float x) {
    return fmaxf(x, 0.0f) + log1pf(expf(-fabsf(x)));
}

__device__ __forceinline__ void cpa16(void* s, const void* g) {
    uint32_t sa = (uint32_t)__cvta_generic_to_shared(s);
    asm volatile("cp.async.cg.shared.global [%0], [%1], 16;" :: "r"(sa), "l"(g) : "memory");
}
#define CP_COMMIT() asm volatile("cp.async.commit_group;" ::: "memory")
#define CP_WAIT1()  asm volatile("cp.async.wait_group 1;" ::: "memory")

__device__ __forceinline__ void ldm_x4(uint32_t* r, const void* p) {
    uint32_t a = (uint32_t)__cvta_generic_to_shared(p);
    asm volatile("ldmatrix.sync.aligned.m8n8.x4.shared.b16 {%0,%1,%2,%3}, [%4];"
        : "=r"(r[0]), "=r"(r[1]), "=r"(r[2]), "=r"(r[3]) : "r"(a));
}
__device__ __forceinline__ void ldm_x2t(uint32_t* r, const void* p) {
    uint32_t a = (uint32_t)__cvta_generic_to_shared(p);
    asm volatile("ldmatrix.sync.aligned.m8n8.x2.trans.shared.b16 {%0,%1}, [%2];"
        : "=r"(r[0]), "=r"(r[1]) : "r"(a));
}
__device__ __forceinline__ void mma16816(float* c, const uint32_t* a, const uint32_t* b) {
    asm volatile("mma.sync.aligned.m16n8k16.row.col.f32.f16.f16.f32 "
        "{%0,%1,%2,%3}, {%4,%5,%6,%7}, {%8,%9}, {%0,%1,%2,%3};"
        : "+f"(c[0]), "+f"(c[1]), "+f"(c[2]), "+f"(c[3])
        : "r"(a[0]), "r"(a[1]), "r"(a[2]), "r"(a[3]), "r"(b[0]), "r"(b[1]));
}

__device__ __forceinline__ void split1(float v, f16& h, f16& l) {
    h = __float2half(v);
    l = __float2half(v - __half2float(h));
}

// ---------------- small prep kernels ----------------
__global__ void sq_kernel(const float* __restrict__ cond, float* __restrict__ sq) {
    const int row  = blockIdx.x * 8 + (threadIdx.x >> 5);
    const int lane = threadIdx.x & 31;
    const float4 t = reinterpret_cast<const float4*>(cond)[row * 32 + lane];
    float s = t.x * t.x + t.y * t.y + t.z * t.z + t.w * t.w;
    #pragma unroll
    for (int o = 16; o > 0; o >>= 1) s += __shfl_down_sync(0xffffffffu, s, o);
    if (lane == 0) sq[row] = s;
}

__global__ void split4_kernel(const float* __restrict__ src, f16* __restrict__ hi,
                              f16* __restrict__ lo, int n4) {
    const int i0 = blockIdx.x * (blockDim.x * 4) + threadIdx.x;
    #pragma unroll
    for (int u = 0; u < 4; u++) {
        const int i = i0 + u * blockDim.x;
        if (i >= n4) return;
        const float4 v = reinterpret_cast<const float4*>(src)[i];
        f16 h0, l0, h1, l1, h2, l2, h3, l3;
        split1(v.x, h0, l0); split1(v.y, h1, l1);
        split1(v.z, h2, l2); split1(v.w, h3, l3);
        __half2 hh[2] = { __halves2half2(h0, h1), __halves2half2(h2, h3) };
        __half2 ll[2] = { __halves2half2(l0, l1), __halves2half2(l2, l3) };
        reinterpret_cast<uint2*>(hi)[i] = *reinterpret_cast<uint2*>(hh);
        reinterpret_cast<uint2*>(lo)[i] = *reinterpret_cast<uint2*>(ll);
    }
}

__global__ void tsplit_kernel(const float* __restrict__ cond, f16* __restrict__ hi,
                              f16* __restrict__ lo) {
    const int i = blockIdx.x * blockDim.x + threadIdx.x;
    if (i >= DF * NN) return;
    const int k = i / NN, n = i % NN;
    f16 h, l; split1(cond[n * DF + k], h, l);
    hi[i] = h; lo[i] = l;
}

__global__ void concat_split_kernel(const float* __restrict__ cond, const float* __restrict__ tens,
                                    f16* __restrict__ hi, f16* __restrict__ lo) {
    const int i = blockIdx.x * blockDim.x + threadIdx.x;
    if (i >= NN * XDIM) return;
    const int r = i / XDIM, c = i % XDIM;
    const float v = (c < DF) ? cond[r * DF + c] : tens[r * DR + (c - DF)];
    f16 h, l; split1(v, h, l);
    hi[i] = h; lo[i] = l;
}

// ---------------- split-fp16 tensor-core GEMM, BK=32 -------
// PASSES==3: C ~= (Ah+Al)@(Bh+Bl) minus lo*lo (split precision, MLP layers).
// PASSES==1: C ~= Ah@Bh (plain fp16; gram keys -- protected by exact rescore).
// BM=128, warp tile 64x32.
// EPI 0: softplus -> split fp16; EPI 1: extra-(acc+bias); EPI 2: gram keys.
template<int BN, int EPI, int OCC, int PASSES>
__global__ void __launch_bounds__((BN / 32) * 64, OCC)
mma_gemm(const f16* __restrict__ Ah, const f16* __restrict__ Al,
         const f16* __restrict__ Bh, const f16* __restrict__ Bl,
         const float* __restrict__ bias, const float* __restrict__ extra,
         float* __restrict__ Cf, f16* __restrict__ Oh, f16* __restrict__ Ol,
         int M, int N, int K)
{
    constexpr int WN = BN / 32;
    constexpr int THREADS = 2 * WN * 32;
    constexpr int AST = 24;       // per-subtile A row stride (48B, conflict-free)
    constexpr int BST = BN + 8;
    constexpr int ASZ = 128 * AST;
    constexpr int BSZ = 16 * BST;
    constexpr int NSLOT = (PASSES == 1) ? 4 : 8;   // buf(2) x sub(2) x split(1|2)

    extern __shared__ __align__(16) f16 dsm[];
    f16* Abase = dsm;
    f16* Bbase = dsm + NSLOT * ASZ;
    auto slot = [&](int buf, int sub, int s) {
        return (PASSES == 1) ? (buf * 2 + sub) : ((buf * 2 + sub) * 2 + s);
    };
    auto Asp = [&](int buf, int sub, int s) { return Abase + slot(buf, sub, s) * ASZ; };
    auto Bsp = [&](int buf, int sub, int s) { return Bbase + slot(buf, sub, s) * BSZ; };

    const int tid  = threadIdx.x;
    const int lane = tid & 31;
    const int w    = tid >> 5;
    const int wm   = w / WN;
    const int wn   = w % WN;
    const int row0 = blockIdx.y * 128;
    const int col0 = blockIdx.x * BN;

    float acc[4][4][4];
    #pragma unroll
    for (int a = 0; a < 4; a++)
        #pragma unroll
        for (int b = 0; b < 4; b++)
            #pragma unroll
            for (int c = 0; c < 4; c++) acc[a][b][c] = 0.0f;

    const int nchunk = K / 32;
    constexpr int NSPLIT = (PASSES == 1) ? 1 : 2;

    auto load_chunk = [&](int ci, int buf) {
        #pragma unroll
        for (int sub = 0; sub < 2; sub++) {
            const int kt = ci * 32 + sub * 16;
            #pragma unroll
            for (int s = 0; s < NSPLIT; s++) {
                const f16* Ag = s ? Al : Ah;
                f16* As = Asp(buf, sub, s);
                for (int f = tid; f < 128 * 2; f += THREADS) {
                    const int m = f >> 1, c = (f & 1) * 8;
                    cpa16(&As[m * AST + c], Ag + (size_t)(row0 + m) * K + kt + c);
                }
                const f16* Bg = s ? Bl : Bh;
                f16* Bs = Bsp(buf, sub, s);
                for (int f = tid; f < 16 * (BN / 8); f += THREADS) {
                    const int k = f / (BN / 8), c = (f % (BN / 8)) * 8;
                    cpa16(&Bs[k * BST + c], Bg + (size_t)(kt + k) * N + col0 + c);
                }
            }
        }
    };

    load_chunk(0, 0);
    CP_COMMIT();

    for (int ci = 0; ci < nchunk; ci++) {
        const int buf = ci & 1;
        if (ci + 1 < nchunk) load_chunk(ci + 1, buf ^ 1);
        CP_COMMIT();
        CP_WAIT1();
        __syncthreads();

        #pragma unroll
        for (int sub = 0; sub < 2; sub++) {
            uint32_t a[4][4], b[4][2];
            const int arow = wm * 64 + (lane & 15);
            const int acol = (lane >> 4) << 3;
            const int brow = (lane & 15) * BST;
            const int bcol = wn * 32;
            const f16* Ash = Asp(buf, sub, 0);
            const f16* Bsh = Bsp(buf, sub, 0);

            if constexpr (PASSES == 1) {
                // single pass: Ah x Bh
                #pragma unroll
                for (int mt = 0; mt < 4; mt++)
                    ldm_x4(a[mt], &Ash[(arow + mt * 16) * AST + acol]);
                #pragma unroll
                for (int nt = 0; nt < 4; nt++)
                    ldm_x2t(b[nt], &Bsh[brow + bcol + nt * 8]);
                #pragma unroll
                for (int mt = 0; mt < 4; mt++)
                    #pragma unroll
                    for (int nt = 0; nt < 4; nt++) mma16816(acc[mt][nt], a[mt], b[nt]);
            } else {
                const f16* Asl = Asp(buf, sub, 1);
                const f16* Bsl = Bsp(buf, sub, 1);

                // pass 1: Ahi x Blo
                #pragma unroll
                for (int mt = 0; mt < 4; mt++)
                    ldm_x4(a[mt], &Ash[(arow + mt * 16) * AST + acol]);
                #pragma unroll
                for (int nt = 0; nt < 4; nt++)
                    ldm_x2t(b[nt], &Bsl[brow + bcol + nt * 8]);
                #pragma unroll
                for (int mt = 0; mt < 4; mt++)
                    #pragma unroll
                    for (int nt = 0; nt < 4; nt++) mma16816(acc[mt][nt], a[mt], b[nt]);

                // pass 2: Ahi x Bhi
                #pragma unroll
                for (int nt = 0; nt < 4; nt++)
                    ldm_x2t(b[nt], &Bsh[brow + bcol + nt * 8]);
                #pragma unroll
                for (int mt = 0; mt < 4; mt++)
                    #pragma unroll
                    for (int nt = 0; nt < 4; nt++) mma16816(acc[mt][nt], a[mt], b[nt]);

                // pass 3: Alo x Bhi
                #pragma unroll
                for (int mt = 0; mt < 4; mt++)
                    ldm_x4(a[mt], &Asl[(arow + mt * 16) * AST + acol]);
                #pragma unroll
                for (int mt = 0; mt < 4; mt++)
                    #pragma unroll
                    for (int nt = 0; nt < 4; nt++) mma16816(acc[mt][nt], a[mt], b[nt]);
            }
        }
        __syncthreads();
    }

    // epilogue
    #pragma unroll
    for (int mt = 0; mt < 4; mt++) {
        #pragma unroll
        for (int nt = 0; nt < 4; nt++) {
            const int r = row0 + wm * 64 + mt * 16 + (lane >> 2);
            const int c = col0 + wn * 32 + nt * 8 + ((lane & 3) << 1);
            const float* ac = acc[mt][nt];
            if constexpr (EPI == 0) {
                const float bc0 = bias[c], bc1 = bias[c + 1];
                #pragma unroll
                for (int h = 0; h < 2; h++) {
                    const int rr = r + 8 * h;
                    const float y0 = sp(ac[2 * h] + bc0);
                    const float y1 = sp(ac[2 * h + 1] + bc1);
                    f16 h0, l0, h1, l1;
                    split1(y0, h0, l0); split1(y1, h1, l1);
                    *(__half2*)(Oh + (size_t)rr * N + c) = __halves2half2(h0, h1);
                    *(__half2*)(Ol + (size_t)rr * N + c) = __halves2half2(l0, l1);
                }
            } else if constexpr (EPI == 1) {
                const float bc0 = bias[c], bc1 = bias[c + 1];
                #pragma unroll
                for (int h = 0; h < 2; h++) {
                    const size_t o = (size_t)(r + 8 * h) * N + c;
                    Cf[o]     = extra[o]     - (ac[2 * h]     + bc0);
                    Cf[o + 1] = extra[o + 1] - (ac[2 * h + 1] + bc1);
                }
            } else {
                const float sc0 = bias[c], sc1 = bias[c + 1];
                #pragma unroll
                for (int h = 0; h < 2; h++) {
                    const float sr = bias[r + 8 * h];
                    const size_t o = (size_t)(r + 8 * h) * NN + c;
                    Cf[o]     = fmaxf(sr + sc0 - 2.0f * ac[2 * h],     0.0f);
                    Cf[o + 1] = fmaxf(sr + sc1 - 2.0f * ac[2 * h + 1], 0.0f);
                }
            }
        }
    }
}

// ---------------- top-NCAND smallest per row (approx keys), register lists ------
template<int L>
__device__ __forceinline__ void insL(float x, int j, float (&v)[L], int (&id)[L]) {
    if (x >= v[L - 1]) return;
    #pragma unroll
    for (int t = L - 1; t > 0; t--) {
        const bool shf = (x < v[t - 1]);
        const bool put = !shf && (x < v[t]);
        v[t]  = shf ? v[t - 1]  : (put ? x : v[t]);
        id[t] = shf ? id[t - 1] : (put ? j : id[t]);
    }
    if (x < v[0]) { v[0] = x; id[0] = j; }
}

__global__ void topk_kernel(const float* __restrict__ key, int* __restrict__ out_cand) {
    const int row  = blockIdx.x * 8 + (threadIdx.x >> 5);
    const int lane = threadIdx.x & 31;
    const float4* k4 = reinterpret_cast<const float4*>(key + (size_t)row * NN);

    float v[NCAND]; int id[NCAND];
    #pragma unroll
    for (int t = 0; t < NCAND; t++) { v[t] = 3.0e38f; id[t] = 0x7fffffff; }

    #pragma unroll 4
    for (int j = lane; j < NN / 4; j += 32) {
        const float4 t = k4[j];
        const int b = 4 * j;
        insL<NCAND>(t.x, b,     v, id);
        insL<NCAND>(t.y, b + 1, v, id);
        insL<NCAND>(t.z, b + 2, v, id);
        insL<NCAND>(t.w, b + 3, v, id);
    }

    #pragma unroll
    for (int k = 0; k < NCAND; k++) {
        float mv = v[0]; int mi = id[0];
        #pragma unroll
        for (int off = 16; off > 0; off >>= 1) {
            const float ov = __shfl_down_sync(0xffffffffu, mv, off);
            const int   oi = __shfl_down_sync(0xffffffffu, mi, off);
            if (ov < mv || (ov == mv && oi < mi)) { mv = ov; mi = oi; }
        }
        mv = __shfl_sync(0xffffffffu, mv, 0);
        mi = __shfl_sync(0xffffffffu, mi, 0);
        if (id[0] == mi) {
            #pragma unroll
            for (int t = 0; t < NCAND - 1; t++) { v[t] = v[t + 1]; id[t] = id[t + 1]; }
            v[NCAND - 1] = 3.0e38f; id[NCAND - 1] = 0x7fffffff;
        }
        if (lane == 0) out_cand[row * NCAND + k] = mi;
    }
}

// ---------------- exact fp32 rescore of the 16 candidates -> final top-10 --------
__global__ void rescore_kernel(const float* __restrict__ cond, const float* __restrict__ sq,
                               const int* __restrict__ cand, int* __restrict__ out_idx) {
    const int row  = blockIdx.x * 8 + (threadIdx.x >> 5);
    const int lane = threadIdx.x & 31;
    const float4 cr = reinterpret_cast<const float4*>(cond)[row * 32 + lane];
    const float sr = sq[row];

    float mv = 3.0e38f; int mid = 0x7fffffff;
    #pragma unroll
    for (int c = 0; c < NCAND; c++) {
        const int j = cand[row * NCAND + c];
        const float4 cc = reinterpret_cast<const float4*>(cond)[j * 32 + lane];
        float d = cr.x * cc.x + cr.y * cc.y + cr.z * cc.z + cr.w * cc.w;
        #pragma unroll
        for (int o = 16; o > 0; o >>= 1) d += __shfl_down_sync(0xffffffffu, d, o);
        d = __shfl_sync(0xffffffffu, d, 0);
        const float k = fmaxf(sr + sq[j] - 2.0f * d, 0.0f);
        if (lane == c) { mv = k; mid = j; }
    }

    #pragma unroll
    for (int k = 0; k < TOPK; k++) {
        float bv = mv; int bi = mid;
        #pragma unroll
        for (int off = 16; off > 0; off >>= 1) {
            const float ov = __shfl_down_sync(0xffffffffu, bv, off);
            const int   oi = __shfl_down_sync(0xffffffffu, bi, off);
            if (ov < bv || (ov == bv && oi < bi)) { bv = ov; bi = oi; }
        }
        bv = __shfl_sync(0xffffffffu, bv, 0);
        bi = __shfl_sync(0xffffffffu, bi, 0);
        if (mid == bi) { mv = 3.0e38f; mid = 0x7fffffff; }
        if (lane == 0) out_idx[row * TOPK + k] = bi;
    }
}

// ---------------- final gather ----------------
__global__ void gather_kernel(const int* __restrict__ nidx, const float* __restrict__ pushed,
                              float* __restrict__ out) {
    const int t = blockIdx.x * blockDim.x + threadIdx.x;
    if (t >= NN * TOPK * 16) return;
    const int r = t >> 4, c = t & 15;
    const int j = nidx[r];
    reinterpret_cast<float4*>(out)[t] = reinterpret_cast<const float4*>(pushed)[j * 16 + c];
}

// ---------------- launch ----------------
extern "C" void kernel_launch(void* const* d_in, const int* in_sizes, int n_in,
                              void* d_out, int out_size)
{
    const float* cond = (const float*)d_in[0];
    const float* tens = (const float*)d_in[1];
    const float* Win  = (const float*)d_in[2];
    const float* b_in = (const float*)d_in[3];
    const float* W1   = (const float*)d_in[4];
    const float* b1   = (const float*)d_in[5];
    const float* W2   = (const float*)d_in[6];
    const float* b2   = (const float*)d_in[7];
    const float* W3   = (const float*)d_in[8];
    const float* b3   = (const float*)d_in[9];
    const float* Wout = (const float*)d_in[10];
    const float* bout = (const float*)d_in[11];
    float* out = (float*)d_out;

    float *key, *sq, *pushed; int *cand, *nidx;
    f16 *x0h, *x0l, *hAh, *hAl, *hBh, *hBl, *ch, *cl, *cth, *ctl;
    f16 *Wih, *Wil, *W1h, *W1l, *W2h, *W2l, *W3h, *W3l, *Woh, *Wol;
    cudaGetSymbolAddress((void**)&key, g_key);
    cudaGetSymbolAddress((void**)&sq, g_sq);
    cudaGetSymbolAddress((void**)&cand, g_cand);
    cudaGetSymbolAddress((void**)&nidx, g_nidx);
    cudaGetSymbolAddress((void**)&pushed, g_pushed);
    cudaGetSymbolAddress((void**)&x0h, g_x0h); cudaGetSymbolAddress((void**)&x0l, g_x0l);
    cudaGetSymbolAddress((void**)&hAh, g_hAh); cudaGetSymbolAddress((void**)&hAl, g_hAl);
    cudaGetSymbolAddress((void**)&hBh, g_hBh); cudaGetSymbolAddress((void**)&hBl, g_hBl);
    cudaGetSymbolAddress((void**)&ch,  g_ch);  cudaGetSymbolAddress((void**)&cl,  g_cl);
    cudaGetSymbolAddress((void**)&cth, g_cth); cudaGetSymbolAddress((void**)&ctl, g_ctl);
    cudaGetSymbolAddress((void**)&Wih, g_Wih); cudaGetSymbolAddress((void**)&Wil, g_Wil);
    cudaGetSymbolAddress((void**)&W1h, g_W1h); cudaGetSymbolAddress((void**)&W1l, g_W1l);
    cudaGetSymbolAddress((void**)&W2h, g_W2h); cudaGetSymbolAddress((void**)&W2l, g_W2l);
    cudaGetSymbolAddress((void**)&W3h, g_W3h); cudaGetSymbolAddress((void**)&W3l, g_W3l);
    cudaGetSymbolAddress((void**)&Woh, g_Woh); cudaGetSymbolAddress((void**)&Wol, g_Wol);

    // dynamic smem sizes (bytes)
    const int SMEM128  = 2 * 8 * (128 * 24 + 16 * (128 + 8));  // 3-pass, BN=128: 83968
    const int SMEM64   = 2 * 8 * (128 * 24 + 16 * (64 + 8));   // 3-pass, BN=64:  67584
    const int SMEMG    = 2 * 4 * (128 * 24 + 16 * (128 + 8));  // 1-pass, BN=128: 41984

    // lazy-create side streams + events + smem opt-in (outside graph capture)
    static cudaStream_t s2 = nullptr, s3 = nullptr;
    static cudaEvent_t evF = nullptr, evJ = nullptr, evW = nullptr;
    if (s2 == nullptr) {
        cudaStreamCreateWithFlags(&s2, cudaStreamNonBlocking);
        cudaStreamCreateWithFlags(&s3, cudaStreamNonBlocking);
        cudaEventCreateWithFlags(&evF, cudaEventDisableTiming);
        cudaEventCreateWithFlags(&evJ, cudaEventDisableTiming);
        cudaEventCreateWithFlags(&evW, cudaEventDisableTiming);
        cudaFuncSetAttribute(mma_gemm<128, 0, 2, 3>, cudaFuncAttributeMaxDynamicSharedMemorySize, SMEM128);
        cudaFuncSetAttribute(mma_gemm<128, 2, 2, 1>, cudaFuncAttributeMaxDynamicSharedMemorySize, SMEMG);
        cudaFuncSetAttribute(mma_gemm<64, 1, 2, 3>,  cudaFuncAttributeMaxDynamicSharedMemorySize, SMEM64);
    }

    // ---- fork point ----
    cudaEventRecord(evF, 0);
    cudaStreamWaitEvent(s2, evF, 0);
    cudaStreamWaitEvent(s3, evF, 0);

    // ---- s3: weight splits (DRAM-bound; overlap with tensor-bound gram) ----
    split4_kernel<<<(XDIM * HID / 4 + 1023) / 1024, 256, 0, s3>>>(Win, Wih, Wil, XDIM * HID / 4);
    split4_kernel<<<(HID * HID / 4 + 1023) / 1024, 256, 0, s3>>>(W1, W1h, W1l, HID * HID / 4);
    split4_kernel<<<(HID * HID / 4 + 1023) / 1024, 256, 0, s3>>>(W2, W2h, W2l, HID * HID / 4);
    split4_kernel<<<(HID * HID / 4 + 1023) / 1024, 256, 0, s3>>>(W3, W3h, W3l, HID * HID / 4);
    split4_kernel<<<(HID * DR / 4 + 1023) / 1024, 256, 0, s3>>>(Wout, Woh, Wol, HID * DR / 4);
    cudaEventRecord(evW, s3);

    // ---- default: prep needed by the gram chain ----
    sq_kernel<<<NN / 8, 256>>>(cond, sq);
    split4_kernel<<<(NN * DF / 4 + 1023) / 1024, 256>>>(cond, ch, cl, NN * DF / 4);
    tsplit_kernel<<<(DF * NN + 255) / 256, 256>>>(cond, cth, ctl);

    // ---- fork: gram (1-pass fp16) -> topk -> rescore on s2 ----
    cudaEventRecord(evF, 0);
    cudaStreamWaitEvent(s2, evF, 0);
    mma_gemm<128, 2, 2, 1><<<dim3(NN / 128, NN / 128), 256, SMEMG, s2>>>(
        ch, cl, cth, ctl, sq, nullptr, key, nullptr, nullptr, NN, NN, DF);
    topk_kernel<<<NN / 8, 256, 0, s2>>>(key, cand);
    rescore_kernel<<<NN / 8, 256, 0, s2>>>(cond, sq, cand, nidx);
    cudaEventRecord(evJ, s2);

    // ---- default: MLP chain (BN=128, 256 thr, occ 2, 3-pass split fp16) ----
    concat_split_kernel<<<(NN * XDIM + 255) / 256, 256>>>(cond, tens, x0h, x0l);
    cudaStreamWaitEvent(0, evW, 0);

    mma_gemm<128, 0, 2, 3><<<dim3(HID / 128, NN / 128), 256, SMEM128>>>(
        x0h, x0l, Wih, Wil, b_in, nullptr, nullptr, hAh, hAl, NN, HID, XDIM);
    mma_gemm<128, 0, 2, 3><<<dim3(HID / 128, NN / 128), 256, SMEM128>>>(
        hAh, hAl, W1h, W1l, b1, nullptr, nullptr, hBh, hBl, NN, HID, HID);
    mma_gemm<128, 0, 2, 3><<<dim3(HID / 128, NN / 128), 256, SMEM128>>>(
        hBh, hBl, W2h, W2l, b2, nullptr, nullptr, hAh, hAl, NN, HID, HID);
    mma_gemm<128, 0, 2, 3><<<dim3(HID / 128, NN / 128), 256, SMEM128>>>(
        hAh, hAl, W3h, W3l, b3, nullptr, nullptr, hBh, hBl, NN, HID, HID);

    mma_gemm<64, 1, 2, 3><<<dim3(DR / 64, NN / 128), 128, SMEM64>>>(
        hBh, hBl, Woh, Wol, bout, tens, pushed, nullptr, nullptr, NN, DR, HID);

    // ---- join, then gather ----
    cudaStreamWaitEvent(0, evJ, 0);
    gather_kernel<<<(NN * TOPK * 16 + 255) / 256, 256>>>(nidx, pushed, out);
}

// round 13
// speedup vs baseline: 1.1556x; 1.0755x over previous
#include <cuda_runtime.h>
#include <cuda_fp16.h>
#include <cstdint>

#define NN    4096
#define DF    128
#define DR    64
#define HID   1024
#define TOPK  10
#define NCAND 16
#define XDIM  192

typedef __half f16;

// ---------------- static scratch ----------------
__device__ float g_key[(size_t)NN * NN];
__device__ float g_sq [NN];
__device__ int   g_cand[NN * NCAND];
__device__ int   g_nidx[NN * TOPK];
__device__ float g_pushed[NN * DR];

__device__ f16 g_x0h[NN * XDIM], g_x0l[NN * XDIM];
__device__ f16 g_hAh[NN * HID],  g_hAl[NN * HID];
__device__ f16 g_hBh[NN * HID],  g_hBl[NN * HID];
__device__ f16 g_ch [NN * DF],   g_cl [NN * DF];
__device__ f16 g_cth[DF * NN],   g_ctl[DF * NN];
__device__ f16 g_Wih[XDIM * HID], g_Wil[XDIM * HID];
__device__ f16 g_W1h[HID * HID],  g_W1l[HID * HID];
__device__ f16 g_W2h[HID * HID],  g_W2l[HID * HID];
__device__ f16 g_W3h[HID * HID],  g_W3l[HID * HID];
__device__ f16 g_Woh[HID * DR],   g_Wol[HID * DR];

// ---------------- helpers ----------------
__device__ __forceinline__ float sp(float x) {
    return fmaxf(x, 0.0f) + log1pf(expf(-fabsf(x)));
}

__device__ __forceinline__ void cpa16(void* s, const void* g) {
    uint32_t sa = (uint32_t)__cvta_generic_to_shared(s);
    asm volatile("cp.async.cg.shared.global [%0], [%1], 16;" :: "r"(sa), "l"(g) : "memory");
}
#define CP_COMMIT() asm volatile("cp.async.commit_group;" ::: "memory")
#define CP_WAIT1()  asm volatile("cp.async.wait_group 1;" ::: "memory")

__device__ __forceinline__ void ldm_x4(uint32_t* r, const void* p) {
    uint32_t a = (uint32_t)__cvta_generic_to_shared(p);
    asm volatile("ldmatrix.sync.aligned.m8n8.x4.shared.b16 {%0,%1,%2,%3}, [%4];"
        : "=r"(r[0]), "=r"(r[1]), "=r"(r[2]), "=r"(r[3]) : "r"(a));
}
__device__ __forceinline__ void ldm_x2t(uint32_t* r, const void* p) {
    uint32_t a = (uint32_t)__cvta_generic_to_shared(p);
    asm volatile("ldmatrix.sync.aligned.m8n8.x2.trans.shared.b16 {%0,%1}, [%2];"
        : "=r"(r[0]), "=r"(r[1]) : "r"(a));
}
__device__ __forceinline__ void mma16816(float* c, const uint32_t* a, const uint32_t* b) {
    asm volatile("mma.sync.aligned.m16n8k16.row.col.f32.f16.f16.f32 "
        "{%0,%1,%2,%3}, {%4,%5,%6,%7}, {%8,%9}, {%0,%1,%2,%3};"
        : "+f"(c[0]), "+f"(c[1]), "+f"(c[2]), "+f"(c[3])
        : "r"(a[0]), "r"(a[1]), "r"(a[2]), "r"(a[3]), "r"(b[0]), "r"(b[1]));
}

__device__ __forceinline__ void split1(float v, f16& h, f16& l) {
    h = __float2half(v);
    l = __float2half(v - __half2float(h));
}

// ---------------- small prep kernels ----------------
__global__ void sq_kernel(const float* __restrict__ cond, float* __restrict__ sq) {
    const int row  = blockIdx.x * 8 + (threadIdx.x >> 5);
    const int lane = threadIdx.x & 31;
    const float4 t = reinterpret_cast<const float4*>(cond)[row * 32 + lane];
    float s = t.x * t.x + t.y * t.y + t.z * t.z + t.w * t.w;
    #pragma unroll
    for (int o = 16; o > 0; o >>= 1) s += __shfl_down_sync(0xffffffffu, s, o);
    if (lane == 0) sq[row] = s;
}

__global__ void split4_kernel(const float* __restrict__ src, f16* __restrict__ hi,
                              f16* __restrict__ lo, int n4) {
    const int i0 = blockIdx.x * (blockDim.x * 4) + threadIdx.x;
    #pragma unroll
    for (int u = 0; u < 4; u++) {
        const int i = i0 + u * blockDim.x;
        if (i >= n4) return;
        const float4 v = reinterpret_cast<const float4*>(src)[i];
        f16 h0, l0, h1, l1, h2, l2, h3, l3;
        split1(v.x, h0, l0); split1(v.y, h1, l1);
        split1(v.z, h2, l2); split1(v.w, h3, l3);
        __half2 hh[2] = { __halves2half2(h0, h1), __halves2half2(h2, h3) };
        __half2 ll[2] = { __halves2half2(l0, l1), __halves2half2(l2, l3) };
        reinterpret_cast<uint2*>(hi)[i] = *reinterpret_cast<uint2*>(hh);
        reinterpret_cast<uint2*>(lo)[i] = *reinterpret_cast<uint2*>(ll);
    }
}

__global__ void tsplit_kernel(const float* __restrict__ cond, f16* __restrict__ hi,
                              f16* __restrict__ lo) {
    const int i = blockIdx.x * blockDim.x + threadIdx.x;
    if (i >= DF * NN) return;
    const int k = i / NN, n = i % NN;
    f16 h, l; split1(cond[n * DF + k], h, l);
    hi[i] = h; lo[i] = l;
}

__global__ void concat_split_kernel(const float* __restrict__ cond, const float* __restrict__ tens,
                                    f16* __restrict__ hi, f16* __restrict__ lo) {
    const int i = blockIdx.x * blockDim.x + threadIdx.x;
    if (i >= NN * XDIM) return;
    const int r = i / XDIM, c = i % XDIM;
    const float v = (c < DF) ? cond[r * DF + c] : tens[r * DR + (c - DF)];
    f16 h, l; split1(v, h, l);
    hi[i] = h; lo[i] = l;
}

// ---------------- split-fp16 tensor-core GEMM, BK=32 -------
// PASSES==3: C ~= (Ah+Al)@(Bh+Bl) minus lo*lo (split precision, MLP layers).
// PASSES==1: C ~= Ah@Bh (plain fp16; gram keys -- protected by exact rescore).
// BM=128, warp tile 64x32.
// EPI 0: softplus -> split fp16; EPI 1: extra-(acc+bias); EPI 2: gram keys.
template<int BN, int EPI, int OCC, int PASSES>
__global__ void __launch_bounds__((BN / 32) * 64, OCC)
mma_gemm(const f16* __restrict__ Ah, const f16* __restrict__ Al,
         const f16* __restrict__ Bh, const f16* __restrict__ Bl,
         const float* __restrict__ bias, const float* __restrict__ extra,
         float* __restrict__ Cf, f16* __restrict__ Oh, f16* __restrict__ Ol,
         int M, int N, int K)
{
    constexpr int WN = BN / 32;
    constexpr int THREADS = 2 * WN * 32;
    constexpr int AST = 24;       // per-subtile A row stride (48B, conflict-free)
    constexpr int BST = BN + 8;
    constexpr int ASZ = 128 * AST;
    constexpr int BSZ = 16 * BST;
    constexpr int NSLOT = (PASSES == 1) ? 4 : 8;   // buf(2) x sub(2) x split(1|2)

    extern __shared__ __align__(16) f16 dsm[];
    f16* Abase = dsm;
    f16* Bbase = dsm + NSLOT * ASZ;
    auto slot = [&](int buf, int sub, int s) {
        return (PASSES == 1) ? (buf * 2 + sub) : ((buf * 2 + sub) * 2 + s);
    };
    auto Asp = [&](int buf, int sub, int s) { return Abase + slot(buf, sub, s) * ASZ; };
    auto Bsp = [&](int buf, int sub, int s) { return Bbase + slot(buf, sub, s) * BSZ; };

    const int tid  = threadIdx.x;
    const int lane = tid & 31;
    const int w    = tid >> 5;
    const int wm   = w / WN;
    const int wn   = w % WN;
    const int row0 = blockIdx.y * 128;
    const int col0 = blockIdx.x * BN;

    float acc[4][4][4];
    #pragma unroll
    for (int a = 0; a < 4; a++)
        #pragma unroll
        for (int b = 0; b < 4; b++)
            #pragma unroll
            for (int c = 0; c < 4; c++) acc[a][b][c] = 0.0f;

    const int nchunk = K / 32;
    constexpr int NSPLIT = (PASSES == 1) ? 1 : 2;

    auto load_chunk = [&](int ci, int buf) {
        #pragma unroll
        for (int sub = 0; sub < 2; sub++) {
            const int kt = ci * 32 + sub * 16;
            #pragma unroll
            for (int s = 0; s < NSPLIT; s++) {
                const f16* Ag = s ? Al : Ah;
                f16* As = Asp(buf, sub, s);
                for (int f = tid; f < 128 * 2; f += THREADS) {
                    const int m = f >> 1, c = (f & 1) * 8;
                    cpa16(&As[m * AST + c], Ag + (size_t)(row0 + m) * K + kt + c);
                }
                const f16* Bg = s ? Bl : Bh;
                f16* Bs = Bsp(buf, sub, s);
                for (int f = tid; f < 16 * (BN / 8); f += THREADS) {
                    const int k = f / (BN / 8), c = (f % (BN / 8)) * 8;
                    cpa16(&Bs[k * BST + c], Bg + (size_t)(kt + k) * N + col0 + c);
                }
            }
        }
    };

    load_chunk(0, 0);
    CP_COMMIT();

    for (int ci = 0; ci < nchunk; ci++) {
        const int buf = ci & 1;
        if (ci + 1 < nchunk) load_chunk(ci + 1, buf ^ 1);
        CP_COMMIT();
        CP_WAIT1();
        __syncthreads();

        #pragma unroll
        for (int sub = 0; sub < 2; sub++) {
            uint32_t a[4][4], b[4][2];
            const int arow = wm * 64 + (lane & 15);
            const int acol = (lane >> 4) << 3;
            const int brow = (lane & 15) * BST;
            const int bcol = wn * 32;
            const f16* Ash = Asp(buf, sub, 0);
            const f16* Bsh = Bsp(buf, sub, 0);

            if constexpr (PASSES == 1) {
                // single pass: Ah x Bh
                #pragma unroll
                for (int mt = 0; mt < 4; mt++)
                    ldm_x4(a[mt], &Ash[(arow + mt * 16) * AST + acol]);
                #pragma unroll
                for (int nt = 0; nt < 4; nt++)
                    ldm_x2t(b[nt], &Bsh[brow + bcol + nt * 8]);
                #pragma unroll
                for (int mt = 0; mt < 4; mt++)
                    #pragma unroll
                    for (int nt = 0; nt < 4; nt++) mma16816(acc[mt][nt], a[mt], b[nt]);
            } else {
                const f16* Asl = Asp(buf, sub, 1);
                const f16* Bsl = Bsp(buf, sub, 1);

                // pass 1: Ahi x Blo
                #pragma unroll
                for (int mt = 0; mt < 4; mt++)
                    ldm_x4(a[mt], &Ash[(arow + mt * 16) * AST + acol]);
                #pragma unroll
                for (int nt = 0; nt < 4; nt++)
                    ldm_x2t(b[nt], &Bsl[brow + bcol + nt * 8]);
                #pragma unroll
                for (int mt = 0; mt < 4; mt++)
                    #pragma unroll
                    for (int nt = 0; nt < 4; nt++) mma16816(acc[mt][nt], a[mt], b[nt]);

                // pass 2: Ahi x Bhi
                #pragma unroll
                for (int nt = 0; nt < 4; nt++)
                    ldm_x2t(b[nt], &Bsh[brow + bcol + nt * 8]);
                #pragma unroll
                for (int mt = 0; mt < 4; mt++)
                    #pragma unroll
                    for (int nt = 0; nt < 4; nt++) mma16816(acc[mt][nt], a[mt], b[nt]);

                // pass 3: Alo x Bhi
                #pragma unroll
                for (int mt = 0; mt < 4; mt++)
                    ldm_x4(a[mt], &Asl[(arow + mt * 16) * AST + acol]);
                #pragma unroll
                for (int mt = 0; mt < 4; mt++)
                    #pragma unroll
                    for (int nt = 0; nt < 4; nt++) mma16816(acc[mt][nt], a[mt], b[nt]);
            }
        }
        __syncthreads();
    }

    // epilogue
    #pragma unroll
    for (int mt = 0; mt < 4; mt++) {
        #pragma unroll
        for (int nt = 0; nt < 4; nt++) {
            const int r = row0 + wm * 64 + mt * 16 + (lane >> 2);
            const int c = col0 + wn * 32 + nt * 8 + ((lane & 3) << 1);
            const float* ac = acc[mt][nt];
            if constexpr (EPI == 0) {
                const float bc0 = bias[c], bc1 = bias[c + 1];
                #pragma unroll
                for (int h = 0; h < 2; h++) {
                    const int rr = r + 8 * h;
                    const float y0 = sp(ac[2 * h] + bc0);
                    const float y1 = sp(ac[2 * h + 1] + bc1);
                    f16 h0, l0, h1, l1;
                    split1(y0, h0, l0); split1(y1, h1, l1);
                    *(__half2*)(Oh + (size_t)rr * N + c) = __halves2half2(h0, h1);
                    *(__half2*)(Ol + (size_t)rr * N + c) = __halves2half2(l0, l1);
                }
            } else if constexpr (EPI == 1) {
                const float bc0 = bias[c], bc1 = bias[c + 1];
                #pragma unroll
                for (int h = 0; h < 2; h++) {
                    const size_t o = (size_t)(r + 8 * h) * N + c;
                    Cf[o]     = extra[o]     - (ac[2 * h]     + bc0);
                    Cf[o + 1] = extra[o + 1] - (ac[2 * h + 1] + bc1);
                }
            } else {
                const float sc0 = bias[c], sc1 = bias[c + 1];
                #pragma unroll
                for (int h = 0; h < 2; h++) {
                    const float sr = bias[r + 8 * h];
                    const size_t o = (size_t)(r + 8 * h) * NN + c;
                    Cf[o]     = fmaxf(sr + sc0 - 2.0f * ac[2 * h],     0.0f);
                    Cf[o + 1] = fmaxf(sr + sc1 - 2.0f * ac[2 * h + 1], 0.0f);
                }
            }
        }
    }
}

// ---------------- top-NCAND smallest per row (approx keys), register lists ------
template<int L>
__device__ __forceinline__ void insL(float x, int j, float (&v)[L], int (&id)[L]) {
    if (x >= v[L - 1]) return;
    #pragma unroll
    for (int t = L - 1; t > 0; t--) {
        const bool shf = (x < v[t - 1]);
        const bool put = !shf && (x < v[t]);
        v[t]  = shf ? v[t - 1]  : (put ? x : v[t]);
        id[t] = shf ? id[t - 1] : (put ? j : id[t]);
    }
    if (x < v[0]) { v[0] = x; id[0] = j; }
}

__global__ void topk_kernel(const float* __restrict__ key, int* __restrict__ out_cand) {
    const int row  = blockIdx.x * 8 + (threadIdx.x >> 5);
    const int lane = threadIdx.x & 31;
    const float4* k4 = reinterpret_cast<const float4*>(key + (size_t)row * NN);

    float v[NCAND]; int id[NCAND];
    #pragma unroll
    for (int t = 0; t < NCAND; t++) { v[t] = 3.0e38f; id[t] = 0x7fffffff; }

    #pragma unroll 4
    for (int j = lane; j < NN / 4; j += 32) {
        const float4 t = k4[j];
        const int b = 4 * j;
        insL<NCAND>(t.x, b,     v, id);
        insL<NCAND>(t.y, b + 1, v, id);
        insL<NCAND>(t.z, b + 2, v, id);
        insL<NCAND>(t.w, b + 3, v, id);
    }

    #pragma unroll
    for (int k = 0; k < NCAND; k++) {
        float mv = v[0]; int mi = id[0];
        #pragma unroll
        for (int off = 16; off > 0; off >>= 1) {
            const float ov = __shfl_down_sync(0xffffffffu, mv, off);
            const int   oi = __shfl_down_sync(0xffffffffu, mi, off);
            if (ov < mv || (ov == mv && oi < mi)) { mv = ov; mi = oi; }
        }
        mv = __shfl_sync(0xffffffffu, mv, 0);
        mi = __shfl_sync(0xffffffffu, mi, 0);
        if (id[0] == mi) {
            #pragma unroll
            for (int t = 0; t < NCAND - 1; t++) { v[t] = v[t + 1]; id[t] = id[t + 1]; }
            v[NCAND - 1] = 3.0e38f; id[NCAND - 1] = 0x7fffffff;
        }
        if (lane == 0) out_cand[row * NCAND + k] = mi;
    }
}

// ---------------- exact fp32 rescore of the 16 candidates -> final top-10 --------
__global__ void rescore_kernel(const float* __restrict__ cond, const float* __restrict__ sq,
                               const int* __restrict__ cand, int* __restrict__ out_idx) {
    const int row  = blockIdx.x * 8 + (threadIdx.x >> 5);
    const int lane = threadIdx.x & 31;
    const float4 cr = reinterpret_cast<const float4*>(cond)[row * 32 + lane];
    const float sr = sq[row];

    float mv = 3.0e38f; int mid = 0x7fffffff;
    #pragma unroll
    for (int c = 0; c < NCAND; c++) {
        const int j = cand[row * NCAND + c];
        const float4 cc = reinterpret_cast<const float4*>(cond)[j * 32 + lane];
        float d = cr.x * cc.x + cr.y * cc.y + cr.z * cc.z + cr.w * cc.w;
        #pragma unroll
        for (int o = 16; o > 0; o >>= 1) d += __shfl_down_sync(0xffffffffu, d, o);
        d = __shfl_sync(0xffffffffu, d, 0);
        const float k = fmaxf(sr + sq[j] - 2.0f * d, 0.0f);
        if (lane == c) { mv = k; mid = j; }
    }

    #pragma unroll
    for (int k = 0; k < TOPK; k++) {
        float bv = mv; int bi = mid;
        #pragma unroll
        for (int off = 16; off > 0; off >>= 1) {
            const float ov = __shfl_down_sync(0xffffffffu, bv, off);
            const int   oi = __shfl_down_sync(0xffffffffu, bi, off);
            if (ov < bv || (ov == bv && oi < bi)) { bv = ov; bi = oi; }
        }
        bv = __shfl_sync(0xffffffffu, bv, 0);
        bi = __shfl_sync(0xffffffffu, bi, 0);
        if (mid == bi) { mv = 3.0e38f; mid = 0x7fffffff; }
        if (lane == 0) out_idx[row * TOPK + k] = bi;
    }
}

// ---------------- final gather ----------------
__global__ void gather_kernel(const int* __restrict__ nidx, const float* __restrict__ pushed,
                              float* __restrict__ out) {
    const int t = blockIdx.x * blockDim.x + threadIdx.x;
    if (t >= NN * TOPK * 16) return;
    const int r = t >> 4, c = t & 15;
    const int j = nidx[r];
    reinterpret_cast<float4*>(out)[t] = reinterpret_cast<const float4*>(pushed)[j * 16 + c];
}

// ---------------- launch ----------------
extern "C" void kernel_launch(void* const* d_in, const int* in_sizes, int n_in,
                              void* d_out, int out_size)
{
    const float* cond = (const float*)d_in[0];
    const float* tens = (const float*)d_in[1];
    const float* Win  = (const float*)d_in[2];
    const float* b_in = (const float*)d_in[3];
    const float* W1   = (const float*)d_in[4];
    const float* b1   = (const float*)d_in[5];
    const float* W2   = (const float*)d_in[6];
    const float* b2   = (const float*)d_in[7];
    const float* W3   = (const float*)d_in[8];
    const float* b3   = (const float*)d_in[9];
    const float* Wout = (const float*)d_in[10];
    const float* bout = (const float*)d_in[11];
    float* out = (float*)d_out;

    float *key, *sq, *pushed; int *cand, *nidx;
    f16 *x0h, *x0l, *hAh, *hAl, *hBh, *hBl, *ch, *cl, *cth, *ctl;
    f16 *Wih, *Wil, *W1h, *W1l, *W2h, *W2l, *W3h, *W3l, *Woh, *Wol;
    cudaGetSymbolAddress((void**)&key, g_key);
    cudaGetSymbolAddress((void**)&sq, g_sq);
    cudaGetSymbolAddress((void**)&cand, g_cand);
    cudaGetSymbolAddress((void**)&nidx, g_nidx);
    cudaGetSymbolAddress((void**)&pushed, g_pushed);
    cudaGetSymbolAddress((void**)&x0h, g_x0h); cudaGetSymbolAddress((void**)&x0l, g_x0l);
    cudaGetSymbolAddress((void**)&hAh, g_hAh); cudaGetSymbolAddress((void**)&hAl, g_hAl);
    cudaGetSymbolAddress((void**)&hBh, g_hBh); cudaGetSymbolAddress((void**)&hBl, g_hBl);
    cudaGetSymbolAddress((void**)&ch,  g_ch);  cudaGetSymbolAddress((void**)&cl,  g_cl);
    cudaGetSymbolAddress((void**)&cth, g_cth); cudaGetSymbolAddress((void**)&ctl, g_ctl);
    cudaGetSymbolAddress((void**)&Wih, g_Wih); cudaGetSymbolAddress((void**)&Wil, g_Wil);
    cudaGetSymbolAddress((void**)&W1h, g_W1h); cudaGetSymbolAddress((void**)&W1l, g_W1l);
    cudaGetSymbolAddress((void**)&W2h, g_W2h); cudaGetSymbolAddress((void**)&W2l, g_W2l);
    cudaGetSymbolAddress((void**)&W3h, g_W3h); cudaGetSymbolAddress((void**)&W3l, g_W3l);
    cudaGetSymbolAddress((void**)&Woh, g_Woh); cudaGetSymbolAddress((void**)&Wol, g_Wol);

    // dynamic smem sizes (bytes)
    const int SMEM128  = 2 * 8 * (128 * 24 + 16 * (128 + 8));  // 3-pass, BN=128: 83968
    const int SMEM64   = 2 * 8 * (128 * 24 + 16 * (64 + 8));   // 3-pass, BN=64:  67584
    const int SMEMG    = 2 * 4 * (128 * 24 + 16 * (128 + 8));  // 1-pass, BN=128: 41984

    // lazy-create side streams + events + smem opt-in (outside graph capture)
    static cudaStream_t s2 = nullptr, s3 = nullptr;
    static cudaEvent_t evF = nullptr, evJ = nullptr;
    static cudaEvent_t ev1 = nullptr, ev2 = nullptr, ev3 = nullptr, ev4 = nullptr;
    if (s2 == nullptr) {
        cudaStreamCreateWithFlags(&s2, cudaStreamNonBlocking);
        cudaStreamCreateWithFlags(&s3, cudaStreamNonBlocking);
        cudaEventCreateWithFlags(&evF, cudaEventDisableTiming);
        cudaEventCreateWithFlags(&evJ, cudaEventDisableTiming);
        cudaEventCreateWithFlags(&ev1, cudaEventDisableTiming);
        cudaEventCreateWithFlags(&ev2, cudaEventDisableTiming);
        cudaEventCreateWithFlags(&ev3, cudaEventDisableTiming);
        cudaEventCreateWithFlags(&ev4, cudaEventDisableTiming);
        cudaFuncSetAttribute(mma_gemm<128, 0, 2, 3>, cudaFuncAttributeMaxDynamicSharedMemorySize, SMEM128);
        cudaFuncSetAttribute(mma_gemm<128, 2, 2, 1>, cudaFuncAttributeMaxDynamicSharedMemorySize, SMEMG);
        cudaFuncSetAttribute(mma_gemm<64, 1, 2, 3>,  cudaFuncAttributeMaxDynamicSharedMemorySize, SMEM64);
    }

    // ---- fork point (both side streams branch off the capture stream) ----
    cudaEventRecord(evF, 0);
    cudaStreamWaitEvent(s2, evF, 0);
    cudaStreamWaitEvent(s3, evF, 0);

    // ---- s2: FULL gram chain (prep + gram + topk + rescore), joins at gather ----
    sq_kernel<<<NN / 8, 256, 0, s2>>>(cond, sq);
    split4_kernel<<<(NN * DF / 4 + 1023) / 1024, 256, 0, s2>>>(cond, ch, cl, NN * DF / 4);
    tsplit_kernel<<<(DF * NN + 255) / 256, 256, 0, s2>>>(cond, cth, ctl);
    mma_gemm<128, 2, 2, 1><<<dim3(NN / 128, NN / 128), 256, SMEMG, s2>>>(
        ch, cl, cth, ctl, sq, nullptr, key, nullptr, nullptr, NN, NN, DF);
    topk_kernel<<<NN / 8, 256, 0, s2>>>(key, cand);
    rescore_kernel<<<NN / 8, 256, 0, s2>>>(cond, sq, cand, nidx);
    cudaEventRecord(evJ, s2);

    // ---- s3: deferred weight splits, per-weight events (pipelined with layers) ----
    split4_kernel<<<(HID * HID / 4 + 1023) / 1024, 256, 0, s3>>>(W1, W1h, W1l, HID * HID / 4);
    cudaEventRecord(ev1, s3);
    split4_kernel<<<(HID * HID / 4 + 1023) / 1024, 256, 0, s3>>>(W2, W2h, W2l, HID * HID / 4);
    cudaEventRecord(ev2, s3);
    split4_kernel<<<(HID * HID / 4 + 1023) / 1024, 256, 0, s3>>>(W3, W3h, W3l, HID * HID / 4);
    cudaEventRecord(ev3, s3);
    split4_kernel<<<(HID * DR / 4 + 1023) / 1024, 256, 0, s3>>>(Wout, Woh, Wol, HID * DR / 4);
    cudaEventRecord(ev4, s3);

    // ---- default: minimal prep for layer 1, then the MLP chain ----
    concat_split_kernel<<<(NN * XDIM + 255) / 256, 256>>>(cond, tens, x0h, x0l);
    split4_kernel<<<(XDIM * HID / 4 + 1023) / 1024, 256>>>(Win, Wih, Wil, XDIM * HID / 4);

    mma_gemm<128, 0, 2, 3><<<dim3(HID / 128, NN / 128), 256, SMEM128>>>(
        x0h, x0l, Wih, Wil, b_in, nullptr, nullptr, hAh, hAl, NN, HID, XDIM);
    cudaStreamWaitEvent(0, ev1, 0);
    mma_gemm<128, 0, 2, 3><<<dim3(HID / 128, NN / 128), 256, SMEM128>>>(
        hAh, hAl, W1h, W1l, b1, nullptr, nullptr, hBh, hBl, NN, HID, HID);
    cudaStreamWaitEvent(0, ev2, 0);
    mma_gemm<128, 0, 2, 3><<<dim3(HID / 128, NN / 128), 256, SMEM128>>>(
        hBh, hBl, W2h, W2l, b2, nullptr, nullptr, hAh, hAl, NN, HID, HID);
    cudaStreamWaitEvent(0, ev3, 0);
    mma_gemm<128, 0, 2, 3><<<dim3(HID / 128, NN / 128), 256, SMEM128>>>(
        hAh, hAl, W3h, W3l, b3, nullptr, nullptr, hBh, hBl, NN, HID, HID);
    cudaStreamWaitEvent(0, ev4, 0);
    mma_gemm<64, 1, 2, 3><<<dim3(DR / 64, NN / 128), 128, SMEM64>>>(
        hBh, hBl, Woh, Wol, bout, tens, pushed, nullptr, nullptr, NN, DR, HID);

    // ---- join, then gather ----
    cudaStreamWaitEvent(0, evJ, 0);
    gather_kernel<<<(NN * TOPK * 16 + 255) / 256, 256>>>(nidx, pushed, out);
}

// round 14
// speedup vs baseline: 1.1765x; 1.0181x over previous
#include <cuda_runtime.h>
#include <cuda_fp16.h>
#include <cstdint>

#define NN    4096
#define DF    128
#define DR    64
#define HID   1024
#define TOPK  10
#define NCAND 16
#define XDIM  192

typedef __half f16;

// ---------------- static scratch ----------------
__device__ f16   g_key[(size_t)NN * NN];    // fp16 keys (32 MB -> L2-resident)
__device__ float g_sq [NN];
__device__ int   g_cand[NN * NCAND];
__device__ int   g_nidx[NN * TOPK];
__device__ float g_pushed[NN * DR];

__device__ f16 g_x0h[NN * XDIM], g_x0l[NN * XDIM];
__device__ f16 g_hAh[NN * HID],  g_hAl[NN * HID];
__device__ f16 g_hBh[NN * HID],  g_hBl[NN * HID];
__device__ f16 g_ch [NN * DF],   g_cl [NN * DF];
__device__ f16 g_cth[DF * NN],   g_ctl[DF * NN];
__device__ f16 g_Wih[XDIM * HID], g_Wil[XDIM * HID];
__device__ f16 g_W1h[HID * HID],  g_W1l[HID * HID];
__device__ f16 g_W2h[HID * HID],  g_W2l[HID * HID];
__device__ f16 g_W3h[HID * HID],  g_W3l[HID * HID];
__device__ f16 g_Woh[HID * DR],   g_Wol[HID * DR];

// ---------------- helpers ----------------
__device__ __forceinline__ float sp(float x) {
    return fmaxf(x, 0.0f) + log1pf(expf(-fabsf(x)));
}

__device__ __forceinline__ void cpa16(void* s, const void* g) {
    uint32_t sa = (uint32_t)__cvta_generic_to_shared(s);
    asm volatile("cp.async.cg.shared.global [%0], [%1], 16;" :: "r"(sa), "l"(g) : "memory");
}
#define CP_COMMIT() asm volatile("cp.async.commit_group;" ::: "memory")
#define CP_WAIT1()  asm volatile("cp.async.wait_group 1;" ::: "memory")

__device__ __forceinline__ void ldm_x4(uint32_t* r, const void* p) {
    uint32_t a = (uint32_t)__cvta_generic_to_shared(p);
    asm volatile("ldmatrix.sync.aligned.m8n8.x4.shared.b16 {%0,%1,%2,%3}, [%4];"
        : "=r"(r[0]), "=r"(r[1]), "=r"(r[2]), "=r"(r[3]) : "r"(a));
}
__device__ __forceinline__ void ldm_x2t(uint32_t* r, const void* p) {
    uint32_t a = (uint32_t)__cvta_generic_to_shared(p);
    asm volatile("ldmatrix.sync.aligned.m8n8.x2.trans.shared.b16 {%0,%1}, [%2];"
        : "=r"(r[0]), "=r"(r[1]) : "r"(a));
}
__device__ __forceinline__ void mma16816(float* c, const uint32_t* a, const uint32_t* b) {
    asm volatile("mma.sync.aligned.m16n8k16.row.col.f32.f16.f16.f32 "
        "{%0,%1,%2,%3}, {%4,%5,%6,%7}, {%8,%9}, {%0,%1,%2,%3};"
        : "+f"(c[0]), "+f"(c[1]), "+f"(c[2]), "+f"(c[3])
        : "r"(a[0]), "r"(a[1]), "r"(a[2]), "r"(a[3]), "r"(b[0]), "r"(b[1]));
}

__device__ __forceinline__ void split1(float v, f16& h, f16& l) {
    h = __float2half(v);
    l = __float2half(v - __half2float(h));
}

// ---------------- small prep kernels ----------------
__global__ void sq_kernel(const float* __restrict__ cond, float* __restrict__ sq) {
    const int row  = blockIdx.x * 8 + (threadIdx.x >> 5);
    const int lane = threadIdx.x & 31;
    const float4 t = reinterpret_cast<const float4*>(cond)[row * 32 + lane];
    float s = t.x * t.x + t.y * t.y + t.z * t.z + t.w * t.w;
    #pragma unroll
    for (int o = 16; o > 0; o >>= 1) s += __shfl_down_sync(0xffffffffu, s, o);
    if (lane == 0) sq[row] = s;
}

__global__ void split4_kernel(const float* __restrict__ src, f16* __restrict__ hi,
                              f16* __restrict__ lo, int n4) {
    const int i0 = blockIdx.x * (blockDim.x * 4) + threadIdx.x;
    #pragma unroll
    for (int u = 0; u < 4; u++) {
        const int i = i0 + u * blockDim.x;
        if (i >= n4) return;
        const float4 v = reinterpret_cast<const float4*>(src)[i];
        f16 h0, l0, h1, l1, h2, l2, h3, l3;
        split1(v.x, h0, l0); split1(v.y, h1, l1);
        split1(v.z, h2, l2); split1(v.w, h3, l3);
        __half2 hh[2] = { __halves2half2(h0, h1), __halves2half2(h2, h3) };
        __half2 ll[2] = { __halves2half2(l0, l1), __halves2half2(l2, l3) };
        reinterpret_cast<uint2*>(hi)[i] = *reinterpret_cast<uint2*>(hh);
        reinterpret_cast<uint2*>(lo)[i] = *reinterpret_cast<uint2*>(ll);
    }
}

__global__ void tsplit_kernel(const float* __restrict__ cond, f16* __restrict__ hi,
                              f16* __restrict__ lo) {
    const int i = blockIdx.x * blockDim.x + threadIdx.x;
    if (i >= DF * NN) return;
    const int k = i / NN, n = i % NN;
    f16 h, l; split1(cond[n * DF + k], h, l);
    hi[i] = h; lo[i] = l;
}

__global__ void concat_split_kernel(const float* __restrict__ cond, const float* __restrict__ tens,
                                    f16* __restrict__ hi, f16* __restrict__ lo) {
    const int i = blockIdx.x * blockDim.x + threadIdx.x;
    if (i >= NN * XDIM) return;
    const int r = i / XDIM, c = i % XDIM;
    const float v = (c < DF) ? cond[r * DF + c] : tens[r * DR + (c - DF)];
    f16 h, l; split1(v, h, l);
    hi[i] = h; lo[i] = l;
}

// ---------------- split-fp16 tensor-core GEMM, BK=32 -------
// PASSES==3: C ~= (Ah+Al)@(Bh+Bl) minus lo*lo (split precision, MLP layers).
// PASSES==1: C ~= Ah@Bh (plain fp16; gram keys -- protected by exact rescore).
// BM=128, warp tile 64x32.
// EPI 0: softplus -> split fp16; EPI 1: extra-(acc+bias); EPI 2: fp16 gram keys -> Oh.
template<int BN, int EPI, int OCC, int PASSES>
__global__ void __launch_bounds__((BN / 32) * 64, OCC)
mma_gemm(const f16* __restrict__ Ah, const f16* __restrict__ Al,
         const f16* __restrict__ Bh, const f16* __restrict__ Bl,
         const float* __restrict__ bias, const float* __restrict__ extra,
         float* __restrict__ Cf, f16* __restrict__ Oh, f16* __restrict__ Ol,
         int M, int N, int K)
{
    constexpr int WN = BN / 32;
    constexpr int THREADS = 2 * WN * 32;
    constexpr int AST = 24;       // per-subtile A row stride (48B, conflict-free)
    constexpr int BST = BN + 8;
    constexpr int ASZ = 128 * AST;
    constexpr int BSZ = 16 * BST;
    constexpr int NSLOT = (PASSES == 1) ? 4 : 8;   // buf(2) x sub(2) x split(1|2)

    extern __shared__ __align__(16) f16 dsm[];
    f16* Abase = dsm;
    f16* Bbase = dsm + NSLOT * ASZ;
    auto slot = [&](int buf, int sub, int s) {
        return (PASSES == 1) ? (buf * 2 + sub) : ((buf * 2 + sub) * 2 + s);
    };
    auto Asp = [&](int buf, int sub, int s) { return Abase + slot(buf, sub, s) * ASZ; };
    auto Bsp = [&](int buf, int sub, int s) { return Bbase + slot(buf, sub, s) * BSZ; };

    const int tid  = threadIdx.x;
    const int lane = tid & 31;
    const int w    = tid >> 5;
    const int wm   = w / WN;
    const int wn   = w % WN;
    const int row0 = blockIdx.y * 128;
    const int col0 = blockIdx.x * BN;

    float acc[4][4][4];
    #pragma unroll
    for (int a = 0; a < 4; a++)
        #pragma unroll
        for (int b = 0; b < 4; b++)
            #pragma unroll
            for (int c = 0; c < 4; c++) acc[a][b][c] = 0.0f;

    const int nchunk = K / 32;
    constexpr int NSPLIT = (PASSES == 1) ? 1 : 2;

    auto load_chunk = [&](int ci, int buf) {
        #pragma unroll
        for (int sub = 0; sub < 2; sub++) {
            const int kt = ci * 32 + sub * 16;
            #pragma unroll
            for (int s = 0; s < NSPLIT; s++) {
                const f16* Ag = s ? Al : Ah;
                f16* As = Asp(buf, sub, s);
                for (int f = tid; f < 128 * 2; f += THREADS) {
                    const int m = f >> 1, c = (f & 1) * 8;
                    cpa16(&As[m * AST + c], Ag + (size_t)(row0 + m) * K + kt + c);
                }
                const f16* Bg = s ? Bl : Bh;
                f16* Bs = Bsp(buf, sub, s);
                for (int f = tid; f < 16 * (BN / 8); f += THREADS) {
                    const int k = f / (BN / 8), c = (f % (BN / 8)) * 8;
                    cpa16(&Bs[k * BST + c], Bg + (size_t)(kt + k) * N + col0 + c);
                }
            }
        }
    };

    load_chunk(0, 0);
    CP_COMMIT();

    for (int ci = 0; ci < nchunk; ci++) {
        const int buf = ci & 1;
        if (ci + 1 < nchunk) load_chunk(ci + 1, buf ^ 1);
        CP_COMMIT();
        CP_WAIT1();
        __syncthreads();

        #pragma unroll
        for (int sub = 0; sub < 2; sub++) {
            uint32_t a[4][4], b[4][2];
            const int arow = wm * 64 + (lane & 15);
            const int acol = (lane >> 4) << 3;
            const int brow = (lane & 15) * BST;
            const int bcol = wn * 32;
            const f16* Ash = Asp(buf, sub, 0);
            const f16* Bsh = Bsp(buf, sub, 0);

            if constexpr (PASSES == 1) {
                // single pass: Ah x Bh
                #pragma unroll
                for (int mt = 0; mt < 4; mt++)
                    ldm_x4(a[mt], &Ash[(arow + mt * 16) * AST + acol]);
                #pragma unroll
                for (int nt = 0; nt < 4; nt++)
                    ldm_x2t(b[nt], &Bsh[brow + bcol + nt * 8]);
                #pragma unroll
                for (int mt = 0; mt < 4; mt++)
                    #pragma unroll
                    for (int nt = 0; nt < 4; nt++) mma16816(acc[mt][nt], a[mt], b[nt]);
            } else {
                const f16* Asl = Asp(buf, sub, 1);
                const f16* Bsl = Bsp(buf, sub, 1);

                // pass 1: Ahi x Blo
                #pragma unroll
                for (int mt = 0; mt < 4; mt++)
                    ldm_x4(a[mt], &Ash[(arow + mt * 16) * AST + acol]);
                #pragma unroll
                for (int nt = 0; nt < 4; nt++)
                    ldm_x2t(b[nt], &Bsl[brow + bcol + nt * 8]);
                #pragma unroll
                for (int mt = 0; mt < 4; mt++)
                    #pragma unroll
                    for (int nt = 0; nt < 4; nt++) mma16816(acc[mt][nt], a[mt], b[nt]);

                // pass 2: Ahi x Bhi
                #pragma unroll
                for (int nt = 0; nt < 4; nt++)
                    ldm_x2t(b[nt], &Bsh[brow + bcol + nt * 8]);
                #pragma unroll
                for (int mt = 0; mt < 4; mt++)
                    #pragma unroll
                    for (int nt = 0; nt < 4; nt++) mma16816(acc[mt][nt], a[mt], b[nt]);

                // pass 3: Alo x Bhi
                #pragma unroll
                for (int mt = 0; mt < 4; mt++)
                    ldm_x4(a[mt], &Asl[(arow + mt * 16) * AST + acol]);
                #pragma unroll
                for (int mt = 0; mt < 4; mt++)
                    #pragma unroll
                    for (int nt = 0; nt < 4; nt++) mma16816(acc[mt][nt], a[mt], b[nt]);
            }
        }
        __syncthreads();
    }

    // epilogue
    #pragma unroll
    for (int mt = 0; mt < 4; mt++) {
        #pragma unroll
        for (int nt = 0; nt < 4; nt++) {
            const int r = row0 + wm * 64 + mt * 16 + (lane >> 2);
            const int c = col0 + wn * 32 + nt * 8 + ((lane & 3) << 1);
            const float* ac = acc[mt][nt];
            if constexpr (EPI == 0) {
                const float bc0 = bias[c], bc1 = bias[c + 1];
                #pragma unroll
                for (int h = 0; h < 2; h++) {
                    const int rr = r + 8 * h;
                    const float y0 = sp(ac[2 * h] + bc0);
                    const float y1 = sp(ac[2 * h + 1] + bc1);
                    f16 h0, l0, h1, l1;
                    split1(y0, h0, l0); split1(y1, h1, l1);
                    *(__half2*)(Oh + (size_t)rr * N + c) = __halves2half2(h0, h1);
                    *(__half2*)(Ol + (size_t)rr * N + c) = __halves2half2(l0, l1);
                }
            } else if constexpr (EPI == 1) {
                const float bc0 = bias[c], bc1 = bias[c + 1];
                #pragma unroll
                for (int h = 0; h < 2; h++) {
                    const size_t o = (size_t)(r + 8 * h) * N + c;
                    Cf[o]     = extra[o]     - (ac[2 * h]     + bc0);
                    Cf[o + 1] = extra[o + 1] - (ac[2 * h + 1] + bc1);
                }
            } else {
                const float sc0 = bias[c], sc1 = bias[c + 1];
                #pragma unroll
                for (int h = 0; h < 2; h++) {
                    const float sr = bias[r + 8 * h];
                    const size_t o = (size_t)(r + 8 * h) * NN + c;
                    const float k0 = fmaxf(sr + sc0 - 2.0f * ac[2 * h],     0.0f);
                    const float k1 = fmaxf(sr + sc1 - 2.0f * ac[2 * h + 1], 0.0f);
                    *(__half2*)(Oh + o) = __halves2half2(__float2half(k0), __float2half(k1));
                }
            }
        }
    }
}

// ---------------- top-NCAND smallest per row (fp16 approx keys) ----------------
template<int L>
__device__ __forceinline__ void insL(float x, int j, float (&v)[L], int (&id)[L]) {
    if (x >= v[L - 1]) return;
    #pragma unroll
    for (int t = L - 1; t > 0; t--) {
        const bool shf = (x < v[t - 1]);
        const bool put = !shf && (x < v[t]);
        v[t]  = shf ? v[t - 1]  : (put ? x : v[t]);
        id[t] = shf ? id[t - 1] : (put ? j : id[t]);
    }
    if (x < v[0]) { v[0] = x; id[0] = j; }
}

__global__ void topk_kernel(const f16* __restrict__ key, int* __restrict__ out_cand) {
    const int row  = blockIdx.x * 8 + (threadIdx.x >> 5);
    const int lane = threadIdx.x & 31;
    const uint4* k8 = reinterpret_cast<const uint4*>(key + (size_t)row * NN);  // 8 halves

    float v[NCAND]; int id[NCAND];
    #pragma unroll
    for (int t = 0; t < NCAND; t++) { v[t] = 3.0e38f; id[t] = 0x7fffffff; }

    #pragma unroll 4
    for (int j = lane; j < NN / 8; j += 32) {
        const uint4 t = k8[j];
        const int b = 8 * j;
        const __half2 p0 = *reinterpret_cast<const __half2*>(&t.x);
        const __half2 p1 = *reinterpret_cast<const __half2*>(&t.y);
        const __half2 p2 = *reinterpret_cast<const __half2*>(&t.z);
        const __half2 p3 = *reinterpret_cast<const __half2*>(&t.w);
        insL<NCAND>(__low2float(p0),  b,     v, id);
        insL<NCAND>(__high2float(p0), b + 1, v, id);
        insL<NCAND>(__low2float(p1),  b + 2, v, id);
        insL<NCAND>(__high2float(p1), b + 3, v, id);
        insL<NCAND>(__low2float(p2),  b + 4, v, id);
        insL<NCAND>(__high2float(p2), b + 5, v, id);
        insL<NCAND>(__low2float(p3),  b + 6, v, id);
        insL<NCAND>(__high2float(p3), b + 7, v, id);
    }

    #pragma unroll
    for (int k = 0; k < NCAND; k++) {
        float mv = v[0]; int mi = id[0];
        #pragma unroll
        for (int off = 16; off > 0; off >>= 1) {
            const float ov = __shfl_down_sync(0xffffffffu, mv, off);
            const int   oi = __shfl_down_sync(0xffffffffu, mi, off);
            if (ov < mv || (ov == mv && oi < mi)) { mv = ov; mi = oi; }
        }
        mv = __shfl_sync(0xffffffffu, mv, 0);
        mi = __shfl_sync(0xffffffffu, mi, 0);
        if (id[0] == mi) {
            #pragma unroll
            for (int t = 0; t < NCAND - 1; t++) { v[t] = v[t + 1]; id[t] = id[t + 1]; }
            v[NCAND - 1] = 3.0e38f; id[NCAND - 1] = 0x7fffffff;
        }
        if (lane == 0) out_cand[row * NCAND + k] = mi;
    }
}

// ---------------- exact fp32 rescore of the 16 candidates -> final top-10 --------
__global__ void rescore_kernel(const float* __restrict__ cond, const float* __restrict__ sq,
                               const int* __restrict__ cand, int* __restrict__ out_idx) {
    const int row  = blockIdx.x * 8 + (threadIdx.x >> 5);
    const int lane = threadIdx.x & 31;
    const float4 cr = reinterpret_cast<const float4*>(cond)[row * 32 + lane];
    const float sr = sq[row];

    float mv = 3.0e38f; int mid = 0x7fffffff;
    #pragma unroll
    for (int c = 0; c < NCAND; c++) {
        const int j = cand[row * NCAND + c];
        const float4 cc = reinterpret_cast<const float4*>(cond)[j * 32 + lane];
        float d = cr.x * cc.x + cr.y * cc.y + cr.z * cc.z + cr.w * cc.w;
        #pragma unroll
        for (int o = 16; o > 0; o >>= 1) d += __shfl_down_sync(0xffffffffu, d, o);
        d = __shfl_sync(0xffffffffu, d, 0);
        const float k = fmaxf(sr + sq[j] - 2.0f * d, 0.0f);
        if (lane == c) { mv = k; mid = j; }
    }

    #pragma unroll
    for (int k = 0; k < TOPK; k++) {
        float bv = mv; int bi = mid;
        #pragma unroll
        for (int off = 16; off > 0; off >>= 1) {
            const float ov = __shfl_down_sync(0xffffffffu, bv, off);
            const int   oi = __shfl_down_sync(0xffffffffu, bi, off);
            if (ov < bv || (ov == bv && oi < bi)) { bv = ov; bi = oi; }
        }
        bv = __shfl_sync(0xffffffffu, bv, 0);
        bi = __shfl_sync(0xffffffffu, bi, 0);
        if (mid == bi) { mv = 3.0e38f; mid = 0x7fffffff; }
        if (lane == 0) out_idx[row * TOPK + k] = bi;
    }
}

// ---------------- final gather ----------------
__global__ void gather_kernel(const int* __restrict__ nidx, const float* __restrict__ pushed,
                              float* __restrict__ out) {
    const int t = blockIdx.x * blockDim.x + threadIdx.x;
    if (t >= NN * TOPK * 16) return;
    const int r = t >> 4, c = t & 15;
    const int j = nidx[r];
    reinterpret_cast<float4*>(out)[t] = reinterpret_cast<const float4*>(pushed)[j * 16 + c];
}

// ---------------- launch ----------------
extern "C" void kernel_launch(void* const* d_in, const int* in_sizes, int n_in,
                              void* d_out, int out_size)
{
    const float* cond = (const float*)d_in[0];
    const float* tens = (const float*)d_in[1];
    const float* Win  = (const float*)d_in[2];
    const float* b_in = (const float*)d_in[3];
    const float* W1   = (const float*)d_in[4];
    const float* b1   = (const float*)d_in[5];
    const float* W2   = (const float*)d_in[6];
    const float* b2   = (const float*)d_in[7];
    const float* W3   = (const float*)d_in[8];
    const float* b3   = (const float*)d_in[9];
    const float* Wout = (const float*)d_in[10];
    const float* bout = (const float*)d_in[11];
    float* out = (float*)d_out;

    float *sq, *pushed; int *cand, *nidx;
    f16 *key;
    f16 *x0h, *x0l, *hAh, *hAl, *hBh, *hBl, *ch, *cl, *cth, *ctl;
    f16 *Wih, *Wil, *W1h, *W1l, *W2h, *W2l, *W3h, *W3l, *Woh, *Wol;
    cudaGetSymbolAddress((void**)&key, g_key);
    cudaGetSymbolAddress((void**)&sq, g_sq);
    cudaGetSymbolAddress((void**)&cand, g_cand);
    cudaGetSymbolAddress((void**)&nidx, g_nidx);
    cudaGetSymbolAddress((void**)&pushed, g_pushed);
    cudaGetSymbolAddress((void**)&x0h, g_x0h); cudaGetSymbolAddress((void**)&x0l, g_x0l);
    cudaGetSymbolAddress((void**)&hAh, g_hAh); cudaGetSymbolAddress((void**)&hAl, g_hAl);
    cudaGetSymbolAddress((void**)&hBh, g_hBh); cudaGetSymbolAddress((void**)&hBl, g_hBl);
    cudaGetSymbolAddress((void**)&ch,  g_ch);  cudaGetSymbolAddress((void**)&cl,  g_cl);
    cudaGetSymbolAddress((void**)&cth, g_cth); cudaGetSymbolAddress((void**)&ctl, g_ctl);
    cudaGetSymbolAddress((void**)&Wih, g_Wih); cudaGetSymbolAddress((void**)&Wil, g_Wil);
    cudaGetSymbolAddress((void**)&W1h, g_W1h); cudaGetSymbolAddress((void**)&W1l, g_W1l);
    cudaGetSymbolAddress((void**)&W2h, g_W2h); cudaGetSymbolAddress((void**)&W2l, g_W2l);
    cudaGetSymbolAddress((void**)&W3h, g_W3h); cudaGetSymbolAddress((void**)&W3l, g_W3l);
    cudaGetSymbolAddress((void**)&Woh, g_Woh); cudaGetSymbolAddress((void**)&Wol, g_Wol);

    // dynamic smem sizes (bytes)
    const int SMEM128  = 2 * 8 * (128 * 24 + 16 * (128 + 8));  // 3-pass, BN=128: 83968
    const int SMEM64   = 2 * 8 * (128 * 24 + 16 * (64 + 8));   // 3-pass, BN=64:  67584
    const int SMEMG    = 2 * 4 * (128 * 24 + 16 * (128 + 8));  // 1-pass, BN=128: 41984

    // lazy-create side streams + events + smem opt-in (outside graph capture)
    static cudaStream_t s2 = nullptr, s3 = nullptr;
    static cudaEvent_t evF = nullptr, evJ = nullptr;
    static cudaEvent_t ev1 = nullptr, ev2 = nullptr, ev3 = nullptr, ev4 = nullptr;
    if (s2 == nullptr) {
        cudaStreamCreateWithFlags(&s2, cudaStreamNonBlocking);
        cudaStreamCreateWithFlags(&s3, cudaStreamNonBlocking);
        cudaEventCreateWithFlags(&evF, cudaEventDisableTiming);
        cudaEventCreateWithFlags(&evJ, cudaEventDisableTiming);
        cudaEventCreateWithFlags(&ev1, cudaEventDisableTiming);
        cudaEventCreateWithFlags(&ev2, cudaEventDisableTiming);
        cudaEventCreateWithFlags(&ev3, cudaEventDisableTiming);
        cudaEventCreateWithFlags(&ev4, cudaEventDisableTiming);
        cudaFuncSetAttribute(mma_gemm<128, 0, 2, 3>, cudaFuncAttributeMaxDynamicSharedMemorySize, SMEM128);
        cudaFuncSetAttribute(mma_gemm<128, 2, 2, 1>, cudaFuncAttributeMaxDynamicSharedMemorySize, SMEMG);
        cudaFuncSetAttribute(mma_gemm<64, 1, 2, 3>,  cudaFuncAttributeMaxDynamicSharedMemorySize, SMEM64);
    }

    // ---- fork point (both side streams branch off the capture stream) ----
    cudaEventRecord(evF, 0);
    cudaStreamWaitEvent(s2, evF, 0);
    cudaStreamWaitEvent(s3, evF, 0);

    // ---- s2: FULL gram chain (prep + gram + topk + rescore), joins at gather ----
    sq_kernel<<<NN / 8, 256, 0, s2>>>(cond, sq);
    split4_kernel<<<(NN * DF / 4 + 1023) / 1024, 256, 0, s2>>>(cond, ch, cl, NN * DF / 4);
    tsplit_kernel<<<(DF * NN + 255) / 256, 256, 0, s2>>>(cond, cth, ctl);
    mma_gemm<128, 2, 2, 1><<<dim3(NN / 128, NN / 128), 256, SMEMG, s2>>>(
        ch, cl, cth, ctl, sq, nullptr, nullptr, key, nullptr, NN, NN, DF);
    topk_kernel<<<NN / 8, 256, 0, s2>>>(key, cand);
    rescore_kernel<<<NN / 8, 256, 0, s2>>>(cond, sq, cand, nidx);
    cudaEventRecord(evJ, s2);

    // ---- s3: deferred weight splits, per-weight events (pipelined with layers) ----
    split4_kernel<<<(HID * HID / 4 + 1023) / 1024, 256, 0, s3>>>(W1, W1h, W1l, HID * HID / 4);
    cudaEventRecord(ev1, s3);
    split4_kernel<<<(HID * HID / 4 + 1023) / 1024, 256, 0, s3>>>(W2, W2h, W2l, HID * HID / 4);
    cudaEventRecord(ev2, s3);
    split4_kernel<<<(HID * HID / 4 + 1023) / 1024, 256, 0, s3>>>(W3, W3h, W3l, HID * HID / 4);
    cudaEventRecord(ev3, s3);
    split4_kernel<<<(HID * DR / 4 + 1023) / 1024, 256, 0, s3>>>(Wout, Woh, Wol, HID * DR / 4);
    cudaEventRecord(ev4, s3);

    // ---- default: minimal prep for layer 1, then the MLP chain ----
    concat_split_kernel<<<(NN * XDIM + 255) / 256, 256>>>(cond, tens, x0h, x0l);
    split4_kernel<<<(XDIM * HID / 4 + 1023) / 1024, 256>>>(Win, Wih, Wil, XDIM * HID / 4);

    mma_gemm<128, 0, 2, 3><<<dim3(HID / 128, NN / 128), 256, SMEM128>>>(
        x0h, x0l, Wih, Wil, b_in, nullptr, nullptr, hAh, hAl, NN, HID, XDIM);
    cudaStreamWaitEvent(0, ev1, 0);
    mma_gemm<128, 0, 2, 3><<<dim3(HID / 128, NN / 128), 256, SMEM128>>>(
        hAh, hAl, W1h, W1l, b1, nullptr, nullptr, hBh, hBl, NN, HID, HID);
    cudaStreamWaitEvent(0, ev2, 0);
    mma_gemm<128, 0, 2, 3><<<dim3(HID / 128, NN / 128), 256, SMEM128>>>(
        hBh, hBl, W2h, W2l, b2, nullptr, nullptr, hAh, hAl, NN, HID, HID);
    cudaStreamWaitEvent(0, ev3, 0);
    mma_gemm<128, 0, 2, 3><<<dim3(HID / 128, NN / 128), 256, SMEM128>>>(
        hAh, hAl, W3h, W3l, b3, nullptr, nullptr, hBh, hBl, NN, HID, HID);
    cudaStreamWaitEvent(0, ev4, 0);
    mma_gemm<64, 1, 2, 3><<<dim3(DR / 64, NN / 128), 128, SMEM64>>>(
        hBh, hBl, Woh, Wol, bout, tens, pushed, nullptr, nullptr, NN, DR, HID);

    // ---- join, then gather ----
    cudaStreamWaitEvent(0, evJ, 0);
    gather_kernel<<<(NN * TOPK * 16 + 255) / 256, 256>>>(nidx, pushed, out);
}

// round 15
// speedup vs baseline: 1.2041x; 1.0234x over previous
#include <cuda_runtime.h>
#include <cuda_fp16.h>
#include <cstdint>

#define NN    4096
#define DF    128
#define DR    64
#define HID   1024
#define TOPK  10
#define NCAND 16
#define XDIM  192

typedef __half f16;

// ---------------- static scratch ----------------
__device__ f16   g_key[(size_t)NN * NN];    // fp16 keys (32 MB -> L2-resident)
__device__ float g_sq [NN];
__device__ int   g_cand[NN * NCAND];
__device__ int   g_nidx[NN * TOPK];
__device__ float g_pushed[NN * DR];

__device__ f16 g_x0h[NN * XDIM], g_x0l[NN * XDIM];
__device__ f16 g_hAh[NN * HID],  g_hAl[NN * HID];
__device__ f16 g_hBh[NN * HID],  g_hBl[NN * HID];
__device__ f16 g_ch [NN * DF],   g_cl [NN * DF];
__device__ f16 g_cth[DF * NN],   g_ctl[DF * NN];
__device__ f16 g_Wih[XDIM * HID], g_Wil[XDIM * HID];
__device__ f16 g_W1h[HID * HID],  g_W1l[HID * HID];
__device__ f16 g_W2h[HID * HID],  g_W2l[HID * HID];
__device__ f16 g_W3h[HID * HID],  g_W3l[HID * HID];
__device__ f16 g_Woh[HID * DR],   g_Wol[HID * DR];

// ---------------- helpers ----------------
__device__ __forceinline__ float sp(float x) {
    return fmaxf(x, 0.0f) + log1pf(expf(-fabsf(x)));
}

__device__ __forceinline__ void cpa16(void* s, const void* g) {
    uint32_t sa = (uint32_t)__cvta_generic_to_shared(s);
    asm volatile("cp.async.cg.shared.global [%0], [%1], 16;" :: "r"(sa), "l"(g) : "memory");
}
#define CP_COMMIT() asm volatile("cp.async.commit_group;" ::: "memory")
#define CP_WAIT0()  asm volatile("cp.async.wait_group 0;" ::: "memory")

__device__ __forceinline__ void ldm_x4(uint32_t* r, const void* p) {
    uint32_t a = (uint32_t)__cvta_generic_to_shared(p);
    asm volatile("ldmatrix.sync.aligned.m8n8.x4.shared.b16 {%0,%1,%2,%3}, [%4];"
        : "=r"(r[0]), "=r"(r[1]), "=r"(r[2]), "=r"(r[3]) : "r"(a));
}
__device__ __forceinline__ void ldm_x2t(uint32_t* r, const void* p) {
    uint32_t a = (uint32_t)__cvta_generic_to_shared(p);
    asm volatile("ldmatrix.sync.aligned.m8n8.x2.trans.shared.b16 {%0,%1}, [%2];"
        : "=r"(r[0]), "=r"(r[1]) : "r"(a));
}
__device__ __forceinline__ void mma16816(float* c, const uint32_t* a, const uint32_t* b) {
    asm volatile("mma.sync.aligned.m16n8k16.row.col.f32.f16.f16.f32 "
        "{%0,%1,%2,%3}, {%4,%5,%6,%7}, {%8,%9}, {%0,%1,%2,%3};"
        : "+f"(c[0]), "+f"(c[1]), "+f"(c[2]), "+f"(c[3])
        : "r"(a[0]), "r"(a[1]), "r"(a[2]), "r"(a[3]), "r"(b[0]), "r"(b[1]));
}

__device__ __forceinline__ void split1(float v, f16& h, f16& l) {
    h = __float2half(v);
    l = __float2half(v - __half2float(h));
}

// ---------------- small prep kernels ----------------
__global__ void sq_kernel(const float* __restrict__ cond, float* __restrict__ sq) {
    const int row  = blockIdx.x * 8 + (threadIdx.x >> 5);
    const int lane = threadIdx.x & 31;
    const float4 t = reinterpret_cast<const float4*>(cond)[row * 32 + lane];
    float s = t.x * t.x + t.y * t.y + t.z * t.z + t.w * t.w;
    #pragma unroll
    for (int o = 16; o > 0; o >>= 1) s += __shfl_down_sync(0xffffffffu, s, o);
    if (lane == 0) sq[row] = s;
}

__global__ void split4_kernel(const float* __restrict__ src, f16* __restrict__ hi,
                              f16* __restrict__ lo, int n4) {
    const int i0 = blockIdx.x * (blockDim.x * 4) + threadIdx.x;
    #pragma unroll
    for (int u = 0; u < 4; u++) {
        const int i = i0 + u * blockDim.x;
        if (i >= n4) return;
        const float4 v = reinterpret_cast<const float4*>(src)[i];
        f16 h0, l0, h1, l1, h2, l2, h3, l3;
        split1(v.x, h0, l0); split1(v.y, h1, l1);
        split1(v.z, h2, l2); split1(v.w, h3, l3);
        __half2 hh[2] = { __halves2half2(h0, h1), __halves2half2(h2, h3) };
        __half2 ll[2] = { __halves2half2(l0, l1), __halves2half2(l2, l3) };
        reinterpret_cast<uint2*>(hi)[i] = *reinterpret_cast<uint2*>(hh);
        reinterpret_cast<uint2*>(lo)[i] = *reinterpret_cast<uint2*>(ll);
    }
}

__global__ void tsplit_kernel(const float* __restrict__ cond, f16* __restrict__ hi,
                              f16* __restrict__ lo) {
    const int i = blockIdx.x * blockDim.x + threadIdx.x;
    if (i >= DF * NN) return;
    const int k = i / NN, n = i % NN;
    f16 h, l; split1(cond[n * DF + k], h, l);
    hi[i] = h; lo[i] = l;
}

__global__ void concat_split_kernel(const float* __restrict__ cond, const float* __restrict__ tens,
                                    f16* __restrict__ hi, f16* __restrict__ lo) {
    const int i = blockIdx.x * blockDim.x + threadIdx.x;
    if (i >= NN * XDIM) return;
    const int r = i / XDIM, c = i % XDIM;
    const float v = (c < DF) ? cond[r * DF + c] : tens[r * DR + (c - DF)];
    f16 h, l; split1(v, h, l);
    hi[i] = h; lo[i] = l;
}

// ---------------- split-fp16 tensor-core GEMM, BK=32, single-barrier pipeline ----
// PASSES==3: C ~= (Ah+Al)@(Bh+Bl) minus lo*lo (split precision, MLP layers).
// PASSES==1: C ~= Ah@Bh (plain fp16; gram keys -- protected by exact rescore).
// BM=128, warp tile 64x32.
// EPI 0: softplus -> split fp16; EPI 1: extra-(acc+bias); EPI 2: fp16 gram keys -> Oh.
template<int BN, int EPI, int OCC, int PASSES>
__global__ void __launch_bounds__((BN / 32) * 64, OCC)
mma_gemm(const f16* __restrict__ Ah, const f16* __restrict__ Al,
         const f16* __restrict__ Bh, const f16* __restrict__ Bl,
         const float* __restrict__ bias, const float* __restrict__ extra,
         float* __restrict__ Cf, f16* __restrict__ Oh, f16* __restrict__ Ol,
         int M, int N, int K)
{
    constexpr int WN = BN / 32;
    constexpr int THREADS = 2 * WN * 32;
    constexpr int AST = 24;       // per-subtile A row stride (48B, conflict-free)
    constexpr int BST = BN + 8;
    constexpr int ASZ = 128 * AST;
    constexpr int BSZ = 16 * BST;
    constexpr int NSLOT = (PASSES == 1) ? 4 : 8;   // buf(2) x sub(2) x split(1|2)

    extern __shared__ __align__(16) f16 dsm[];
    f16* Abase = dsm;
    f16* Bbase = dsm + NSLOT * ASZ;
    auto slot = [&](int buf, int sub, int s) {
        return (PASSES == 1) ? (buf * 2 + sub) : ((buf * 2 + sub) * 2 + s);
    };
    auto Asp = [&](int buf, int sub, int s) { return Abase + slot(buf, sub, s) * ASZ; };
    auto Bsp = [&](int buf, int sub, int s) { return Bbase + slot(buf, sub, s) * BSZ; };

    const int tid  = threadIdx.x;
    const int lane = tid & 31;
    const int w    = tid >> 5;
    const int wm   = w / WN;
    const int wn   = w % WN;
    const int row0 = blockIdx.y * 128;
    const int col0 = blockIdx.x * BN;

    // fragment addressing, hoisted
    const int arow = wm * 64 + (lane & 15);
    const int acol = (lane >> 4) << 3;
    const int brow = (lane & 15) * BST;
    const int bcol = wn * 32;

    float acc[4][4][4];
    #pragma unroll
    for (int a = 0; a < 4; a++)
        #pragma unroll
        for (int b = 0; b < 4; b++)
            #pragma unroll
            for (int c = 0; c < 4; c++) acc[a][b][c] = 0.0f;

    const int nchunk = K / 32;
    constexpr int NSPLIT = (PASSES == 1) ? 1 : 2;

    auto load_chunk = [&](int ci, int buf) {
        #pragma unroll
        for (int sub = 0; sub < 2; sub++) {
            const int kt = ci * 32 + sub * 16;
            #pragma unroll
            for (int s = 0; s < NSPLIT; s++) {
                const f16* Ag = s ? Al : Ah;
                f16* As = Asp(buf, sub, s);
                for (int f = tid; f < 128 * 2; f += THREADS) {
                    const int m = f >> 1, c = (f & 1) * 8;
                    cpa16(&As[m * AST + c], Ag + (size_t)(row0 + m) * K + kt + c);
                }
                const f16* Bg = s ? Bl : Bh;
                f16* Bs = Bsp(buf, sub, s);
                for (int f = tid; f < 16 * (BN / 8); f += THREADS) {
                    const int k = f / (BN / 8), c = (f % (BN / 8)) * 8;
                    cpa16(&Bs[k * BST + c], Bg + (size_t)(kt + k) * N + col0 + c);
                }
            }
        }
    };

    load_chunk(0, 0);
    CP_COMMIT();

    for (int ci = 0; ci < nchunk; ci++) {
        const int buf = ci & 1;
        // single-barrier pipeline: wait current, barrier (also fences prior
        // compute on buf^1), then prefetch next into buf^1, then compute.
        CP_WAIT0();
        __syncthreads();
        if (ci + 1 < nchunk) {
            load_chunk(ci + 1, buf ^ 1);
            CP_COMMIT();
        }

        #pragma unroll
        for (int sub = 0; sub < 2; sub++) {
            uint32_t a[4][4], b[4][2];
            const f16* Ash = Asp(buf, sub, 0);
            const f16* Bsh = Bsp(buf, sub, 0);

            if constexpr (PASSES == 1) {
                // single pass: Ah x Bh
                #pragma unroll
                for (int mt = 0; mt < 4; mt++)
                    ldm_x4(a[mt], &Ash[(arow + mt * 16) * AST + acol]);
                #pragma unroll
                for (int nt = 0; nt < 4; nt++)
                    ldm_x2t(b[nt], &Bsh[brow + bcol + nt * 8]);
                #pragma unroll
                for (int mt = 0; mt < 4; mt++)
                    #pragma unroll
                    for (int nt = 0; nt < 4; nt++) mma16816(acc[mt][nt], a[mt], b[nt]);
            } else {
                const f16* Asl = Asp(buf, sub, 1);
                const f16* Bsl = Bsp(buf, sub, 1);

                // pass 1: Ahi x Blo
                #pragma unroll
                for (int mt = 0; mt < 4; mt++)
                    ldm_x4(a[mt], &Ash[(arow + mt * 16) * AST + acol]);
                #pragma unroll
                for (int nt = 0; nt < 4; nt++)
                    ldm_x2t(b[nt], &Bsl[brow + bcol + nt * 8]);
                #pragma unroll
                for (int mt = 0; mt < 4; mt++)
                    #pragma unroll
                    for (int nt = 0; nt < 4; nt++) mma16816(acc[mt][nt], a[mt], b[nt]);

                // pass 2: Ahi x Bhi
                #pragma unroll
                for (int nt = 0; nt < 4; nt++)
                    ldm_x2t(b[nt], &Bsh[brow + bcol + nt * 8]);
                #pragma unroll
                for (int mt = 0; mt < 4; mt++)
                    #pragma unroll
                    for (int nt = 0; nt < 4; nt++) mma16816(acc[mt][nt], a[mt], b[nt]);

                // pass 3: Alo x Bhi
                #pragma unroll
                for (int mt = 0; mt < 4; mt++)
                    ldm_x4(a[mt], &Asl[(arow + mt * 16) * AST + acol]);
                #pragma unroll
                for (int mt = 0; mt < 4; mt++)
                    #pragma unroll
                    for (int nt = 0; nt < 4; nt++) mma16816(acc[mt][nt], a[mt], b[nt]);
            }
        }
        // no trailing barrier: next iteration's barrier protects buf reuse
    }

    // epilogue
    #pragma unroll
    for (int mt = 0; mt < 4; mt++) {
        #pragma unroll
        for (int nt = 0; nt < 4; nt++) {
            const int r = row0 + wm * 64 + mt * 16 + (lane >> 2);
            const int c = col0 + wn * 32 + nt * 8 + ((lane & 3) << 1);
            const float* ac = acc[mt][nt];
            if constexpr (EPI == 0) {
                const float bc0 = bias[c], bc1 = bias[c + 1];
                #pragma unroll
                for (int h = 0; h < 2; h++) {
                    const int rr = r + 8 * h;
                    const float y0 = sp(ac[2 * h] + bc0);
                    const float y1 = sp(ac[2 * h + 1] + bc1);
                    f16 h0, l0, h1, l1;
                    split1(y0, h0, l0); split1(y1, h1, l1);
                    *(__half2*)(Oh + (size_t)rr * N + c) = __halves2half2(h0, h1);
                    *(__half2*)(Ol + (size_t)rr * N + c) = __halves2half2(l0, l1);
                }
            } else if constexpr (EPI == 1) {
                const float bc0 = bias[c], bc1 = bias[c + 1];
                #pragma unroll
                for (int h = 0; h < 2; h++) {
                    const size_t o = (size_t)(r + 8 * h) * N + c;
                    Cf[o]     = extra[o]     - (ac[2 * h]     + bc0);
                    Cf[o + 1] = extra[o + 1] - (ac[2 * h + 1] + bc1);
                }
            } else {
                const float sc0 = bias[c], sc1 = bias[c + 1];
                #pragma unroll
                for (int h = 0; h < 2; h++) {
                    const float sr = bias[r + 8 * h];
                    const size_t o = (size_t)(r + 8 * h) * NN + c;
                    const float k0 = fmaxf(sr + sc0 - 2.0f * ac[2 * h],     0.0f);
                    const float k1 = fmaxf(sr + sc1 - 2.0f * ac[2 * h + 1], 0.0f);
                    *(__half2*)(Oh + o) = __halves2half2(__float2half(k0), __float2half(k1));
                }
            }
        }
    }
}

// ---------------- top-NCAND smallest per row (fp16 approx keys) ----------------
template<int L>
__device__ __forceinline__ void insL(float x, int j, float (&v)[L], int (&id)[L]) {
    if (x >= v[L - 1]) return;
    #pragma unroll
    for (int t = L - 1; t > 0; t--) {
        const bool shf = (x < v[t - 1]);
        const bool put = !shf && (x < v[t]);
        v[t]  = shf ? v[t - 1]  : (put ? x : v[t]);
        id[t] = shf ? id[t - 1] : (put ? j : id[t]);
    }
    if (x < v[0]) { v[0] = x; id[0] = j; }
}

__global__ void topk_kernel(const f16* __restrict__ key, int* __restrict__ out_cand) {
    const int row  = blockIdx.x * 8 + (threadIdx.x >> 5);
    const int lane = threadIdx.x & 31;
    const uint4* k8 = reinterpret_cast<const uint4*>(key + (size_t)row * NN);  // 8 halves

    float v[NCAND]; int id[NCAND];
    #pragma unroll
    for (int t = 0; t < NCAND; t++) { v[t] = 3.0e38f; id[t] = 0x7fffffff; }

    #pragma unroll 4
    for (int j = lane; j < NN / 8; j += 32) {
        const uint4 t = k8[j];
        const int b = 8 * j;
        const __half2 p0 = *reinterpret_cast<const __half2*>(&t.x);
        const __half2 p1 = *reinterpret_cast<const __half2*>(&t.y);
        const __half2 p2 = *reinterpret_cast<const __half2*>(&t.z);
        const __half2 p3 = *reinterpret_cast<const __half2*>(&t.w);
        insL<NCAND>(__low2float(p0),  b,     v, id);
        insL<NCAND>(__high2float(p0), b + 1, v, id);
        insL<NCAND>(__low2float(p1),  b + 2, v, id);
        insL<NCAND>(__high2float(p1), b + 3, v, id);
        insL<NCAND>(__low2float(p2),  b + 4, v, id);
        insL<NCAND>(__high2float(p2), b + 5, v, id);
        insL<NCAND>(__low2float(p3),  b + 6, v, id);
        insL<NCAND>(__high2float(p3), b + 7, v, id);
    }

    #pragma unroll
    for (int k = 0; k < NCAND; k++) {
        float mv = v[0]; int mi = id[0];
        #pragma unroll
        for (int off = 16; off > 0; off >>= 1) {
            const float ov = __shfl_down_sync(0xffffffffu, mv, off);
            const int   oi = __shfl_down_sync(0xffffffffu, mi, off);
            if (ov < mv || (ov == mv && oi < mi)) { mv = ov; mi = oi; }
        }
        mv = __shfl_sync(0xffffffffu, mv, 0);
        mi = __shfl_sync(0xffffffffu, mi, 0);
        if (id[0] == mi) {
            #pragma unroll
            for (int t = 0; t < NCAND - 1; t++) { v[t] = v[t + 1]; id[t] = id[t + 1]; }
            v[NCAND - 1] = 3.0e38f; id[NCAND - 1] = 0x7fffffff;
        }
        if (lane == 0) out_cand[row * NCAND + k] = mi;
    }
}

// ---------------- exact fp32 rescore of the 16 candidates -> final top-10 --------
__global__ void rescore_kernel(const float* __restrict__ cond, const float* __restrict__ sq,
                               const int* __restrict__ cand, int* __restrict__ out_idx) {
    const int row  = blockIdx.x * 8 + (threadIdx.x >> 5);
    const int lane = threadIdx.x & 31;
    const float4 cr = reinterpret_cast<const float4*>(cond)[row * 32 + lane];
    const float sr = sq[row];

    float mv = 3.0e38f; int mid = 0x7fffffff;
    #pragma unroll
    for (int c = 0; c < NCAND; c++) {
        const int j = cand[row * NCAND + c];
        const float4 cc = reinterpret_cast<const float4*>(cond)[j * 32 + lane];
        float d = cr.x * cc.x + cr.y * cc.y + cr.z * cc.z + cr.w * cc.w;
        #pragma unroll
        for (int o = 16; o > 0; o >>= 1) d += __shfl_down_sync(0xffffffffu, d, o);
        d = __shfl_sync(0xffffffffu, d, 0);
        const float k = fmaxf(sr + sq[j] - 2.0f * d, 0.0f);
        if (lane == c) { mv = k; mid = j; }
    }

    #pragma unroll
    for (int k = 0; k < TOPK; k++) {
        float bv = mv; int bi = mid;
        #pragma unroll
        for (int off = 16; off > 0; off >>= 1) {
            const float ov = __shfl_down_sync(0xffffffffu, bv, off);
            const int   oi = __shfl_down_sync(0xffffffffu, bi, off);
            if (ov < bv || (ov == bv && oi < bi)) { bv = ov; bi = oi; }
        }
        bv = __shfl_sync(0xffffffffu, bv, 0);
        bi = __shfl_sync(0xffffffffu, bi, 0);
        if (mid == bi) { mv = 3.0e38f; mid = 0x7fffffff; }
        if (lane == 0) out_idx[row * TOPK + k] = bi;
    }
}

// ---------------- final gather ----------------
__global__ void gather_kernel(const int* __restrict__ nidx, const float* __restrict__ pushed,
                              float* __restrict__ out) {
    const int t = blockIdx.x * blockDim.x + threadIdx.x;
    if (t >= NN * TOPK * 16) return;
    const int r = t >> 4, c = t & 15;
    const int j = nidx[r];
    reinterpret_cast<float4*>(out)[t] = reinterpret_cast<const float4*>(pushed)[j * 16 + c];
}

// ---------------- launch ----------------
extern "C" void kernel_launch(void* const* d_in, const int* in_sizes, int n_in,
                              void* d_out, int out_size)
{
    const float* cond = (const float*)d_in[0];
    const float* tens = (const float*)d_in[1];
    const float* Win  = (const float*)d_in[2];
    const float* b_in = (const float*)d_in[3];
    const float* W1   = (const float*)d_in[4];
    const float* b1   = (const float*)d_in[5];
    const float* W2   = (const float*)d_in[6];
    const float* b2   = (const float*)d_in[7];
    const float* W3   = (const float*)d_in[8];
    const float* b3   = (const float*)d_in[9];
    const float* Wout = (const float*)d_in[10];
    const float* bout = (const float*)d_in[11];
    float* out = (float*)d_out;

    float *sq, *pushed; int *cand, *nidx;
    f16 *key;
    f16 *x0h, *x0l, *hAh, *hAl, *hBh, *hBl, *ch, *cl, *cth, *ctl;
    f16 *Wih, *Wil, *W1h, *W1l, *W2h, *W2l, *W3h, *W3l, *Woh, *Wol;
    cudaGetSymbolAddress((void**)&key, g_key);
    cudaGetSymbolAddress((void**)&sq, g_sq);
    cudaGetSymbolAddress((void**)&cand, g_cand);
    cudaGetSymbolAddress((void**)&nidx, g_nidx);
    cudaGetSymbolAddress((void**)&pushed, g_pushed);
    cudaGetSymbolAddress((void**)&x0h, g_x0h); cudaGetSymbolAddress((void**)&x0l, g_x0l);
    cudaGetSymbolAddress((void**)&hAh, g_hAh); cudaGetSymbolAddress((void**)&hAl, g_hAl);
    cudaGetSymbolAddress((void**)&hBh, g_hBh); cudaGetSymbolAddress((void**)&hBl, g_hBl);
    cudaGetSymbolAddress((void**)&ch,  g_ch);  cudaGetSymbolAddress((void**)&cl,  g_cl);
    cudaGetSymbolAddress((void**)&cth, g_cth); cudaGetSymbolAddress((void**)&ctl, g_ctl);
    cudaGetSymbolAddress((void**)&Wih, g_Wih); cudaGetSymbolAddress((void**)&Wil, g_Wil);
    cudaGetSymbolAddress((void**)&W1h, g_W1h); cudaGetSymbolAddress((void**)&W1l, g_W1l);
    cudaGetSymbolAddress((void**)&W2h, g_W2h); cudaGetSymbolAddress((void**)&W2l, g_W2l);
    cudaGetSymbolAddress((void**)&W3h, g_W3h); cudaGetSymbolAddress((void**)&W3l, g_W3l);
    cudaGetSymbolAddress((void**)&Woh, g_Woh); cudaGetSymbolAddress((void**)&Wol, g_Wol);

    // dynamic smem sizes (bytes)
    const int SMEM128  = 2 * 8 * (128 * 24 + 16 * (128 + 8));  // 3-pass, BN=128: 83968
    const int SMEM64   = 2 * 8 * (128 * 24 + 16 * (64 + 8));   // 3-pass, BN=64:  67584
    const int SMEMG    = 2 * 4 * (128 * 24 + 16 * (128 + 8));  // 1-pass, BN=128: 41984

    // lazy-create side streams + events + smem opt-in (outside graph capture)
    static cudaStream_t s2 = nullptr, s3 = nullptr;
    static cudaEvent_t evF = nullptr, evJ = nullptr;
    static cudaEvent_t ev0 = nullptr, ev1 = nullptr, ev2 = nullptr, ev3 = nullptr, ev4 = nullptr;
    if (s2 == nullptr) {
        cudaStreamCreateWithFlags(&s2, cudaStreamNonBlocking);
        cudaStreamCreateWithFlags(&s3, cudaStreamNonBlocking);
        cudaEventCreateWithFlags(&evF, cudaEventDisableTiming);
        cudaEventCreateWithFlags(&evJ, cudaEventDisableTiming);
        cudaEventCreateWithFlags(&ev0, cudaEventDisableTiming);
        cudaEventCreateWithFlags(&ev1, cudaEventDisableTiming);
        cudaEventCreateWithFlags(&ev2, cudaEventDisableTiming);
        cudaEventCreateWithFlags(&ev3, cudaEventDisableTiming);
        cudaEventCreateWithFlags(&ev4, cudaEventDisableTiming);
        cudaFuncSetAttribute(mma_gemm<128, 0, 2, 3>, cudaFuncAttributeMaxDynamicSharedMemorySize, SMEM128);
        cudaFuncSetAttribute(mma_gemm<128, 2, 2, 1>, cudaFuncAttributeMaxDynamicSharedMemorySize, SMEMG);
        cudaFuncSetAttribute(mma_gemm<64, 1, 2, 3>,  cudaFuncAttributeMaxDynamicSharedMemorySize, SMEM64);
    }

    // ---- fork point (both side streams branch off the capture stream) ----
    cudaEventRecord(evF, 0);
    cudaStreamWaitEvent(s2, evF, 0);
    cudaStreamWaitEvent(s3, evF, 0);

    // ---- s2: FULL gram chain (prep + gram + topk + rescore), joins at gather ----
    sq_kernel<<<NN / 8, 256, 0, s2>>>(cond, sq);
    split4_kernel<<<(NN * DF / 4 + 1023) / 1024, 256, 0, s2>>>(cond, ch, cl, NN * DF / 4);
    tsplit_kernel<<<(DF * NN + 255) / 256, 256, 0, s2>>>(cond, cth, ctl);
    mma_gemm<128, 2, 2, 1><<<dim3(NN / 128, NN / 128), 256, SMEMG, s2>>>(
        ch, cl, cth, ctl, sq, nullptr, nullptr, key, nullptr, NN, NN, DF);
    topk_kernel<<<NN / 8, 256, 0, s2>>>(key, cand);
    rescore_kernel<<<NN / 8, 256, 0, s2>>>(cond, sq, cand, nidx);
    cudaEventRecord(evJ, s2);

    // ---- s3: weight splits front-to-back, per-weight events ----
    split4_kernel<<<(XDIM * HID / 4 + 1023) / 1024, 256, 0, s3>>>(Win, Wih, Wil, XDIM * HID / 4);
    cudaEventRecord(ev0, s3);
    split4_kernel<<<(HID * HID / 4 + 1023) / 1024, 256, 0, s3>>>(W1, W1h, W1l, HID * HID / 4);
    cudaEventRecord(ev1, s3);
    split4_kernel<<<(HID * HID / 4 + 1023) / 1024, 256, 0, s3>>>(W2, W2h, W2l, HID * HID / 4);
    cudaEventRecord(ev2, s3);
    split4_kernel<<<(HID * HID / 4 + 1023) / 1024, 256, 0, s3>>>(W3, W3h, W3l, HID * HID / 4);
    cudaEventRecord(ev3, s3);
    split4_kernel<<<(HID * DR / 4 + 1023) / 1024, 256, 0, s3>>>(Wout, Woh, Wol, HID * DR / 4);
    cudaEventRecord(ev4, s3);

    // ---- default: minimal prep for layer 1, then the MLP chain ----
    concat_split_kernel<<<(NN * XDIM + 255) / 256, 256>>>(cond, tens, x0h, x0l);
    cudaStreamWaitEvent(0, ev0, 0);

    mma_gemm<128, 0, 2, 3><<<dim3(HID / 128, NN / 128), 256, SMEM128>>>(
        x0h, x0l, Wih, Wil, b_in, nullptr, nullptr, hAh, hAl, NN, HID, XDIM);
    cudaStreamWaitEvent(0, ev1, 0);
    mma_gemm<128, 0, 2, 3><<<dim3(HID / 128, NN / 128), 256, SMEM128>>>(
        hAh, hAl, W1h, W1l, b1, nullptr, nullptr, hBh, hBl, NN, HID, HID);
    cudaStreamWaitEvent(0, ev2, 0);
    mma_gemm<128, 0, 2, 3><<<dim3(HID / 128, NN / 128), 256, SMEM128>>>(
        hBh, hBl, W2h, W2l, b2, nullptr, nullptr, hAh, hAl, NN, HID, HID);
    cudaStreamWaitEvent(0, ev3, 0);
    mma_gemm<128, 0, 2, 3><<<dim3(HID / 128, NN / 128), 256, SMEM128>>>(
        hAh, hAl, W3h, W3l, b3, nullptr, nullptr, hBh, hBl, NN, HID, HID);
    cudaStreamWaitEvent(0, ev4, 0);
    mma_gemm<64, 1, 2, 3><<<dim3(DR / 64, NN / 128), 128, SMEM64>>>(
        hBh, hBl, Woh, Wol, bout, tens, pushed, nullptr, nullptr, NN, DR, HID);

    // ---- join, then gather ----
    cudaStreamWaitEvent(0, evJ, 0);
    gather_kernel<<<(NN * TOPK * 16 + 255) / 256, 256>>>(nidx, pushed, out);
}

// round 16
// speedup vs baseline: 1.2622x; 1.0482x over previous
#include <cuda_runtime.h>
#include <cuda_fp16.h>
#include <cstdint>

#define NN    4096
#define DF    128
#define DR    64
#define HID   1024
#define TOPK  10
#define NCAND 16
#define XDIM  192
#define KSPL  4

typedef __half f16;

// ---------------- static scratch ----------------
__device__ f16   g_key[(size_t)NN * NN];    // fp16 keys (32 MB -> L2-resident)
__device__ float g_sq [NN];
__device__ int   g_cand[NN * NCAND];
__device__ int   g_nidx[NN * TOPK];
__device__ float g_pushed[NN * DR];
__device__ float g_part[KSPL * NN * DR];    // split-K partials for the out layer

__device__ f16 g_x0h[NN * XDIM], g_x0l[NN * XDIM];
__device__ f16 g_hAh[NN * HID],  g_hAl[NN * HID];
__device__ f16 g_hBh[NN * HID],  g_hBl[NN * HID];
__device__ f16 g_ch [NN * DF],   g_cl [NN * DF];
__device__ f16 g_cth[DF * NN],   g_ctl[DF * NN];
__device__ f16 g_Wih[XDIM * HID], g_Wil[XDIM * HID];
__device__ f16 g_W1h[HID * HID],  g_W1l[HID * HID];
__device__ f16 g_W2h[HID * HID],  g_W2l[HID * HID];
__device__ f16 g_W3h[HID * HID],  g_W3l[HID * HID];
__device__ f16 g_Woh[HID * DR],   g_Wol[HID * DR];

// ---------------- helpers ----------------
__device__ __forceinline__ float sp(float x) {
    return fmaxf(x, 0.0f) + log1pf(expf(-fabsf(x)));
}

__device__ __forceinline__ void cpa16(void* s, const void* g) {
    uint32_t sa = (uint32_t)__cvta_generic_to_shared(s);
    asm volatile("cp.async.cg.shared.global [%0], [%1], 16;" :: "r"(sa), "l"(g) : "memory");
}
#define CP_COMMIT() asm volatile("cp.async.commit_group;" ::: "memory")
#define CP_WAIT0()  asm volatile("cp.async.wait_group 0;" ::: "memory")

__device__ __forceinline__ void ldm_x4(uint32_t* r, const void* p) {
    uint32_t a = (uint32_t)__cvta_generic_to_shared(p);
    asm volatile("ldmatrix.sync.aligned.m8n8.x4.shared.b16 {%0,%1,%2,%3}, [%4];"
        : "=r"(r[0]), "=r"(r[1]), "=r"(r[2]), "=r"(r[3]) : "r"(a));
}
__device__ __forceinline__ void ldm_x2t(uint32_t* r, const void* p) {
    uint32_t a = (uint32_t)__cvta_generic_to_shared(p);
    asm volatile("ldmatrix.sync.aligned.m8n8.x2.trans.shared.b16 {%0,%1}, [%2];"
        : "=r"(r[0]), "=r"(r[1]) : "r"(a));
}
__device__ __forceinline__ void mma16816(float* c, const uint32_t* a, const uint32_t* b) {
    asm volatile("mma.sync.aligned.m16n8k16.row.col.f32.f16.f16.f32 "
        "{%0,%1,%2,%3}, {%4,%5,%6,%7}, {%8,%9}, {%0,%1,%2,%3};"
        : "+f"(c[0]), "+f"(c[1]), "+f"(c[2]), "+f"(c[3])
        : "r"(a[0]), "r"(a[1]), "r"(a[2]), "r"(a[3]), "r"(b[0]), "r"(b[1]));
}

__device__ __forceinline__ void split1(float v, f16& h, f16& l) {
    h = __float2half(v);
    l = __float2half(v - __half2float(h));
}

// ---------------- small prep kernels ----------------
__global__ void sq_kernel(const float* __restrict__ cond, float* __restrict__ sq) {
    const int row  = blockIdx.x * 8 + (threadIdx.x >> 5);
    const int lane = threadIdx.x & 31;
    const float4 t = reinterpret_cast<const float4*>(cond)[row * 32 + lane];
    float s = t.x * t.x + t.y * t.y + t.z * t.z + t.w * t.w;
    #pragma unroll
    for (int o = 16; o > 0; o >>= 1) s += __shfl_down_sync(0xffffffffu, s, o);
    if (lane == 0) sq[row] = s;
}

__global__ void split4_kernel(const float* __restrict__ src, f16* __restrict__ hi,
                              f16* __restrict__ lo, int n4) {
    const int i0 = blockIdx.x * (blockDim.x * 4) + threadIdx.x;
    #pragma unroll
    for (int u = 0; u < 4; u++) {
        const int i = i0 + u * blockDim.x;
        if (i >= n4) return;
        const float4 v = reinterpret_cast<const float4*>(src)[i];
        f16 h0, l0, h1, l1, h2, l2, h3, l3;
        split1(v.x, h0, l0); split1(v.y, h1, l1);
        split1(v.z, h2, l2); split1(v.w, h3, l3);
        __half2 hh[2] = { __halves2half2(h0, h1), __halves2half2(h2, h3) };
        __half2 ll[2] = { __halves2half2(l0, l1), __halves2half2(l2, l3) };
        reinterpret_cast<uint2*>(hi)[i] = *reinterpret_cast<uint2*>(hh);
        reinterpret_cast<uint2*>(lo)[i] = *reinterpret_cast<uint2*>(ll);
    }
}

__global__ void tsplit_kernel(const float* __restrict__ cond, f16* __restrict__ hi,
                              f16* __restrict__ lo) {
    const int i = blockIdx.x * blockDim.x + threadIdx.x;
    if (i >= DF * NN) return;
    const int k = i / NN, n = i % NN;
    f16 h, l; split1(cond[n * DF + k], h, l);
    hi[i] = h; lo[i] = l;
}

__global__ void concat_split_kernel(const float* __restrict__ cond, const float* __restrict__ tens,
                                    f16* __restrict__ hi, f16* __restrict__ lo) {
    const int i = blockIdx.x * blockDim.x + threadIdx.x;
    if (i >= NN * XDIM) return;
    const int r = i / XDIM, c = i % XDIM;
    const float v = (c < DF) ? cond[r * DF + c] : tens[r * DR + (c - DF)];
    f16 h, l; split1(v, h, l);
    hi[i] = h; lo[i] = l;
}

// ---------------- split-fp16 tensor-core GEMM, BK=32, single-barrier pipeline ----
// PASSES==3: C ~= (Ah+Al)@(Bh+Bl) minus lo*lo (split precision, MLP layers).
// PASSES==1: C ~= Ah@Bh (plain fp16; gram keys -- protected by exact rescore).
// K is the per-launch (per-z-slice) depth; lda is the true A row stride.
// kt offset includes blockIdx.z*K (split-K slices).
// EPI 0: softplus -> split fp16; EPI 2: fp16 gram keys -> Oh;
// EPI 3: raw fp32 partial acc -> Cf + blockIdx.z*M*N (split-K out layer).
template<int BN, int EPI, int OCC, int PASSES>
__global__ void __launch_bounds__((BN / 32) * 64, OCC)
mma_gemm(const f16* __restrict__ Ah, const f16* __restrict__ Al,
         const f16* __restrict__ Bh, const f16* __restrict__ Bl,
         const float* __restrict__ bias, const float* __restrict__ extra,
         float* __restrict__ Cf, f16* __restrict__ Oh, f16* __restrict__ Ol,
         int M, int N, int K, int lda)
{
    constexpr int WN = BN / 32;
    constexpr int THREADS = 2 * WN * 32;
    constexpr int AST = 24;       // per-subtile A row stride (48B, conflict-free)
    constexpr int BST = BN + 8;
    constexpr int ASZ = 128 * AST;
    constexpr int BSZ = 16 * BST;
    constexpr int NSLOT = (PASSES == 1) ? 4 : 8;   // buf(2) x sub(2) x split(1|2)

    extern __shared__ __align__(16) f16 dsm[];
    f16* Abase = dsm;
    f16* Bbase = dsm + NSLOT * ASZ;
    auto slot = [&](int buf, int sub, int s) {
        return (PASSES == 1) ? (buf * 2 + sub) : ((buf * 2 + sub) * 2 + s);
    };
    auto Asp = [&](int buf, int sub, int s) { return Abase + slot(buf, sub, s) * ASZ; };
    auto Bsp = [&](int buf, int sub, int s) { return Bbase + slot(buf, sub, s) * BSZ; };

    const int tid  = threadIdx.x;
    const int lane = tid & 31;
    const int w    = tid >> 5;
    const int wm   = w / WN;
    const int wn   = w % WN;
    const int row0 = blockIdx.y * 128;
    const int col0 = blockIdx.x * BN;
    const int kz   = blockIdx.z * K;

    // fragment addressing, hoisted
    const int arow = wm * 64 + (lane & 15);
    const int acol = (lane >> 4) << 3;
    const int brow = (lane & 15) * BST;
    const int bcol = wn * 32;

    float acc[4][4][4];
    #pragma unroll
    for (int a = 0; a < 4; a++)
        #pragma unroll
        for (int b = 0; b < 4; b++)
            #pragma unroll
            for (int c = 0; c < 4; c++) acc[a][b][c] = 0.0f;

    const int nchunk = K / 32;
    constexpr int NSPLIT = (PASSES == 1) ? 1 : 2;

    auto load_chunk = [&](int ci, int buf) {
        #pragma unroll
        for (int sub = 0; sub < 2; sub++) {
            const int kt = kz + ci * 32 + sub * 16;
            #pragma unroll
            for (int s = 0; s < NSPLIT; s++) {
                const f16* Ag = s ? Al : Ah;
                f16* As = Asp(buf, sub, s);
                for (int f = tid; f < 128 * 2; f += THREADS) {
                    const int m = f >> 1, c = (f & 1) * 8;
                    cpa16(&As[m * AST + c], Ag + (size_t)(row0 + m) * lda + kt + c);
                }
                const f16* Bg = s ? Bl : Bh;
                f16* Bs = Bsp(buf, sub, s);
                for (int f = tid; f < 16 * (BN / 8); f += THREADS) {
                    const int k = f / (BN / 8), c = (f % (BN / 8)) * 8;
                    cpa16(&Bs[k * BST + c], Bg + (size_t)(kt + k) * N + col0 + c);
                }
            }
        }
    };

    load_chunk(0, 0);
    CP_COMMIT();

    for (int ci = 0; ci < nchunk; ci++) {
        const int buf = ci & 1;
        CP_WAIT0();
        __syncthreads();
        if (ci + 1 < nchunk) {
            load_chunk(ci + 1, buf ^ 1);
            CP_COMMIT();
        }

        #pragma unroll
        for (int sub = 0; sub < 2; sub++) {
            uint32_t a[4][4], b[4][2];
            const f16* Ash = Asp(buf, sub, 0);
            const f16* Bsh = Bsp(buf, sub, 0);

            if constexpr (PASSES == 1) {
                #pragma unroll
                for (int mt = 0; mt < 4; mt++)
                    ldm_x4(a[mt], &Ash[(arow + mt * 16) * AST + acol]);
                #pragma unroll
                for (int nt = 0; nt < 4; nt++)
                    ldm_x2t(b[nt], &Bsh[brow + bcol + nt * 8]);
                #pragma unroll
                for (int mt = 0; mt < 4; mt++)
                    #pragma unroll
                    for (int nt = 0; nt < 4; nt++) mma16816(acc[mt][nt], a[mt], b[nt]);
            } else {
                const f16* Asl = Asp(buf, sub, 1);
                const f16* Bsl = Bsp(buf, sub, 1);

                // pass 1: Ahi x Blo
                #pragma unroll
                for (int mt = 0; mt < 4; mt++)
                    ldm_x4(a[mt], &Ash[(arow + mt * 16) * AST + acol]);
                #pragma unroll
                for (int nt = 0; nt < 4; nt++)
                    ldm_x2t(b[nt], &Bsl[brow + bcol + nt * 8]);
                #pragma unroll
                for (int mt = 0; mt < 4; mt++)
                    #pragma unroll
                    for (int nt = 0; nt < 4; nt++) mma16816(acc[mt][nt], a[mt], b[nt]);

                // pass 2: Ahi x Bhi
                #pragma unroll
                for (int nt = 0; nt < 4; nt++)
                    ldm_x2t(b[nt], &Bsh[brow + bcol + nt * 8]);
                #pragma unroll
                for (int mt = 0; mt < 4; mt++)
                    #pragma unroll
                    for (int nt = 0; nt < 4; nt++) mma16816(acc[mt][nt], a[mt], b[nt]);

                // pass 3: Alo x Bhi
                #pragma unroll
                for (int mt = 0; mt < 4; mt++)
                    ldm_x4(a[mt], &Asl[(arow + mt * 16) * AST + acol]);
                #pragma unroll
                for (int mt = 0; mt < 4; mt++)
                    #pragma unroll
                    for (int nt = 0; nt < 4; nt++) mma16816(acc[mt][nt], a[mt], b[nt]);
            }
        }
    }

    // epilogue
    #pragma unroll
    for (int mt = 0; mt < 4; mt++) {
        #pragma unroll
        for (int nt = 0; nt < 4; nt++) {
            const int r = row0 + wm * 64 + mt * 16 + (lane >> 2);
            const int c = col0 + wn * 32 + nt * 8 + ((lane & 3) << 1);
            const float* ac = acc[mt][nt];
            if constexpr (EPI == 0) {
                const float bc0 = bias[c], bc1 = bias[c + 1];
                #pragma unroll
                for (int h = 0; h < 2; h++) {
                    const int rr = r + 8 * h;
                    const float y0 = sp(ac[2 * h] + bc0);
                    const float y1 = sp(ac[2 * h + 1] + bc1);
                    f16 h0, l0, h1, l1;
                    split1(y0, h0, l0); split1(y1, h1, l1);
                    *(__half2*)(Oh + (size_t)rr * N + c) = __halves2half2(h0, h1);
                    *(__half2*)(Ol + (size_t)rr * N + c) = __halves2half2(l0, l1);
                }
            } else if constexpr (EPI == 2) {
                const float sc0 = bias[c], sc1 = bias[c + 1];
                #pragma unroll
                for (int h = 0; h < 2; h++) {
                    const float sr = bias[r + 8 * h];
                    const size_t o = (size_t)(r + 8 * h) * NN + c;
                    const float k0 = fmaxf(sr + sc0 - 2.0f * ac[2 * h],     0.0f);
                    const float k1 = fmaxf(sr + sc1 - 2.0f * ac[2 * h + 1], 0.0f);
                    *(__half2*)(Oh + o) = __halves2half2(__float2half(k0), __float2half(k1));
                }
            } else {  // EPI == 3: raw split-K partial
                float* part = Cf + (size_t)blockIdx.z * M * N;
                #pragma unroll
                for (int h = 0; h < 2; h++) {
                    const size_t o = (size_t)(r + 8 * h) * N + c;
                    part[o]     = ac[2 * h];
                    part[o + 1] = ac[2 * h + 1];
                }
            }
        }
    }
}

// ---------------- combine split-K partials: pushed = tens - (sum parts + bias) ----
__global__ void combine_kernel(const float* __restrict__ part, const float* __restrict__ bias,
                               const float* __restrict__ tens, float* __restrict__ pushed) {
    const int i = blockIdx.x * blockDim.x + threadIdx.x;   // over NN*DR/4 float4
    if (i >= NN * DR / 4) return;
    const int c4 = (i * 4) % DR;
    const float4 b4 = *reinterpret_cast<const float4*>(bias + c4);
    float4 s = reinterpret_cast<const float4*>(part)[i];
    #pragma unroll
    for (int ks = 1; ks < KSPL; ks++) {
        const float4 p = reinterpret_cast<const float4*>(part + (size_t)ks * NN * DR)[i];
        s.x += p.x; s.y += p.y; s.z += p.z; s.w += p.w;
    }
    const float4 t = reinterpret_cast<const float4*>(tens)[i];
    float4 o;
    o.x = t.x - (s.x + b4.x);
    o.y = t.y - (s.y + b4.y);
    o.z = t.z - (s.z + b4.z);
    o.w = t.w - (s.w + b4.w);
    reinterpret_cast<float4*>(pushed)[i] = o;
}

// ---------------- top-NCAND smallest per row (fp16 approx keys) ----------------
template<int L>
__device__ __forceinline__ void insL(float x, int j, float (&v)[L], int (&id)[L]) {
    if (x >= v[L - 1]) return;
    #pragma unroll
    for (int t = L - 1; t > 0; t--) {
        const bool shf = (x < v[t - 1]);
        const bool put = !shf && (x < v[t]);
        v[t]  = shf ? v[t - 1]  : (put ? x : v[t]);
        id[t] = shf ? id[t - 1] : (put ? j : id[t]);
    }
    if (x < v[0]) { v[0] = x; id[0] = j; }
}

__global__ void topk_kernel(const f16* __restrict__ key, int* __restrict__ out_cand) {
    const int row  = blockIdx.x * 8 + (threadIdx.x >> 5);
    const int lane = threadIdx.x & 31;
    const uint4* k8 = reinterpret_cast<const uint4*>(key + (size_t)row * NN);

    float v[NCAND]; int id[NCAND];
    #pragma unroll
    for (int t = 0; t < NCAND; t++) { v[t] = 3.0e38f; id[t] = 0x7fffffff; }

    #pragma unroll 4
    for (int j = lane; j < NN / 8; j += 32) {
        const uint4 t = k8[j];
        const int b = 8 * j;
        const __half2 p0 = *reinterpret_cast<const __half2*>(&t.x);
        const __half2 p1 = *reinterpret_cast<const __half2*>(&t.y);
        const __half2 p2 = *reinterpret_cast<const __half2*>(&t.z);
        const __half2 p3 = *reinterpret_cast<const __half2*>(&t.w);
        insL<NCAND>(__low2float(p0),  b,     v, id);
        insL<NCAND>(__high2float(p0), b + 1, v, id);
        insL<NCAND>(__low2float(p1),  b + 2, v, id);
        insL<NCAND>(__high2float(p1), b + 3, v, id);
        insL<NCAND>(__low2float(p2),  b + 4, v, id);
        insL<NCAND>(__high2float(p2), b + 5, v, id);
        insL<NCAND>(__low2float(p3),  b + 6, v, id);
        insL<NCAND>(__high2float(p3), b + 7, v, id);
    }

    #pragma unroll
    for (int k = 0; k < NCAND; k++) {
        float mv = v[0]; int mi = id[0];
        #pragma unroll
        for (int off = 16; off > 0; off >>= 1) {
            const float ov = __shfl_down_sync(0xffffffffu, mv, off);
            const int   oi = __shfl_down_sync(0xffffffffu, mi, off);
            if (ov < mv || (ov == mv && oi < mi)) { mv = ov; mi = oi; }
        }
        mv = __shfl_sync(0xffffffffu, mv, 0);
        mi = __shfl_sync(0xffffffffu, mi, 0);
        if (id[0] == mi) {
            #pragma unroll
            for (int t = 0; t < NCAND - 1; t++) { v[t] = v[t + 1]; id[t] = id[t + 1]; }
            v[NCAND - 1] = 3.0e38f; id[NCAND - 1] = 0x7fffffff;
        }
        if (lane == 0) out_cand[row * NCAND + k] = mi;
    }
}

// ---------------- exact fp32 rescore of the 16 candidates -> final top-10 --------
__global__ void rescore_kernel(const float* __restrict__ cond, const float* __restrict__ sq,
                               const int* __restrict__ cand, int* __restrict__ out_idx) {
    const int row  = blockIdx.x * 8 + (threadIdx.x >> 5);
    const int lane = threadIdx.x & 31;
    const float4 cr = reinterpret_cast<const float4*>(cond)[row * 32 + lane];
    const float sr = sq[row];

    float mv = 3.0e38f; int mid = 0x7fffffff;
    #pragma unroll
    for (int c = 0; c < NCAND; c++) {
        const int j = cand[row * NCAND + c];
        const float4 cc = reinterpret_cast<const float4*>(cond)[j * 32 + lane];
        float d = cr.x * cc.x + cr.y * cc.y + cr.z * cc.z + cr.w * cc.w;
        #pragma unroll
        for (int o = 16; o > 0; o >>= 1) d += __shfl_down_sync(0xffffffffu, d, o);
        d = __shfl_sync(0xffffffffu, d, 0);
        const float k = fmaxf(sr + sq[j] - 2.0f * d, 0.0f);
        if (lane == c) { mv = k; mid = j; }
    }

    #pragma unroll
    for (int k = 0; k < TOPK; k++) {
        float bv = mv; int bi = mid;
        #pragma unroll
        for (int off = 16; off > 0; off >>= 1) {
            const float ov = __shfl_down_sync(0xffffffffu, bv, off);
            const int   oi = __shfl_down_sync(0xffffffffu, bi, off);
            if (ov < bv || (ov == bv && oi < bi)) { bv = ov; bi = oi; }
        }
        bv = __shfl_sync(0xffffffffu, bv, 0);
        bi = __shfl_sync(0xffffffffu, bi, 0);
        if (mid == bi) { mv = 3.0e38f; mid = 0x7fffffff; }
        if (lane == 0) out_idx[row * TOPK + k] = bi;
    }
}

// ---------------- final gather ----------------
__global__ void gather_kernel(const int* __restrict__ nidx, const float* __restrict__ pushed,
                              float* __restrict__ out) {
    const int t = blockIdx.x * blockDim.x + threadIdx.x;
    if (t >= NN * TOPK * 16) return;
    const int r = t >> 4, c = t & 15;
    const int j = nidx[r];
    reinterpret_cast<float4*>(out)[t] = reinterpret_cast<const float4*>(pushed)[j * 16 + c];
}

// ---------------- launch ----------------
extern "C" void kernel_launch(void* const* d_in, const int* in_sizes, int n_in,
                              void* d_out, int out_size)
{
    const float* cond = (const float*)d_in[0];
    const float* tens = (const float*)d_in[1];
    const float* Win  = (const float*)d_in[2];
    const float* b_in = (const float*)d_in[3];
    const float* W1   = (const float*)d_in[4];
    const float* b1   = (const float*)d_in[5];
    const float* W2   = (const float*)d_in[6];
    const float* b2   = (const float*)d_in[7];
    const float* W3   = (const float*)d_in[8];
    const float* b3   = (const float*)d_in[9];
    const float* Wout = (const float*)d_in[10];
    const float* bout = (const float*)d_in[11];
    float* out = (float*)d_out;

    float *sq, *pushed, *part; int *cand, *nidx;
    f16 *key;
    f16 *x0h, *x0l, *hAh, *hAl, *hBh, *hBl, *ch, *cl, *cth, *ctl;
    f16 *Wih, *Wil, *W1h, *W1l, *W2h, *W2l, *W3h, *W3l, *Woh, *Wol;
    cudaGetSymbolAddress((void**)&key, g_key);
    cudaGetSymbolAddress((void**)&sq, g_sq);
    cudaGetSymbolAddress((void**)&cand, g_cand);
    cudaGetSymbolAddress((void**)&nidx, g_nidx);
    cudaGetSymbolAddress((void**)&pushed, g_pushed);
    cudaGetSymbolAddress((void**)&part, g_part);
    cudaGetSymbolAddress((void**)&x0h, g_x0h); cudaGetSymbolAddress((void**)&x0l, g_x0l);
    cudaGetSymbolAddress((void**)&hAh, g_hAh); cudaGetSymbolAddress((void**)&hAl, g_hAl);
    cudaGetSymbolAddress((void**)&hBh, g_hBh); cudaGetSymbolAddress((void**)&hBl, g_hBl);
    cudaGetSymbolAddress((void**)&ch,  g_ch);  cudaGetSymbolAddress((void**)&cl,  g_cl);
    cudaGetSymbolAddress((void**)&cth, g_cth); cudaGetSymbolAddress((void**)&ctl, g_ctl);
    cudaGetSymbolAddress((void**)&Wih, g_Wih); cudaGetSymbolAddress((void**)&Wil, g_Wil);
    cudaGetSymbolAddress((void**)&W1h, g_W1h); cudaGetSymbolAddress((void**)&W1l, g_W1l);
    cudaGetSymbolAddress((void**)&W2h, g_W2h); cudaGetSymbolAddress((void**)&W2l, g_W2l);
    cudaGetSymbolAddress((void**)&W3h, g_W3h); cudaGetSymbolAddress((void**)&W3l, g_W3l);
    cudaGetSymbolAddress((void**)&Woh, g_Woh); cudaGetSymbolAddress((void**)&Wol, g_Wol);

    // dynamic smem sizes (bytes)
    const int SMEM128  = 2 * 8 * (128 * 24 + 16 * (128 + 8));  // 3-pass, BN=128: 83968
    const int SMEM64   = 2 * 8 * (128 * 24 + 16 * (64 + 8));   // 3-pass, BN=64:  67584
    const int SMEMG    = 2 * 4 * (128 * 24 + 16 * (128 + 8));  // 1-pass, BN=128: 41984

    // lazy-create side streams + events + smem opt-in (outside graph capture)
    static cudaStream_t s2 = nullptr, s3 = nullptr;
    static cudaEvent_t evF = nullptr, evJ = nullptr;
    static cudaEvent_t ev0 = nullptr, ev1 = nullptr, ev2 = nullptr, ev3 = nullptr, ev4 = nullptr;
    if (s2 == nullptr) {
        cudaStreamCreateWithFlags(&s2, cudaStreamNonBlocking);
        cudaStreamCreateWithFlags(&s3, cudaStreamNonBlocking);
        cudaEventCreateWithFlags(&evF, cudaEventDisableTiming);
        cudaEventCreateWithFlags(&evJ, cudaEventDisableTiming);
        cudaEventCreateWithFlags(&ev0, cudaEventDisableTiming);
        cudaEventCreateWithFlags(&ev1, cudaEventDisableTiming);
        cudaEventCreateWithFlags(&ev2, cudaEventDisableTiming);
        cudaEventCreateWithFlags(&ev3, cudaEventDisableTiming);
        cudaEventCreateWithFlags(&ev4, cudaEventDisableTiming);
        cudaFuncSetAttribute(mma_gemm<128, 0, 2, 3>, cudaFuncAttributeMaxDynamicSharedMemorySize, SMEM128);
        cudaFuncSetAttribute(mma_gemm<128, 2, 2, 1>, cudaFuncAttributeMaxDynamicSharedMemorySize, SMEMG);
        cudaFuncSetAttribute(mma_gemm<64, 3, 2, 3>,  cudaFuncAttributeMaxDynamicSharedMemorySize, SMEM64);
    }

    // ---- fork point (both side streams branch off the capture stream) ----
    cudaEventRecord(evF, 0);
    cudaStreamWaitEvent(s2, evF, 0);
    cudaStreamWaitEvent(s3, evF, 0);

    // ---- s2: FULL gram chain (prep + gram + topk + rescore), joins at gather ----
    sq_kernel<<<NN / 8, 256, 0, s2>>>(cond, sq);
    split4_kernel<<<(NN * DF / 4 + 1023) / 1024, 256, 0, s2>>>(cond, ch, cl, NN * DF / 4);
    tsplit_kernel<<<(DF * NN + 255) / 256, 256, 0, s2>>>(cond, cth, ctl);
    mma_gemm<128, 2, 2, 1><<<dim3(NN / 128, NN / 128), 256, SMEMG, s2>>>(
        ch, cl, cth, ctl, sq, nullptr, nullptr, key, nullptr, NN, NN, DF, DF);
    topk_kernel<<<NN / 8, 256, 0, s2>>>(key, cand);
    rescore_kernel<<<NN / 8, 256, 0, s2>>>(cond, sq, cand, nidx);
    cudaEventRecord(evJ, s2);

    // ---- s3: weight splits front-to-back, per-weight events ----
    split4_kernel<<<(XDIM * HID / 4 + 1023) / 1024, 256, 0, s3>>>(Win, Wih, Wil, XDIM * HID / 4);
    cudaEventRecord(ev0, s3);
    split4_kernel<<<(HID * HID / 4 + 1023) / 1024, 256, 0, s3>>>(W1, W1h, W1l, HID * HID / 4);
    cudaEventRecord(ev1, s3);
    split4_kernel<<<(HID * HID / 4 + 1023) / 1024, 256, 0, s3>>>(W2, W2h, W2l, HID * HID / 4);
    cudaEventRecord(ev2, s3);
    split4_kernel<<<(HID * HID / 4 + 1023) / 1024, 256, 0, s3>>>(W3, W3h, W3l, HID * HID / 4);
    cudaEventRecord(ev3, s3);
    split4_kernel<<<(HID * DR / 4 + 1023) / 1024, 256, 0, s3>>>(Wout, Woh, Wol, HID * DR / 4);
    cudaEventRecord(ev4, s3);

    // ---- default: minimal prep for layer 1, then the MLP chain ----
    concat_split_kernel<<<(NN * XDIM + 255) / 256, 256>>>(cond, tens, x0h, x0l);
    cudaStreamWaitEvent(0, ev0, 0);

    mma_gemm<128, 0, 2, 3><<<dim3(HID / 128, NN / 128), 256, SMEM128>>>(
        x0h, x0l, Wih, Wil, b_in, nullptr, nullptr, hAh, hAl, NN, HID, XDIM, XDIM);
    cudaStreamWaitEvent(0, ev1, 0);
    mma_gemm<128, 0, 2, 3><<<dim3(HID / 128, NN / 128), 256, SMEM128>>>(
        hAh, hAl, W1h, W1l, b1, nullptr, nullptr, hBh, hBl, NN, HID, HID, HID);
    cudaStreamWaitEvent(0, ev2, 0);
    mma_gemm<128, 0, 2, 3><<<dim3(HID / 128, NN / 128), 256, SMEM128>>>(
        hBh, hBl, W2h, W2l, b2, nullptr, nullptr, hAh, hAl, NN, HID, HID, HID);
    cudaStreamWaitEvent(0, ev3, 0);
    mma_gemm<128, 0, 2, 3><<<dim3(HID / 128, NN / 128), 256, SMEM128>>>(
        hAh, hAl, W3h, W3l, b3, nullptr, nullptr, hBh, hBl, NN, HID, HID, HID);
    cudaStreamWaitEvent(0, ev4, 0);

    // split-K=4 output layer: raw partials, then deterministic combine
    mma_gemm<64, 3, 2, 3><<<dim3(DR / 64, NN / 128, KSPL), 128, SMEM64>>>(
        hBh, hBl, Woh, Wol, nullptr, nullptr, part, nullptr, nullptr,
        NN, DR, HID / KSPL, HID);
    combine_kernel<<<(NN * DR / 4 + 255) / 256, 256>>>(part, bout, tens, pushed);

    // ---- join, then gather ----
    cudaStreamWaitEvent(0, evJ, 0);
    gather_kernel<<<(NN * TOPK * 16 + 255) / 256, 256>>>(nidx, pushed, out);
}

// round 17
// speedup vs baseline: 1.2809x; 1.0149x over previous
#include <cuda_runtime.h>
#include <cuda_fp16.h>
#include <cstdint>

#define NN    4096
#define DF    128
#define DR    64
#define HID   1024
#define TOPK  10
#define NCAND 16
#define XDIM  192
#define KSPL  4
#define NTIL  32                   // NN/128 column tiles
#define NTRI  (NTIL * (NTIL + 1) / 2)   // 528 upper-triangle tiles

typedef __half f16;

// ---------------- static scratch ----------------
__device__ f16   g_key[(size_t)NN * NN];    // fp16 keys (32 MB -> L2-resident)
__device__ float g_sq [NN];
__device__ int   g_cand[NN * NCAND];
__device__ int   g_nidx[NN * TOPK];
__device__ float g_pushed[NN * DR];
__device__ float g_part[KSPL * NN * DR];

__device__ f16 g_x0h[NN * XDIM], g_x0l[NN * XDIM];
__device__ f16 g_hAh[NN * HID],  g_hAl[NN * HID];
__device__ f16 g_hBh[NN * HID],  g_hBl[NN * HID];
__device__ f16 g_ch [NN * DF],   g_cl [NN * DF];
__device__ f16 g_cth[DF * NN],   g_ctl[DF * NN];
__device__ f16 g_Wih[XDIM * HID], g_Wil[XDIM * HID];
__device__ f16 g_W1h[HID * HID],  g_W1l[HID * HID];
__device__ f16 g_W2h[HID * HID],  g_W2l[HID * HID];
__device__ f16 g_W3h[HID * HID],  g_W3l[HID * HID];
__device__ f16 g_Woh[HID * DR],   g_Wol[HID * DR];

// ---------------- helpers ----------------
__device__ __forceinline__ float sp(float x) {
    return fmaxf(x, 0.0f) + log1pf(expf(-fabsf(x)));
}

__device__ __forceinline__ void cpa16(void* s, const void* g) {
    uint32_t sa = (uint32_t)__cvta_generic_to_shared(s);
    asm volatile("cp.async.cg.shared.global [%0], [%1], 16;" :: "r"(sa), "l"(g) : "memory");
}
#define CP_COMMIT() asm volatile("cp.async.commit_group;" ::: "memory")
#define CP_WAIT0()  asm volatile("cp.async.wait_group 0;" ::: "memory")

__device__ __forceinline__ void ldm_x4(uint32_t* r, const void* p) {
    uint32_t a = (uint32_t)__cvta_generic_to_shared(p);
    asm volatile("ldmatrix.sync.aligned.m8n8.x4.shared.b16 {%0,%1,%2,%3}, [%4];"
        : "=r"(r[0]), "=r"(r[1]), "=r"(r[2]), "=r"(r[3]) : "r"(a));
}
__device__ __forceinline__ void ldm_x2t(uint32_t* r, const void* p) {
    uint32_t a = (uint32_t)__cvta_generic_to_shared(p);
    asm volatile("ldmatrix.sync.aligned.m8n8.x2.trans.shared.b16 {%0,%1}, [%2];"
        : "=r"(r[0]), "=r"(r[1]) : "r"(a));
}
__device__ __forceinline__ void mma16816(float* c, const uint32_t* a, const uint32_t* b) {
    asm volatile("mma.sync.aligned.m16n8k16.row.col.f32.f16.f16.f32 "
        "{%0,%1,%2,%3}, {%4,%5,%6,%7}, {%8,%9}, {%0,%1,%2,%3};"
        : "+f"(c[0]), "+f"(c[1]), "+f"(c[2]), "+f"(c[3])
        : "r"(a[0]), "r"(a[1]), "r"(a[2]), "r"(a[3]), "r"(b[0]), "r"(b[1]));
}

__device__ __forceinline__ void split1(float v, f16& h, f16& l) {
    h = __float2half(v);
    l = __float2half(v - __half2float(h));
}

// ---------------- small prep kernels ----------------
__global__ void sq_kernel(const float* __restrict__ cond, float* __restrict__ sq) {
    const int row  = blockIdx.x * 8 + (threadIdx.x >> 5);
    const int lane = threadIdx.x & 31;
    const float4 t = reinterpret_cast<const float4*>(cond)[row * 32 + lane];
    float s = t.x * t.x + t.y * t.y + t.z * t.z + t.w * t.w;
    #pragma unroll
    for (int o = 16; o > 0; o >>= 1) s += __shfl_down_sync(0xffffffffu, s, o);
    if (lane == 0) sq[row] = s;
}

__global__ void split4_kernel(const float* __restrict__ src, f16* __restrict__ hi,
                              f16* __restrict__ lo, int n4) {
    const int i0 = blockIdx.x * (blockDim.x * 4) + threadIdx.x;
    #pragma unroll
    for (int u = 0; u < 4; u++) {
        const int i = i0 + u * blockDim.x;
        if (i >= n4) return;
        const float4 v = reinterpret_cast<const float4*>(src)[i];
        f16 h0, l0, h1, l1, h2, l2, h3, l3;
        split1(v.x, h0, l0); split1(v.y, h1, l1);
        split1(v.z, h2, l2); split1(v.w, h3, l3);
        __half2 hh[2] = { __halves2half2(h0, h1), __halves2half2(h2, h3) };
        __half2 ll[2] = { __halves2half2(l0, l1), __halves2half2(l2, l3) };
        reinterpret_cast<uint2*>(hi)[i] = *reinterpret_cast<uint2*>(hh);
        reinterpret_cast<uint2*>(lo)[i] = *reinterpret_cast<uint2*>(ll);
    }
}

__global__ void tsplit_kernel(const float* __restrict__ cond, f16* __restrict__ hi,
                              f16* __restrict__ lo) {
    const int i = blockIdx.x * blockDim.x + threadIdx.x;
    if (i >= DF * NN) return;
    const int k = i / NN, n = i % NN;
    f16 h, l; split1(cond[n * DF + k], h, l);
    hi[i] = h; lo[i] = l;
}

__global__ void concat_split_kernel(const float* __restrict__ cond, const float* __restrict__ tens,
                                    f16* __restrict__ hi, f16* __restrict__ lo) {
    const int i = blockIdx.x * blockDim.x + threadIdx.x;
    if (i >= NN * XDIM) return;
    const int r = i / XDIM, c = i % XDIM;
    const float v = (c < DF) ? cond[r * DF + c] : tens[r * DR + (c - DF)];
    f16 h, l; split1(v, h, l);
    hi[i] = h; lo[i] = l;
}

// ---------------- split-fp16 tensor-core GEMM, BK=32, single-barrier pipeline ----
// PASSES==3: C ~= (Ah+Al)@(Bh+Bl) minus lo*lo; PASSES==1: C ~= Ah@Bh.
// EPI 0: softplus -> split fp16; EPI 2: SYMMETRIC fp16 gram keys (triangular grid,
//        mirrored tile written via smem transpose -- bit-identical by symmetry);
// EPI 3: raw fp32 split-K partial.
template<int BN, int EPI, int OCC, int PASSES>
__global__ void __launch_bounds__((BN / 32) * 64, OCC)
mma_gemm(const f16* __restrict__ Ah, const f16* __restrict__ Al,
         const f16* __restrict__ Bh, const f16* __restrict__ Bl,
         const float* __restrict__ bias, const float* __restrict__ extra,
         float* __restrict__ Cf, f16* __restrict__ Oh, f16* __restrict__ Ol,
         int M, int N, int K, int lda)
{
    constexpr int WN = BN / 32;
    constexpr int THREADS = 2 * WN * 32;
    constexpr int AST = 24;
    constexpr int BST = BN + 8;
    constexpr int ASZ = 128 * AST;
    constexpr int BSZ = 16 * BST;
    constexpr int NSLOT = (PASSES == 1) ? 4 : 8;
    constexpr int TST = 136;      // transposed-stage stride (halves, 272B: 16B-aligned)

    extern __shared__ __align__(16) f16 dsm[];
    f16* Abase = dsm;
    f16* Bbase = dsm + NSLOT * ASZ;
    auto slot = [&](int buf, int sub, int s) {
        return (PASSES == 1) ? (buf * 2 + sub) : ((buf * 2 + sub) * 2 + s);
    };
    auto Asp = [&](int buf, int sub, int s) { return Abase + slot(buf, sub, s) * ASZ; };
    auto Bsp = [&](int buf, int sub, int s) { return Bbase + slot(buf, sub, s) * BSZ; };

    const int tid  = threadIdx.x;
    const int lane = tid & 31;
    const int w    = tid >> 5;
    const int wm   = w / WN;
    const int wn   = w % WN;

    int by = blockIdx.y, bx = blockIdx.x;
    if constexpr (EPI == 2) {
        // triangular tile mapping: blockIdx.x -> (bi, bj), bi <= bj
        int t = blockIdx.x, bi = 0;
        while (t >= NTIL - bi) { t -= NTIL - bi; bi++; }
        by = bi; bx = bi + t;
    }
    const int row0 = by * 128;
    const int col0 = bx * BN;
    const int kz   = blockIdx.z * K;

    const int arow = wm * 64 + (lane & 15);
    const int acol = (lane >> 4) << 3;
    const int brow = (lane & 15) * BST;
    const int bcol = wn * 32;

    float acc[4][4][4];
    #pragma unroll
    for (int a = 0; a < 4; a++)
        #pragma unroll
        for (int b = 0; b < 4; b++)
            #pragma unroll
            for (int c = 0; c < 4; c++) acc[a][b][c] = 0.0f;

    const int nchunk = K / 32;
    constexpr int NSPLIT = (PASSES == 1) ? 1 : 2;

    auto load_chunk = [&](int ci, int buf) {
        #pragma unroll
        for (int sub = 0; sub < 2; sub++) {
            const int kt = kz + ci * 32 + sub * 16;
            #pragma unroll
            for (int s = 0; s < NSPLIT; s++) {
                const f16* Ag = s ? Al : Ah;
                f16* As = Asp(buf, sub, s);
                for (int f = tid; f < 128 * 2; f += THREADS) {
                    const int m = f >> 1, c = (f & 1) * 8;
                    cpa16(&As[m * AST + c], Ag + (size_t)(row0 + m) * lda + kt + c);
                }
                const f16* Bg = s ? Bl : Bh;
                f16* Bs = Bsp(buf, sub, s);
                for (int f = tid; f < 16 * (BN / 8); f += THREADS) {
                    const int k = f / (BN / 8), c = (f % (BN / 8)) * 8;
                    cpa16(&Bs[k * BST + c], Bg + (size_t)(kt + k) * N + col0 + c);
                }
            }
        }
    };

    load_chunk(0, 0);
    CP_COMMIT();

    for (int ci = 0; ci < nchunk; ci++) {
        const int buf = ci & 1;
        CP_WAIT0();
        __syncthreads();
        if (ci + 1 < nchunk) {
            load_chunk(ci + 1, buf ^ 1);
            CP_COMMIT();
        }

        #pragma unroll
        for (int sub = 0; sub < 2; sub++) {
            uint32_t a[4][4], b[4][2];
            const f16* Ash = Asp(buf, sub, 0);
            const f16* Bsh = Bsp(buf, sub, 0);

            if constexpr (PASSES == 1) {
                #pragma unroll
                for (int mt = 0; mt < 4; mt++)
                    ldm_x4(a[mt], &Ash[(arow + mt * 16) * AST + acol]);
                #pragma unroll
                for (int nt = 0; nt < 4; nt++)
                    ldm_x2t(b[nt], &Bsh[brow + bcol + nt * 8]);
                #pragma unroll
                for (int mt = 0; mt < 4; mt++)
                    #pragma unroll
                    for (int nt = 0; nt < 4; nt++) mma16816(acc[mt][nt], a[mt], b[nt]);
            } else {
                const f16* Asl = Asp(buf, sub, 1);
                const f16* Bsl = Bsp(buf, sub, 1);

                #pragma unroll
                for (int mt = 0; mt < 4; mt++)
                    ldm_x4(a[mt], &Ash[(arow + mt * 16) * AST + acol]);
                #pragma unroll
                for (int nt = 0; nt < 4; nt++)
                    ldm_x2t(b[nt], &Bsl[brow + bcol + nt * 8]);
                #pragma unroll
                for (int mt = 0; mt < 4; mt++)
                    #pragma unroll
                    for (int nt = 0; nt < 4; nt++) mma16816(acc[mt][nt], a[mt], b[nt]);

                #pragma unroll
                for (int nt = 0; nt < 4; nt++)
                    ldm_x2t(b[nt], &Bsh[brow + bcol + nt * 8]);
                #pragma unroll
                for (int mt = 0; mt < 4; mt++)
                    #pragma unroll
                    for (int nt = 0; nt < 4; nt++) mma16816(acc[mt][nt], a[mt], b[nt]);

                #pragma unroll
                for (int mt = 0; mt < 4; mt++)
                    ldm_x4(a[mt], &Asl[(arow + mt * 16) * AST + acol]);
                #pragma unroll
                for (int mt = 0; mt < 4; mt++)
                    #pragma unroll
                    for (int nt = 0; nt < 4; nt++) mma16816(acc[mt][nt], a[mt], b[nt]);
            }
        }
    }

    // epilogue
    if constexpr (EPI == 2) {
        const bool mirror = (by != bx);
        if (mirror) __syncthreads();   // mainloop smem dead; safe to reuse for staging
        #pragma unroll
        for (int mt = 0; mt < 4; mt++) {
            #pragma unroll
            for (int nt = 0; nt < 4; nt++) {
                const int rr0 = wm * 64 + mt * 16 + (lane >> 2);
                const int cc0 = wn * 32 + nt * 8 + ((lane & 3) << 1);
                const float* ac = acc[mt][nt];
                const float sc0 = bias[col0 + cc0], sc1 = bias[col0 + cc0 + 1];
                #pragma unroll
                for (int h = 0; h < 2; h++) {
                    const int rr = rr0 + 8 * h;
                    const float sr = bias[row0 + rr];
                    const float k0 = fmaxf(sr + sc0 - 2.0f * ac[2 * h],     0.0f);
                    const float k1 = fmaxf(sr + sc1 - 2.0f * ac[2 * h + 1], 0.0f);
                    const f16 h0 = __float2half(k0), h1 = __float2half(k1);
                    *(__half2*)(Oh + (size_t)(row0 + rr) * NN + col0 + cc0) =
                        __halves2half2(h0, h1);
                    if (mirror) {
                        dsm[cc0 * TST + rr]       = h0;
                        dsm[(cc0 + 1) * TST + rr] = h1;
                    }
                }
            }
        }
        if (mirror) {
            __syncthreads();
            for (int f = tid; f < 128 * 16; f += THREADS) {
                const int cc = f >> 4, seg = f & 15;
                const uint4 v = *reinterpret_cast<const uint4*>(&dsm[cc * TST + seg * 8]);
                *reinterpret_cast<uint4*>(Oh + (size_t)(col0 + cc) * NN + row0 + seg * 8) = v;
            }
        }
    } else {
        #pragma unroll
        for (int mt = 0; mt < 4; mt++) {
            #pragma unroll
            for (int nt = 0; nt < 4; nt++) {
                const int r = row0 + wm * 64 + mt * 16 + (lane >> 2);
                const int c = col0 + wn * 32 + nt * 8 + ((lane & 3) << 1);
                const float* ac = acc[mt][nt];
                if constexpr (EPI == 0) {
                    const float bc0 = bias[c], bc1 = bias[c + 1];
                    #pragma unroll
                    for (int h = 0; h < 2; h++) {
                        const int rr = r + 8 * h;
                        const float y0 = sp(ac[2 * h] + bc0);
                        const float y1 = sp(ac[2 * h + 1] + bc1);
                        f16 h0, l0, h1, l1;
                        split1(y0, h0, l0); split1(y1, h1, l1);
                        *(__half2*)(Oh + (size_t)rr * N + c) = __halves2half2(h0, h1);
                        *(__half2*)(Ol + (size_t)rr * N + c) = __halves2half2(l0, l1);
                    }
                } else {  // EPI == 3
                    float* part = Cf + (size_t)blockIdx.z * M * N;
                    #pragma unroll
                    for (int h = 0; h < 2; h++) {
                        const size_t o = (size_t)(r + 8 * h) * N + c;
                        part[o]     = ac[2 * h];
                        part[o + 1] = ac[2 * h + 1];
                    }
                }
            }
        }
    }
}

// ---------------- combine split-K partials ----------------
__global__ void combine_kernel(const float* __restrict__ part, const float* __restrict__ bias,
                               const float* __restrict__ tens, float* __restrict__ pushed) {
    const int i = blockIdx.x * blockDim.x + threadIdx.x;
    if (i >= NN * DR / 4) return;
    const int c4 = (i * 4) % DR;
    const float4 b4 = *reinterpret_cast<const float4*>(bias + c4);
    float4 s = reinterpret_cast<const float4*>(part)[i];
    #pragma unroll
    for (int ks = 1; ks < KSPL; ks++) {
        const float4 p = reinterpret_cast<const float4*>(part + (size_t)ks * NN * DR)[i];
        s.x += p.x; s.y += p.y; s.z += p.z; s.w += p.w;
    }
    const float4 t = reinterpret_cast<const float4*>(tens)[i];
    float4 o;
    o.x = t.x - (s.x + b4.x);
    o.y = t.y - (s.y + b4.y);
    o.z = t.z - (s.z + b4.z);
    o.w = t.w - (s.w + b4.w);
    reinterpret_cast<float4*>(pushed)[i] = o;
}

// ---------------- top-NCAND smallest per row (fp16 approx keys) ----------------
template<int L>
__device__ __forceinline__ void insL(float x, int j, float (&v)[L], int (&id)[L]) {
    if (x >= v[L - 1]) return;
    #pragma unroll
    for (int t = L - 1; t > 0; t--) {
        const bool shf = (x < v[t - 1]);
        const bool put = !shf && (x < v[t]);
        v[t]  = shf ? v[t - 1]  : (put ? x : v[t]);
        id[t] = shf ? id[t - 1] : (put ? j : id[t]);
    }
    if (x < v[0]) { v[0] = x; id[0] = j; }
}

__global__ void topk_kernel(const f16* __restrict__ key, int* __restrict__ out_cand) {
    const int row  = blockIdx.x * 8 + (threadIdx.x >> 5);
    const int lane = threadIdx.x & 31;
    const uint4* k8 = reinterpret_cast<const uint4*>(key + (size_t)row * NN);

    float v[NCAND]; int id[NCAND];
    #pragma unroll
    for (int t = 0; t < NCAND; t++) { v[t] = 3.0e38f; id[t] = 0x7fffffff; }

    #pragma unroll 4
    for (int j = lane; j < NN / 8; j += 32) {
        const uint4 t = k8[j];
        const int b = 8 * j;
        const __half2 p0 = *reinterpret_cast<const __half2*>(&t.x);
        const __half2 p1 = *reinterpret_cast<const __half2*>(&t.y);
        const __half2 p2 = *reinterpret_cast<const __half2*>(&t.z);
        const __half2 p3 = *reinterpret_cast<const __half2*>(&t.w);
        insL<NCAND>(__low2float(p0),  b,     v, id);
        insL<NCAND>(__high2float(p0), b + 1, v, id);
        insL<NCAND>(__low2float(p1),  b + 2, v, id);
        insL<NCAND>(__high2float(p1), b + 3, v, id);
        insL<NCAND>(__low2float(p2),  b + 4, v, id);
        insL<NCAND>(__high2float(p2), b + 5, v, id);
        insL<NCAND>(__low2float(p3),  b + 6, v, id);
        insL<NCAND>(__high2float(p3), b + 7, v, id);
    }

    #pragma unroll
    for (int k = 0; k < NCAND; k++) {
        float mv = v[0]; int mi = id[0];
        #pragma unroll
        for (int off = 16; off > 0; off >>= 1) {
            const float ov = __shfl_down_sync(0xffffffffu, mv, off);
            const int   oi = __shfl_down_sync(0xffffffffu, mi, off);
            if (ov < mv || (ov == mv && oi < mi)) { mv = ov; mi = oi; }
        }
        mv = __shfl_sync(0xffffffffu, mv, 0);
        mi = __shfl_sync(0xffffffffu, mi, 0);
        if (id[0] == mi) {
            #pragma unroll
            for (int t = 0; t < NCAND - 1; t++) { v[t] = v[t + 1]; id[t] = id[t + 1]; }
            v[NCAND - 1] = 3.0e38f; id[NCAND - 1] = 0x7fffffff;
        }
        if (lane == 0) out_cand[row * NCAND + k] = mi;
    }
}

// ---------------- exact fp32 rescore of the 16 candidates -> final top-10 --------
__global__ void rescore_kernel(const float* __restrict__ cond, const float* __restrict__ sq,
                               const int* __restrict__ cand, int* __restrict__ out_idx) {
    const int row  = blockIdx.x * 8 + (threadIdx.x >> 5);
    const int lane = threadIdx.x & 31;
    const float4 cr = reinterpret_cast<const float4*>(cond)[row * 32 + lane];
    const float sr = sq[row];

    float mv = 3.0e38f; int mid = 0x7fffffff;
    #pragma unroll
    for (int c = 0; c < NCAND; c++) {
        const int j = cand[row * NCAND + c];
        const float4 cc = reinterpret_cast<const float4*>(cond)[j * 32 + lane];
        float d = cr.x * cc.x + cr.y * cc.y + cr.z * cc.z + cr.w * cc.w;
        #pragma unroll
        for (int o = 16; o > 0; o >>= 1) d += __shfl_down_sync(0xffffffffu, d, o);
        d = __shfl_sync(0xffffffffu, d, 0);
        const float k = fmaxf(sr + sq[j] - 2.0f * d, 0.0f);
        if (lane == c) { mv = k; mid = j; }
    }

    #pragma unroll
    for (int k = 0; k < TOPK; k++) {
        float bv = mv; int bi = mid;
        #pragma unroll
        for (int off = 16; off > 0; off >>= 1) {
            const float ov = __shfl_down_sync(0xffffffffu, bv, off);
            const int   oi = __shfl_down_sync(0xffffffffu, bi, off);
            if (ov < bv || (ov == bv && oi < bi)) { bv = ov; bi = oi; }
        }
        bv = __shfl_sync(0xffffffffu, bv, 0);
        bi = __shfl_sync(0xffffffffu, bi, 0);
        if (mid == bi) { mv = 3.0e38f; mid = 0x7fffffff; }
        if (lane == 0) out_idx[row * TOPK + k] = bi;
    }
}

// ---------------- final gather ----------------
__global__ void gather_kernel(const int* __restrict__ nidx, const float* __restrict__ pushed,
                              float* __restrict__ out) {
    const int t = blockIdx.x * blockDim.x + threadIdx.x;
    if (t >= NN * TOPK * 16) return;
    const int r = t >> 4, c = t & 15;
    const int j = nidx[r];
    reinterpret_cast<float4*>(out)[t] = reinterpret_cast<const float4*>(pushed)[j * 16 + c];
}

// ---------------- launch ----------------
extern "C" void kernel_launch(void* const* d_in, const int* in_sizes, int n_in,
                              void* d_out, int out_size)
{
    const float* cond = (const float*)d_in[0];
    const float* tens = (const float*)d_in[1];
    const float* Win  = (const float*)d_in[2];
    const float* b_in = (const float*)d_in[3];
    const float* W1   = (const float*)d_in[4];
    const float* b1   = (const float*)d_in[5];
    const float* W2   = (const float*)d_in[6];
    const float* b2   = (const float*)d_in[7];
    const float* W3   = (const float*)d_in[8];
    const float* b3   = (const float*)d_in[9];
    const float* Wout = (const float*)d_in[10];
    const float* bout = (const float*)d_in[11];
    float* out = (float*)d_out;

    float *sq, *pushed, *part; int *cand, *nidx;
    f16 *key;
    f16 *x0h, *x0l, *hAh, *hAl, *hBh, *hBl, *ch, *cl, *cth, *ctl;
    f16 *Wih, *Wil, *W1h, *W1l, *W2h, *W2l, *W3h, *W3l, *Woh, *Wol;
    cudaGetSymbolAddress((void**)&key, g_key);
    cudaGetSymbolAddress((void**)&sq, g_sq);
    cudaGetSymbolAddress((void**)&cand, g_cand);
    cudaGetSymbolAddress((void**)&nidx, g_nidx);
    cudaGetSymbolAddress((void**)&pushed, g_pushed);
    cudaGetSymbolAddress((void**)&part, g_part);
    cudaGetSymbolAddress((void**)&x0h, g_x0h); cudaGetSymbolAddress((void**)&x0l, g_x0l);
    cudaGetSymbolAddress((void**)&hAh, g_hAh); cudaGetSymbolAddress((void**)&hAl, g_hAl);
    cudaGetSymbolAddress((void**)&hBh, g_hBh); cudaGetSymbolAddress((void**)&hBl, g_hBl);
    cudaGetSymbolAddress((void**)&ch,  g_ch);  cudaGetSymbolAddress((void**)&cl,  g_cl);
    cudaGetSymbolAddress((void**)&cth, g_cth); cudaGetSymbolAddress((void**)&ctl, g_ctl);
    cudaGetSymbolAddress((void**)&Wih, g_Wih); cudaGetSymbolAddress((void**)&Wil, g_Wil);
    cudaGetSymbolAddress((void**)&W1h, g_W1h); cudaGetSymbolAddress((void**)&W1l, g_W1l);
    cudaGetSymbolAddress((void**)&W2h, g_W2h); cudaGetSymbolAddress((void**)&W2l, g_W2l);
    cudaGetSymbolAddress((void**)&W3h, g_W3h); cudaGetSymbolAddress((void**)&W3l, g_W3l);
    cudaGetSymbolAddress((void**)&Woh, g_Woh); cudaGetSymbolAddress((void**)&Wol, g_Wol);

    const int SMEM128  = 2 * 8 * (128 * 24 + 16 * (128 + 8));  // 83968
    const int SMEM64   = 2 * 8 * (128 * 24 + 16 * (64 + 8));   // 67584
    const int SMEMG    = 2 * 4 * (128 * 24 + 16 * (128 + 8));  // 41984 (>= 128*136*2)

    static cudaStream_t s2 = nullptr, s3 = nullptr;
    static cudaEvent_t evF = nullptr, evJ = nullptr;
    static cudaEvent_t ev0 = nullptr, ev1 = nullptr, ev2 = nullptr, ev3 = nullptr, ev4 = nullptr;
    if (s2 == nullptr) {
        cudaStreamCreateWithFlags(&s2, cudaStreamNonBlocking);
        cudaStreamCreateWithFlags(&s3, cudaStreamNonBlocking);
        cudaEventCreateWithFlags(&evF, cudaEventDisableTiming);
        cudaEventCreateWithFlags(&evJ, cudaEventDisableTiming);
        cudaEventCreateWithFlags(&ev0, cudaEventDisableTiming);
        cudaEventCreateWithFlags(&ev1, cudaEventDisableTiming);
        cudaEventCreateWithFlags(&ev2, cudaEventDisableTiming);
        cudaEventCreateWithFlags(&ev3, cudaEventDisableTiming);
        cudaEventCreateWithFlags(&ev4, cudaEventDisableTiming);
        cudaFuncSetAttribute(mma_gemm<128, 0, 2, 3>, cudaFuncAttributeMaxDynamicSharedMemorySize, SMEM128);
        cudaFuncSetAttribute(mma_gemm<128, 2, 2, 1>, cudaFuncAttributeMaxDynamicSharedMemorySize, SMEMG);
        cudaFuncSetAttribute(mma_gemm<64, 3, 2, 3>,  cudaFuncAttributeMaxDynamicSharedMemorySize, SMEM64);
    }

    // ---- fork point ----
    cudaEventRecord(evF, 0);
    cudaStreamWaitEvent(s2, evF, 0);
    cudaStreamWaitEvent(s3, evF, 0);

    // ---- s2: FULL gram chain (prep + symmetric gram + topk + rescore) ----
    sq_kernel<<<NN / 8, 256, 0, s2>>>(cond, sq);
    split4_kernel<<<(NN * DF / 4 + 1023) / 1024, 256, 0, s2>>>(cond, ch, cl, NN * DF / 4);
    tsplit_kernel<<<(DF * NN + 255) / 256, 256, 0, s2>>>(cond, cth, ctl);
    mma_gemm<128, 2, 2, 1><<<NTRI, 256, SMEMG, s2>>>(
        ch, cl, cth, ctl, sq, nullptr, nullptr, key, nullptr, NN, NN, DF, DF);
    topk_kernel<<<NN / 8, 256, 0, s2>>>(key, cand);
    rescore_kernel<<<NN / 8, 256, 0, s2>>>(cond, sq, cand, nidx);
    cudaEventRecord(evJ, s2);

    // ---- s3: weight splits front-to-back, per-weight events ----
    split4_kernel<<<(XDIM * HID / 4 + 1023) / 1024, 256, 0, s3>>>(Win, Wih, Wil, XDIM * HID / 4);
    cudaEventRecord(ev0, s3);
    split4_kernel<<<(HID * HID / 4 + 1023) / 1024, 256, 0, s3>>>(W1, W1h, W1l, HID * HID / 4);
    cudaEventRecord(ev1, s3);
    split4_kernel<<<(HID * HID / 4 + 1023) / 1024, 256, 0, s3>>>(W2, W2h, W2l, HID * HID / 4);
    cudaEventRecord(ev2, s3);
    split4_kernel<<<(HID * HID / 4 + 1023) / 1024, 256, 0, s3>>>(W3, W3h, W3l, HID * HID / 4);
    cudaEventRecord(ev3, s3);
    split4_kernel<<<(HID * DR / 4 + 1023) / 1024, 256, 0, s3>>>(Wout, Woh, Wol, HID * DR / 4);
    cudaEventRecord(ev4, s3);

    // ---- default: MLP chain ----
    concat_split_kernel<<<(NN * XDIM + 255) / 256, 256>>>(cond, tens, x0h, x0l);
    cudaStreamWaitEvent(0, ev0, 0);

    mma_gemm<128, 0, 2, 3><<<dim3(HID / 128, NN / 128), 256, SMEM128>>>(
        x0h, x0l, Wih, Wil, b_in, nullptr, nullptr, hAh, hAl, NN, HID, XDIM, XDIM);
    cudaStreamWaitEvent(0, ev1, 0);
    mma_gemm<128, 0, 2, 3><<<dim3(HID / 128, NN / 128), 256, SMEM128>>>(
        hAh, hAl, W1h, W1l, b1, nullptr, nullptr, hBh, hBl, NN, HID, HID, HID);
    cudaStreamWaitEvent(0, ev2, 0);
    mma_gemm<128, 0, 2, 3><<<dim3(HID / 128, NN / 128), 256, SMEM128>>>(
        hBh, hBl, W2h, W2l, b2, nullptr, nullptr, hAh, hAl, NN, HID, HID, HID);
    cudaStreamWaitEvent(0, ev3, 0);
    mma_gemm<128, 0, 2, 3><<<dim3(HID / 128, NN / 128), 256, SMEM128>>>(
        hAh, hAl, W3h, W3l, b3, nullptr, nullptr, hBh, hBl, NN, HID, HID, HID);
    cudaStreamWaitEvent(0, ev4, 0);

    mma_gemm<64, 3, 2, 3><<<dim3(DR / 64, NN / 128, KSPL), 128, SMEM64>>>(
        hBh, hBl, Woh, Wol, nullptr, nullptr, part, nullptr, nullptr,
        NN, DR, HID / KSPL, HID);
    combine_kernel<<<(NN * DR / 4 + 255) / 256, 256>>>(part, bout, tens, pushed);

    // ---- join, then gather ----
    cudaStreamWaitEvent(0, evJ, 0);
    gather_kernel<<<(NN * TOPK * 16 + 255) / 256, 256>>>(nidx, pushed, out);
}